// round 5
// baseline (speedup 1.0000x reference)
#include <cuda_runtime.h>
#include <cuda_bf16.h>
#include <math.h>
#include <stdint.h>

// Problem constants
#define BB   2
#define TT   2048
#define CC   2048
#define NHH  16
#define DKK  128
#define LATT 512
#define DHRR 64
#define MROWS (BB * TT)   // 4096

typedef __nv_bfloat16 bf16;

// ---------------------------------------------------------------------------
// Scratch (static device globals -- no allocation allowed)
// ---------------------------------------------------------------------------
__device__ float g_h   [(size_t)MROWS * 1024];
__device__ float g_kr  [(size_t)MROWS * 64];
__device__ float g_qr  [(size_t)MROWS * 1024];
__device__ float g_kv  [(size_t)MROWS * 4096];
__device__ float g_q   [(size_t)MROWS * 2048];
__device__ float g_attn[(size_t)MROWS * 2048];

// bf16 K-tripled copies (3-term compensated product)
__device__ bf16 g_x2   [(size_t)MROWS * 6144];
__device__ bf16 g_h2   [(size_t)MROWS * 3072];
__device__ bf16 g_attn2[(size_t)MROWS * 6144];
__device__ bf16 g_wdkv2[(size_t)6144 * 1024];
__device__ bf16 g_wqr2 [(size_t)3072 * 1024];
__device__ bf16 g_wuv2 [(size_t)1536 * 4096];
__device__ bf16 g_wuq2 [(size_t)1536 * 2048];
__device__ bf16 g_wo2  [(size_t)6144 * 2048];

// ---------------------------------------------------------------------------
// PTX helpers
// ---------------------------------------------------------------------------
__device__ __forceinline__ uint32_t smem_u32(const void* p)
{ return (uint32_t)__cvta_generic_to_shared(p); }

__device__ __forceinline__ void cp16(uint32_t dst, const void* src)
{ asm volatile("cp.async.cg.shared.global [%0], [%1], 16;\n" :: "r"(dst), "l"(src)); }

__device__ __forceinline__ void cp_commit()
{ asm volatile("cp.async.commit_group;\n"); }

template <int N>
__device__ __forceinline__ void cp_wait()
{ asm volatile("cp.async.wait_group %0;\n" :: "n"(N)); }

__device__ __forceinline__ void ldm_x4(uint32_t* r, uint32_t addr)
{
    asm volatile("ldmatrix.sync.aligned.m8n8.x4.shared.b16 {%0,%1,%2,%3}, [%4];\n"
        : "=r"(r[0]), "=r"(r[1]), "=r"(r[2]), "=r"(r[3]) : "r"(addr));
}
__device__ __forceinline__ void ldm_x4t(uint32_t* r, uint32_t addr)
{
    asm volatile("ldmatrix.sync.aligned.m8n8.x4.trans.shared.b16 {%0,%1,%2,%3}, [%4];\n"
        : "=r"(r[0]), "=r"(r[1]), "=r"(r[2]), "=r"(r[3]) : "r"(addr));
}
__device__ __forceinline__ void mma_bf16(float* d, const uint32_t* a, const uint32_t* b)
{
    asm volatile(
        "mma.sync.aligned.m16n8k16.row.col.f32.bf16.bf16.f32 "
        "{%0,%1,%2,%3}, {%4,%5,%6,%7}, {%8,%9}, {%0,%1,%2,%3};\n"
        : "+f"(d[0]), "+f"(d[1]), "+f"(d[2]), "+f"(d[3])
        : "r"(a[0]), "r"(a[1]), "r"(a[2]), "r"(a[3]), "r"(b[0]), "r"(b[1]));
}

// ---------------------------------------------------------------------------
// Conversion kernels: fp32 -> K-tripled bf16
//  A-triple per k: (hi, hi, lo)   B-triple: (hi, lo, hi)
//  => plain bf16 GEMM over K'=3K computes Ahi*Bhi + Ahi*Blo + Alo*Bhi
// ---------------------------------------------------------------------------
__global__ void convert_act(const float* __restrict__ A, int lda, int aoff,
                            int Kw, bf16* __restrict__ out)
{
    int idx = blockIdx.x * blockDim.x + threadIdx.x;
    if (idx >= MROWS * Kw) return;
    int m = idx / Kw, k = idx - m * Kw;
    float v = A[(size_t)m * lda + aoff + k];
    bf16 hi = __float2bfloat16(v);
    bf16 lo = __float2bfloat16(v - __bfloat162float(hi));
    bf16* o = out + (size_t)m * (3 * Kw) + 3 * k;
    o[0] = hi; o[1] = hi; o[2] = lo;
}

__global__ void convert_w(const float* __restrict__ W, int K, int N,
                          bf16* __restrict__ out)
{
    int idx = blockIdx.x * blockDim.x + threadIdx.x;
    if (idx >= K * N) return;
    int k = idx / N, n = idx - k * N;
    float v = W[(size_t)k * N + n];
    bf16 hi = __float2bfloat16(v);
    bf16 lo = __float2bfloat16(v - __bfloat162float(hi));
    out[(size_t)(3 * k + 0) * N + n] = hi;
    out[(size_t)(3 * k + 1) * N + n] = lo;
    out[(size_t)(3 * k + 2) * N + n] = hi;
}

// ---------------------------------------------------------------------------
// bf16 tensor-core GEMM: Y[M,N] = A[M,K'](ldk, aoff) @ W[K',N] + bias (fp32)
// Block tile 128x256x32, 256 threads (8 warps 2x4, 64x64 per warp),
// 3-stage cp.async pipeline, ldmatrix fragments, mma.m16n8k16.
// Requires M%128==0, N%256==0, K'%32==0, K'/32 >= 2.
// ---------------------------------------------------------------------------
#define AST 40    // A smem row stride (bf16): 32 + 8
#define BST 264   // B smem row stride (bf16): 256 + 8
#define ASTAGE (128 * AST)
#define BSTAGE (32 * BST)

__global__ __launch_bounds__(256, 1)
void gemm_bf16tc(const bf16* __restrict__ A, int ldk, int aoff,
                 const bf16* __restrict__ W, int N, int K,
                 const float* __restrict__ bias,
                 float* __restrict__ Y, int ldy)
{
    extern __shared__ bf16 smem[];
    bf16* As = smem;                 // [3][128*AST]
    bf16* Bs = smem + 3 * ASTAGE;    // [3][32*BST]

    const int tid = threadIdx.x, lane = tid & 31, wid = tid >> 5;
    const int brow = blockIdx.y * 128, bcol = blockIdx.x * 256;
    const int wm = (wid >> 2) * 64, wn = (wid & 3) * 64;

    // A cp.async mapping: row-per-thread (conflict-free smem stores)
    const int arow = tid & 127;            // 0..127
    const int acol = (tid >> 7) * 8;       // 0 or 8 (elements); 2nd chunk +16
    const bf16* Abase = A + (size_t)(brow + arow) * ldk + aoff + acol;
    // B cp.async mapping: rows t>>5 + 8q, col (t&31)*8
    const int brow0 = tid >> 5;            // 0..7
    const int bcol0 = (lane) * 8;          // 0..248
    const bf16* Wbase = W + (size_t)brow0 * N + bcol + bcol0;

    const uint32_t sA = smem_u32(As), sB = smem_u32(Bs);
    const uint32_t dA0 = (uint32_t)(arow * AST + acol) * 2;
    const uint32_t dB0 = (uint32_t)(brow0 * BST + bcol0) * 2;

    const int nk = K / 32;

    auto issue = [&](int st, int kt) {
        const bf16* Ap = Abase + kt * 32;
        uint32_t a_dst = sA + st * (ASTAGE * 2) + dA0;
        cp16(a_dst, Ap);
        cp16(a_dst + 32, Ap + 16);
        const bf16* Wp = Wbase + (size_t)(kt * 32) * N;
        uint32_t b_dst = sB + st * (BSTAGE * 2) + dB0;
#pragma unroll
        for (int q = 0; q < 4; q++)
            cp16(b_dst + q * (8 * BST * 2), Wp + (size_t)(8 * q) * N);
        cp_commit();
    };

    float acc[4][8][4];
#pragma unroll
    for (int i = 0; i < 4; i++)
#pragma unroll
        for (int j = 0; j < 8; j++)
#pragma unroll
            for (int f = 0; f < 4; f++) acc[i][j][f] = 0.f;

    issue(0, 0);
    issue(1, 1);

    const int l16 = lane & 15, lhi = (lane >> 4) * 8;

    for (int kt = 0; kt < nk; kt++) {
        const int cur = kt - (kt / 3) * 3;
        if (kt + 1 < nk) { cp_wait<1>(); } else { cp_wait<0>(); }
        __syncthreads();
        if (kt + 2 < nk) {
            int nst = kt + 2 - ((kt + 2) / 3) * 3;
            issue(nst, kt + 2);
        }

        const uint32_t aBase = sA + cur * (ASTAGE * 2);
        const uint32_t bBase = sB + cur * (BSTAGE * 2);

#pragma unroll
        for (int kk = 0; kk < 32; kk += 16) {
            uint32_t a[4][4], b[8][2];
#pragma unroll
            for (int i = 0; i < 4; i++) {
                uint32_t addr = aBase +
                    (uint32_t)((wm + i * 16 + l16) * AST + kk + lhi) * 2;
                ldm_x4(a[i], addr);
            }
#pragma unroll
            for (int j2 = 0; j2 < 4; j2++) {
                uint32_t t[4];
                uint32_t addr = bBase +
                    (uint32_t)((kk + l16) * BST + wn + j2 * 16 + lhi) * 2;
                ldm_x4t(t, addr);
                b[j2 * 2 + 0][0] = t[0]; b[j2 * 2 + 0][1] = t[1];
                b[j2 * 2 + 1][0] = t[2]; b[j2 * 2 + 1][1] = t[3];
            }
#pragma unroll
            for (int i = 0; i < 4; i++)
#pragma unroll
                for (int j = 0; j < 8; j++)
                    mma_bf16(acc[i][j], a[i], b[j]);
        }
        __syncthreads();
    }

    // epilogue: bias + fp32 store
#pragma unroll
    for (int i = 0; i < 4; i++) {
#pragma unroll
        for (int j = 0; j < 8; j++) {
            int r0 = brow + wm + i * 16 + (lane >> 2);
            int c0 = bcol + wn + j * 8 + (lane & 3) * 2;
            float b0 = bias[c0], b1 = bias[c0 + 1];
            float2 v0 = {acc[i][j][0] + b0, acc[i][j][1] + b1};
            float2 v1 = {acc[i][j][2] + b0, acc[i][j][3] + b1};
            *(float2*)&Y[(size_t)r0 * ldy + c0] = v0;
            *(float2*)&Y[(size_t)(r0 + 8) * ldy + c0] = v1;
        }
    }
}

// ---------------------------------------------------------------------------
// Small SGEMM (kept for the N=64 W_kr projection only)
// ---------------------------------------------------------------------------
#define GBM 64
#define GBN 64
#define GBK 16

__global__ __launch_bounds__(256)
void sgemm_bias(const float* __restrict__ A, int lda, int aoff,
                const float* __restrict__ W,
                const float* __restrict__ bias,
                float* __restrict__ Y, int ldy,
                int M, int N, int K)
{
    __shared__ float As[GBK][GBM];
    __shared__ float Bs[GBK][GBN];

    const int tid = threadIdx.x;
    const int brow = blockIdx.y * GBM;
    const int bcol = blockIdx.x * GBN;
    const int tr = (tid / 16) * 4;
    const int tc = (tid % 16) * 4;

    float acc[4][4];
#pragma unroll
    for (int i = 0; i < 4; i++)
#pragma unroll
        for (int j = 0; j < 4; j++) acc[i][j] = 0.f;

    for (int k0 = 0; k0 < K; k0 += GBK) {
#pragma unroll
        for (int it = 0; it < (GBM * GBK) / 256; it++) {
            int i = tid + it * 256;
            int m = i / GBK, kk = i % GBK;
            As[kk][m] = A[(size_t)(brow + m) * lda + aoff + k0 + kk];
        }
#pragma unroll
        for (int it = 0; it < (GBK * GBN) / 256; it++) {
            int i = tid + it * 256;
            int kk = i / GBN, n = i % GBN;
            Bs[kk][n] = W[(size_t)(k0 + kk) * N + bcol + n];
        }
        __syncthreads();

#pragma unroll
        for (int kk = 0; kk < GBK; kk++) {
            float a[4], b[4];
#pragma unroll
            for (int i = 0; i < 4; i++) a[i] = As[kk][tr + i];
#pragma unroll
            for (int j = 0; j < 4; j++) b[j] = Bs[kk][tc + j];
#pragma unroll
            for (int i = 0; i < 4; i++)
#pragma unroll
                for (int j = 0; j < 4; j++) acc[i][j] = fmaf(a[i], b[j], acc[i][j]);
        }
        __syncthreads();
    }

#pragma unroll
    for (int i = 0; i < 4; i++)
#pragma unroll
        for (int j = 0; j < 4; j++)
            Y[(size_t)(brow + tr + i) * ldy + bcol + tc + j] =
                acc[i][j] + bias[bcol + tc + j];
}

// ---------------------------------------------------------------------------
// Interleaved RoPE (double-precision trig; angles up to ~2048 rad)
// ---------------------------------------------------------------------------
__global__ void rope_kernel(float* __restrict__ buf, int rows, int c)
{
    const int pairs = c >> 1;
    const int idx = blockIdx.x * blockDim.x + threadIdx.x;
    if (idx >= rows * pairs) return;
    const int row = idx / pairs;
    const int i   = idx - row * pairs;
    const int t   = row & (TT - 1);

    float theta = (float)exp(-2.0 * (double)i / (double)c * log(10000.0));
    float angle = (float)(t + 1) * theta;
    double a = (double)angle;
    float cs = (float)cos(a);
    float sn = (float)sin(a);

    float* p = buf + (size_t)row * c + 2 * i;
    float x0 = p[0], x1 = p[1];
    p[0] = x0 * cs - x1 * sn;
    p[1] = x1 * cs + x0 * sn;
}

// ---------------------------------------------------------------------------
// Flash attention: 64 queries x 64 keys per tile, 256 threads.
// ---------------------------------------------------------------------------
__global__ __launch_bounds__(256)
void attn_flash(const float* __restrict__ q, const float* __restrict__ qr,
                const float* __restrict__ kv, const float* __restrict__ kr,
                float* __restrict__ out)
{
    extern __shared__ float sm[];
    float* Qs = sm;                  // [64][196]
    float* Ks = Qs + 64 * 196;       // [64][196]
    float* Vs = Ks + 64 * 196;       // [64][128]
    float* Ps = Vs + 64 * 128;       // [64][68]

    const int bh = blockIdx.y;
    const int b = bh >> 4, h = bh & 15;
    const int qb = gridDim.x - 1 - blockIdx.x;   // largest blocks first
    const int tid = threadIdx.x;
    const int ty = tid >> 4, tx = tid & 15;
    const int row0 = b * TT + qb * 64;
    const size_t kbase = (size_t)b * TT;
    const float scale = 0.08838834764831845f;    // 1/sqrt(128)

    for (int idx = tid; idx < 64 * 48; idx += 256) {
        int qi = idx / 48, d4 = (idx % 48) * 4;
        float4 v;
        if (d4 < 128)
            v = *(const float4*)&q[(size_t)(row0 + qi) * 2048 + h * 128 + d4];
        else
            v = *(const float4*)&qr[(size_t)(row0 + qi) * 1024 + h * 64 + (d4 - 128)];
        v.x *= scale; v.y *= scale; v.z *= scale; v.w *= scale;
        *(float4*)&Qs[qi * 196 + d4] = v;
    }

    float m[4], l[4], acc[4][8];
#pragma unroll
    for (int i = 0; i < 4; i++) {
        m[i] = -3.0e38f; l[i] = 0.f;
#pragma unroll
        for (int j = 0; j < 8; j++) acc[i][j] = 0.f;
    }

    const int ntiles = qb + 1;
    for (int t = 0; t < ntiles; t++) {
        const int j0 = t * 64;
        __syncthreads();
        for (int idx = tid; idx < 64 * 48; idx += 256) {
            int j = idx / 48, d4 = (idx % 48) * 4;
            float4 v;
            if (d4 < 128)
                v = *(const float4*)&kv[(kbase + j0 + j) * 4096 + h * 128 + d4];
            else
                v = *(const float4*)&kr[(kbase + j0 + j) * 64 + (d4 - 128)];
            *(float4*)&Ks[j * 196 + d4] = v;
        }
        for (int idx = tid; idx < 64 * 32; idx += 256) {
            int j = idx / 32, d4 = (idx % 32) * 4;
            *(float4*)&Vs[j * 128 + d4] =
                *(const float4*)&kv[(kbase + j0 + j) * 4096 + 2048 + h * 128 + d4];
        }
        __syncthreads();

        float s[4][4];
#pragma unroll
        for (int i = 0; i < 4; i++)
#pragma unroll
            for (int j = 0; j < 4; j++) s[i][j] = 0.f;

        for (int d4 = 0; d4 < 192; d4 += 4) {
            float4 qv[4], kk[4];
#pragma unroll
            for (int i = 0; i < 4; i++) qv[i] = *(float4*)&Qs[(ty + 16 * i) * 196 + d4];
#pragma unroll
            for (int j = 0; j < 4; j++) kk[j] = *(float4*)&Ks[(tx + 16 * j) * 196 + d4];
#pragma unroll
            for (int i = 0; i < 4; i++)
#pragma unroll
                for (int j = 0; j < 4; j++) {
                    s[i][j] = fmaf(qv[i].x, kk[j].x, s[i][j]);
                    s[i][j] = fmaf(qv[i].y, kk[j].y, s[i][j]);
                    s[i][j] = fmaf(qv[i].z, kk[j].z, s[i][j]);
                    s[i][j] = fmaf(qv[i].w, kk[j].w, s[i][j]);
                }
        }

        if (t == ntiles - 1) {
#pragma unroll
            for (int i = 0; i < 4; i++) {
                int qrow = qb * 64 + ty + 16 * i;
#pragma unroll
                for (int j = 0; j < 4; j++)
                    if (j0 + tx + 16 * j > qrow) s[i][j] = -1.0e30f;
            }
        }

#pragma unroll
        for (int i = 0; i < 4; i++) {
            float mr = fmaxf(fmaxf(s[i][0], s[i][1]), fmaxf(s[i][2], s[i][3]));
#pragma unroll
            for (int o = 1; o < 16; o <<= 1)
                mr = fmaxf(mr, __shfl_xor_sync(0xffffffffu, mr, o));
            float mn = fmaxf(m[i], mr);
            float alpha = __expf(m[i] - mn);
            m[i] = mn;
            float rs = 0.f;
#pragma unroll
            for (int j = 0; j < 4; j++) {
                float p = __expf(s[i][j] - mn);
                s[i][j] = p;
                rs += p;
            }
#pragma unroll
            for (int o = 1; o < 16; o <<= 1)
                rs += __shfl_xor_sync(0xffffffffu, rs, o);
            l[i] = l[i] * alpha + rs;
#pragma unroll
            for (int j = 0; j < 8; j++) acc[i][j] *= alpha;
#pragma unroll
            for (int j = 0; j < 4; j++)
                Ps[(ty + 16 * i) * 68 + tx + 16 * j] = s[i][j];
        }
        __syncthreads();

#pragma unroll 2
        for (int j = 0; j < 64; j++) {
            float pj[4];
#pragma unroll
            for (int i = 0; i < 4; i++) pj[i] = Ps[(ty + 16 * i) * 68 + j];
#pragma unroll
            for (int c = 0; c < 8; c++) {
                float vv = Vs[j * 128 + tx + 16 * c];
#pragma unroll
                for (int i = 0; i < 4; i++) acc[i][c] = fmaf(pj[i], vv, acc[i][c]);
            }
        }
    }

#pragma unroll
    for (int i = 0; i < 4; i++) {
        float inv = 1.f / l[i];
        int orow = row0 + ty + 16 * i;
#pragma unroll
        for (int c = 0; c < 8; c++)
            out[(size_t)orow * 2048 + h * 128 + tx + 16 * c] = acc[i][c] * inv;
    }
}

// ---------------------------------------------------------------------------
// Host launcher
// ---------------------------------------------------------------------------
extern "C" void kernel_launch(void* const* d_in, const int* in_sizes, int n_in,
                              void* d_out, int out_size)
{
    (void)in_sizes; (void)n_in; (void)out_size;

    const float* x     = (const float*)d_in[0];
    const float* W_dkv = (const float*)d_in[1];
    const float* b_dkv = (const float*)d_in[2];
    const float* W_kr  = (const float*)d_in[3];
    const float* b_kr  = (const float*)d_in[4];
    const float* W_qr  = (const float*)d_in[5];
    const float* b_qr  = (const float*)d_in[6];
    const float* W_uv  = (const float*)d_in[7];
    const float* b_uv  = (const float*)d_in[8];
    const float* W_uq  = (const float*)d_in[9];
    const float* b_uq  = (const float*)d_in[10];
    const float* W_o   = (const float*)d_in[11];
    const float* b_o   = (const float*)d_in[12];
    float* out = (float*)d_out;

    float *h, *kr, *qr, *kvb, *qb, *attn;
    bf16 *x2, *h2, *attn2, *wdkv2, *wqr2, *wuv2, *wuq2, *wo2;
    cudaGetSymbolAddress((void**)&h,    g_h);
    cudaGetSymbolAddress((void**)&kr,   g_kr);
    cudaGetSymbolAddress((void**)&qr,   g_qr);
    cudaGetSymbolAddress((void**)&kvb,  g_kv);
    cudaGetSymbolAddress((void**)&qb,   g_q);
    cudaGetSymbolAddress((void**)&attn, g_attn);
    cudaGetSymbolAddress((void**)&x2,    g_x2);
    cudaGetSymbolAddress((void**)&h2,    g_h2);
    cudaGetSymbolAddress((void**)&attn2, g_attn2);
    cudaGetSymbolAddress((void**)&wdkv2, g_wdkv2);
    cudaGetSymbolAddress((void**)&wqr2,  g_wqr2);
    cudaGetSymbolAddress((void**)&wuv2,  g_wuv2);
    cudaGetSymbolAddress((void**)&wuq2,  g_wuq2);
    cudaGetSymbolAddress((void**)&wo2,   g_wo2);

    const int M = MROWS;  // 4096
    const size_t gsmem = (size_t)(3 * ASTAGE + 3 * BSTAGE) * sizeof(bf16);
    static int smem_set = 0;
    cudaFuncSetAttribute(gemm_bf16tc, cudaFuncAttributeMaxDynamicSharedMemorySize,
                         (int)gsmem);
    (void)smem_set;

    // weight conversions
    convert_w<<<(2048 * 1024 + 255) / 256, 256>>>(W_dkv, 2048, 1024, wdkv2);
    convert_w<<<(1024 * 1024 + 255) / 256, 256>>>(W_qr, 1024, 1024, wqr2);
    convert_w<<<(512 * 4096 + 255) / 256, 256>>>(W_uv, 512, 4096, wuv2);
    convert_w<<<(512 * 2048 + 255) / 256, 256>>>(W_uq, 512, 2048, wuq2);
    convert_w<<<(2048 * 2048 + 255) / 256, 256>>>(W_o, 2048, 2048, wo2);

    // x -> x2
    convert_act<<<(M * 2048 + 255) / 256, 256>>>(x, 2048, 0, 2048, x2);

    // 1) h = x @ W_dkv + b_dkv            [4096,1024]
    gemm_bf16tc<<<dim3(1024 / 256, M / 128), 256, gsmem>>>(x2, 6144, 0, wdkv2, 1024, 6144, b_dkv, h, 1024);

    // 2) kr_lin = h @ W_kr + b_kr         [4096,64] (fp32, tiny)
    sgemm_bias<<<dim3(64 / GBN, M / GBM), 256>>>(h, 1024, 0, W_kr, b_kr, kr, 64, M, 64, 1024);

    // h -> h2
    convert_act<<<(M * 1024 + 255) / 256, 256>>>(h, 1024, 0, 1024, h2);

    // 3) qr_lin = h @ W_qr + b_qr         [4096,1024]
    gemm_bf16tc<<<dim3(1024 / 256, M / 128), 256, gsmem>>>(h2, 3072, 0, wqr2, 1024, 3072, b_qr, qr, 1024);

    // 4) RoPE on both branches
    {
        int n1 = M * (64 / 2);
        rope_kernel<<<(n1 + 255) / 256, 256>>>(kr, M, 64);
        int n2 = M * (1024 / 2);
        rope_kernel<<<(n2 + 255) / 256, 256>>>(qr, M, 1024);
    }

    // 5) kv = cKV @ W_uv + b_uv           [4096,4096]   (h2 cols 0..1535)
    gemm_bf16tc<<<dim3(4096 / 256, M / 128), 256, gsmem>>>(h2, 3072, 0, wuv2, 4096, 1536, b_uv, kvb, 4096);
    // 6) q = cq @ W_uq + b_uq             [4096,2048]   (h2 cols 1536..)
    gemm_bf16tc<<<dim3(2048 / 256, M / 128), 256, gsmem>>>(h2, 3072, 1536, wuq2, 2048, 1536, b_uq, qb, 2048);

    // 7) attention -> g_attn
    {
        size_t smem = (size_t)(64 * 196 + 64 * 196 + 64 * 128 + 64 * 68) * sizeof(float);
        cudaFuncSetAttribute(attn_flash, cudaFuncAttributeMaxDynamicSharedMemorySize, (int)smem);
        attn_flash<<<dim3(TT / 64, BB * NHH), 256, smem>>>(qb, qr, kvb, kr, attn);
    }

    // attn -> attn2
    convert_act<<<(M * 2048 + 255) / 256, 256>>>(attn, 2048, 0, 2048, attn2);

    // 8) out = attn @ W_o + b_o           [4096,2048]
    gemm_bf16tc<<<dim3(2048 / 256, M / 128), 256, gsmem>>>(attn2, 6144, 0, wo2, 2048, 6144, b_o, out, 2048);
}

// round 6
// speedup vs baseline: 1.7975x; 1.7975x over previous
#include <cuda_runtime.h>
#include <cuda_bf16.h>
#include <math.h>
#include <stdint.h>

// Problem constants
#define BB   2
#define TT   2048
#define CC   2048
#define NHH  16
#define DKK  128
#define LATT 512
#define DHRR 64
#define MROWS (BB * TT)   // 4096

typedef __nv_bfloat16 bf16;

// ---------------------------------------------------------------------------
// Scratch (static device globals -- no allocation allowed)
// ---------------------------------------------------------------------------
__device__ float g_h   [(size_t)MROWS * 1024];
__device__ float g_kr  [(size_t)MROWS * 64];
__device__ float g_qr  [(size_t)MROWS * 1024];
__device__ float g_kv  [(size_t)MROWS * 4096];
__device__ float g_q   [(size_t)MROWS * 2048];
__device__ float g_attn[(size_t)MROWS * 2048];

// bf16 K-tripled copies for projection GEMMs
__device__ bf16 g_x2   [(size_t)MROWS * 6144];
__device__ bf16 g_h2   [(size_t)MROWS * 3072];
__device__ bf16 g_attn2[(size_t)MROWS * 6144];
__device__ bf16 g_wdkv2[(size_t)6144 * 1024];
__device__ bf16 g_wqr2 [(size_t)3072 * 1024];
__device__ bf16 g_wuv2 [(size_t)1536 * 4096];
__device__ bf16 g_wuq2 [(size_t)1536 * 2048];
__device__ bf16 g_wo2  [(size_t)6144 * 2048];

// attention hi/lo buffers, per-head contiguous [(b*NH+h)*T + t][dim]
__device__ bf16 g_qhi[(size_t)BB * NHH * TT * 192];
__device__ bf16 g_qlo[(size_t)BB * NHH * TT * 192];
__device__ bf16 g_khi[(size_t)BB * NHH * TT * 192];
__device__ bf16 g_klo[(size_t)BB * NHH * TT * 192];
__device__ bf16 g_vhi[(size_t)BB * NHH * TT * 128];
__device__ bf16 g_vlo[(size_t)BB * NHH * TT * 128];

// ---------------------------------------------------------------------------
// PTX helpers
// ---------------------------------------------------------------------------
__device__ __forceinline__ uint32_t smem_u32(const void* p)
{ return (uint32_t)__cvta_generic_to_shared(p); }

__device__ __forceinline__ void cp16(uint32_t dst, const void* src)
{ asm volatile("cp.async.cg.shared.global [%0], [%1], 16;\n" :: "r"(dst), "l"(src)); }

__device__ __forceinline__ void cp_commit()
{ asm volatile("cp.async.commit_group;\n"); }

template <int N>
__device__ __forceinline__ void cp_wait()
{ asm volatile("cp.async.wait_group %0;\n" :: "n"(N)); }

__device__ __forceinline__ void ldm_x4(uint32_t* r, uint32_t addr)
{
    asm volatile("ldmatrix.sync.aligned.m8n8.x4.shared.b16 {%0,%1,%2,%3}, [%4];\n"
        : "=r"(r[0]), "=r"(r[1]), "=r"(r[2]), "=r"(r[3]) : "r"(addr));
}
__device__ __forceinline__ void ldm_x4t(uint32_t* r, uint32_t addr)
{
    asm volatile("ldmatrix.sync.aligned.m8n8.x4.trans.shared.b16 {%0,%1,%2,%3}, [%4];\n"
        : "=r"(r[0]), "=r"(r[1]), "=r"(r[2]), "=r"(r[3]) : "r"(addr));
}
__device__ __forceinline__ void mma_bf16(float* d, const uint32_t* a, const uint32_t* b)
{
    asm volatile(
        "mma.sync.aligned.m16n8k16.row.col.f32.bf16.bf16.f32 "
        "{%0,%1,%2,%3}, {%4,%5,%6,%7}, {%8,%9}, {%0,%1,%2,%3};\n"
        : "+f"(d[0]), "+f"(d[1]), "+f"(d[2]), "+f"(d[3])
        : "r"(a[0]), "r"(a[1]), "r"(a[2]), "r"(a[3]), "r"(b[0]), "r"(b[1]));
}
__device__ __forceinline__ float ex2f(float x)
{ float y; asm("ex2.approx.f32 %0, %1;" : "=f"(y) : "f"(x)); return y; }

__device__ __forceinline__ uint32_t packbf2(float lo, float hi)
{ uint32_t d; asm("cvt.rn.bf16x2.f32 %0, %1, %2;" : "=r"(d) : "f"(hi), "f"(lo)); return d; }

// ---------------------------------------------------------------------------
// Conversion kernels: fp32 -> K-tripled bf16 (A:(hi,hi,lo), B:(hi,lo,hi))
// ---------------------------------------------------------------------------
__global__ void convert_act(const float* __restrict__ A, int lda, int aoff,
                            int Kw, bf16* __restrict__ out)
{
    int idx = blockIdx.x * blockDim.x + threadIdx.x;
    if (idx >= MROWS * Kw) return;
    int m = idx / Kw, k = idx - m * Kw;
    float v = A[(size_t)m * lda + aoff + k];
    bf16 hi = __float2bfloat16(v);
    bf16 lo = __float2bfloat16(v - __bfloat162float(hi));
    bf16* o = out + (size_t)m * (3 * Kw) + 3 * k;
    o[0] = hi; o[1] = hi; o[2] = lo;
}

__global__ void convert_w(const float* __restrict__ W, int K, int N,
                          bf16* __restrict__ out)
{
    int idx = blockIdx.x * blockDim.x + threadIdx.x;
    if (idx >= K * N) return;
    int k = idx / N, n = idx - k * N;
    float v = W[(size_t)k * N + n];
    bf16 hi = __float2bfloat16(v);
    bf16 lo = __float2bfloat16(v - __bfloat162float(hi));
    out[(size_t)(3 * k + 0) * N + n] = hi;
    out[(size_t)(3 * k + 1) * N + n] = lo;
    out[(size_t)(3 * k + 2) * N + n] = hi;
}

// ---------------------------------------------------------------------------
// Build attention hi/lo buffers
// ---------------------------------------------------------------------------
__global__ void build_q(const float* __restrict__ q, const float* __restrict__ qr,
                        bf16* __restrict__ qhi, bf16* __restrict__ qlo)
{
    const float SCL = (float)(0.08838834764831845 * 1.4426950408889634); // 1/sqrt(128)*log2e
    int idx = blockIdx.x * blockDim.x + threadIdx.x;
    if (idx >= BB * NHH * TT * 192) return;
    int d = idx % 192; int r = idx / 192;
    int t = r % TT; int bh = r / TT; int h = bh & 15; int b = bh >> 4;
    float v;
    if (d < 128) v = q[((size_t)(b * TT + t)) * 2048 + h * 128 + d];
    else         v = qr[((size_t)(b * TT + t)) * 1024 + h * 64 + (d - 128)];
    v *= SCL;
    bf16 hi = __float2bfloat16(v);
    qhi[idx] = hi;
    qlo[idx] = __float2bfloat16(v - __bfloat162float(hi));
}

__global__ void build_k(const float* __restrict__ kv, const float* __restrict__ kr,
                        bf16* __restrict__ khi, bf16* __restrict__ klo)
{
    int idx = blockIdx.x * blockDim.x + threadIdx.x;
    if (idx >= BB * NHH * TT * 192) return;
    int d = idx % 192; int r = idx / 192;
    int t = r % TT; int bh = r / TT; int h = bh & 15; int b = bh >> 4;
    float v;
    if (d < 128) v = kv[((size_t)(b * TT + t)) * 4096 + h * 128 + d];
    else         v = kr[((size_t)(b * TT + t)) * 64 + (d - 128)];
    bf16 hi = __float2bfloat16(v);
    khi[idx] = hi;
    klo[idx] = __float2bfloat16(v - __bfloat162float(hi));
}

__global__ void build_v(const float* __restrict__ kv,
                        bf16* __restrict__ vhi, bf16* __restrict__ vlo)
{
    int idx = blockIdx.x * blockDim.x + threadIdx.x;
    if (idx >= BB * NHH * TT * 128) return;
    int d = idx % 128; int r = idx / 128;
    int t = r % TT; int bh = r / TT; int h = bh & 15; int b = bh >> 4;
    float v = kv[((size_t)(b * TT + t)) * 4096 + 2048 + h * 128 + d];
    bf16 hi = __float2bfloat16(v);
    vhi[idx] = hi;
    vlo[idx] = __float2bfloat16(v - __bfloat162float(hi));
}

// ---------------------------------------------------------------------------
// bf16 tensor-core GEMM (R4 config): 128x128x32 tile, 256 thr, 2-stage
// ---------------------------------------------------------------------------
#define AST 40
#define BST 136

__global__ __launch_bounds__(256)
void gemm_bf16tc(const bf16* __restrict__ A, int ldk, int aoff,
                 const bf16* __restrict__ W, int N, int K,
                 const float* __restrict__ bias,
                 float* __restrict__ Y, int ldy)
{
    __shared__ bf16 As[2][128 * AST];
    __shared__ bf16 Bs[2][32 * BST];

    const int tid = threadIdx.x, lane = tid & 31, wid = tid >> 5;
    const int brow = blockIdx.y * 128, bcol = blockIdx.x * 128;
    const int wm = (wid >> 2) * 64, wn = (wid & 3) * 32;

    const int ar0 = tid >> 2, aseg = (tid & 3) * 8;
    const int br0 = tid >> 4, bseg = (tid & 15) * 8;

    const bf16* Abase = A + (size_t)(brow + ar0) * ldk + aoff + aseg;
    const bf16* Wbase = W + (size_t)br0 * N + bcol + bseg;

    uint32_t sA[2], sB[2];
    sA[0] = smem_u32(&As[0][0]); sA[1] = smem_u32(&As[1][0]);
    sB[0] = smem_u32(&Bs[0][0]); sB[1] = smem_u32(&Bs[1][0]);

    const uint32_t dA0 = (uint32_t)(ar0 * AST + aseg) * 2;
    const uint32_t dA1 = (uint32_t)((ar0 + 64) * AST + aseg) * 2;
    const uint32_t dB0 = (uint32_t)(br0 * BST + bseg) * 2;
    const uint32_t dB1 = (uint32_t)((br0 + 16) * BST + bseg) * 2;

    const int nk = K / 32;

    auto issue = [&](int st, int kt) {
        const bf16* Ap = Abase + kt * 32;
        const bf16* Wp = Wbase + (size_t)(kt * 32) * N;
        cp16(sA[st] + dA0, Ap);
        cp16(sA[st] + dA1, Ap + (size_t)64 * ldk);
        cp16(sB[st] + dB0, Wp);
        cp16(sB[st] + dB1, Wp + (size_t)16 * N);
        cp_commit();
    };

    float acc[4][4][4];
#pragma unroll
    for (int i = 0; i < 4; i++)
#pragma unroll
        for (int j = 0; j < 4; j++)
#pragma unroll
            for (int f = 0; f < 4; f++) acc[i][j][f] = 0.f;

    issue(0, 0);

    const int l16 = lane & 15, lhi = (lane >> 4) * 8;

    for (int kt = 0; kt < nk; kt++) {
        int cur = kt & 1;
        if (kt + 1 < nk) {
            issue(cur ^ 1, kt + 1);
            cp_wait<1>();
        } else {
            cp_wait<0>();
        }
        __syncthreads();

#pragma unroll
        for (int kk = 0; kk < 32; kk += 16) {
            uint32_t a[4][4], b[4][2];
#pragma unroll
            for (int i = 0; i < 4; i++) {
                uint32_t addr = sA[cur] +
                    (uint32_t)((wm + i * 16 + l16) * AST + kk + lhi) * 2;
                ldm_x4(a[i], addr);
            }
#pragma unroll
            for (int j2 = 0; j2 < 2; j2++) {
                uint32_t t[4];
                uint32_t addr = sB[cur] +
                    (uint32_t)((kk + l16) * BST + wn + j2 * 16 + lhi) * 2;
                ldm_x4t(t, addr);
                b[j2 * 2 + 0][0] = t[0]; b[j2 * 2 + 0][1] = t[1];
                b[j2 * 2 + 1][0] = t[2]; b[j2 * 2 + 1][1] = t[3];
            }
#pragma unroll
            for (int i = 0; i < 4; i++)
#pragma unroll
                for (int j = 0; j < 4; j++)
                    mma_bf16(acc[i][j], a[i], b[j]);
        }
        __syncthreads();
    }

#pragma unroll
    for (int i = 0; i < 4; i++) {
#pragma unroll
        for (int j = 0; j < 4; j++) {
            int r0 = brow + wm + i * 16 + (lane >> 2);
            int c0 = bcol + wn + j * 8 + (lane & 3) * 2;
            float b0 = bias[c0], b1 = bias[c0 + 1];
            float2 v0 = {acc[i][j][0] + b0, acc[i][j][1] + b1};
            float2 v1 = {acc[i][j][2] + b0, acc[i][j][3] + b1};
            *(float2*)&Y[(size_t)r0 * ldy + c0] = v0;
            *(float2*)&Y[(size_t)(r0 + 8) * ldy + c0] = v1;
        }
    }
}

// ---------------------------------------------------------------------------
// Small SGEMM (N=64 W_kr projection only)
// ---------------------------------------------------------------------------
#define GBM 64
#define GBN 64
#define GBK 16

__global__ __launch_bounds__(256)
void sgemm_bias(const float* __restrict__ A, int lda, int aoff,
                const float* __restrict__ W,
                const float* __restrict__ bias,
                float* __restrict__ Y, int ldy,
                int M, int N, int K)
{
    __shared__ float As[GBK][GBM];
    __shared__ float Bs[GBK][GBN];

    const int tid = threadIdx.x;
    const int brow = blockIdx.y * GBM;
    const int bcol = blockIdx.x * GBN;
    const int tr = (tid / 16) * 4;
    const int tc = (tid % 16) * 4;

    float acc[4][4];
#pragma unroll
    for (int i = 0; i < 4; i++)
#pragma unroll
        for (int j = 0; j < 4; j++) acc[i][j] = 0.f;

    for (int k0 = 0; k0 < K; k0 += GBK) {
#pragma unroll
        for (int it = 0; it < (GBM * GBK) / 256; it++) {
            int i = tid + it * 256;
            int m = i / GBK, kk = i % GBK;
            As[kk][m] = A[(size_t)(brow + m) * lda + aoff + k0 + kk];
        }
#pragma unroll
        for (int it = 0; it < (GBK * GBN) / 256; it++) {
            int i = tid + it * 256;
            int kk = i / GBN, n = i % GBN;
            Bs[kk][n] = W[(size_t)(k0 + kk) * N + bcol + n];
        }
        __syncthreads();

#pragma unroll
        for (int kk = 0; kk < GBK; kk++) {
            float a[4], b[4];
#pragma unroll
            for (int i = 0; i < 4; i++) a[i] = As[kk][tr + i];
#pragma unroll
            for (int j = 0; j < 4; j++) b[j] = Bs[kk][tc + j];
#pragma unroll
            for (int i = 0; i < 4; i++)
#pragma unroll
                for (int j = 0; j < 4; j++) acc[i][j] = fmaf(a[i], b[j], acc[i][j]);
        }
        __syncthreads();
    }

#pragma unroll
    for (int i = 0; i < 4; i++)
#pragma unroll
        for (int j = 0; j < 4; j++)
            Y[(size_t)(brow + tr + i) * ldy + bcol + tc + j] =
                acc[i][j] + bias[bcol + tc + j];
}

// ---------------------------------------------------------------------------
// Interleaved RoPE (double-precision trig)
// ---------------------------------------------------------------------------
__global__ void rope_kernel(float* __restrict__ buf, int rows, int c)
{
    const int pairs = c >> 1;
    const int idx = blockIdx.x * blockDim.x + threadIdx.x;
    if (idx >= rows * pairs) return;
    const int row = idx / pairs;
    const int i   = idx - row * pairs;
    const int t   = row & (TT - 1);

    float theta = (float)exp(-2.0 * (double)i / (double)c * log(10000.0));
    float angle = (float)(t + 1) * theta;
    double a = (double)angle;
    float cs = (float)cos(a);
    float sn = (float)sin(a);

    float* p = buf + (size_t)row * c + 2 * i;
    float x0 = p[0], x1 = p[1];
    p[0] = x0 * cs - x1 * sn;
    p[1] = x1 * cs + x0 * sn;
}

// ---------------------------------------------------------------------------
// Tensor-core flash attention, compensated bf16.
// 128 queries x 64 keys per tile, 8 warps; warp owns 16 full S rows.
// S = Qhi*Khi + Qhi*Klo + Qlo*Khi   (q pre-scaled by 1/sqrt(128)*log2e)
// PV = Phi*Vhi + Phi*Vlo + Plo*Vhi  (P re-packed in-register from S frags)
// ---------------------------------------------------------------------------
#define QSTR 200
#define KSTR 200
#define VSTR 136
#define ATTN_SMEM ((2*128*QSTR + 2*64*KSTR + 2*64*VSTR) * 2)

__global__ __launch_bounds__(256, 1)
void attn_tc(const bf16* __restrict__ qhi, const bf16* __restrict__ qlo,
             const bf16* __restrict__ khi, const bf16* __restrict__ klo,
             const bf16* __restrict__ vhi, const bf16* __restrict__ vlo,
             float* __restrict__ out)
{
    extern __shared__ bf16 smA[];
    bf16* Qh = smA;
    bf16* Ql = Qh + 128 * QSTR;
    bf16* Kh = Ql + 128 * QSTR;
    bf16* Kl = Kh + 64 * KSTR;
    bf16* Vh = Kl + 64 * KSTR;
    bf16* Vl = Vh + 64 * VSTR;

    const int tid = threadIdx.x, lane = tid & 31, wp = tid >> 5;
    const int bh = blockIdx.y;
    const int qi = gridDim.x - 1 - blockIdx.x;    // big tiles first
    const int b = bh >> 4, h = bh & 15;
    const size_t base = (size_t)bh * TT;

    const uint32_t sQh = smem_u32(Qh), sQl = smem_u32(Ql);
    const uint32_t sKh = smem_u32(Kh), sKl = smem_u32(Kl);
    const uint32_t sVh = smem_u32(Vh), sVl = smem_u32(Vl);

    // load Q tile [128 x 192] hi+lo
    for (int i = tid; i < 128 * 24; i += 256) {
        int r = i / 24, c = (i % 24) * 8;
        size_t g = (base + (size_t)qi * 128 + r) * 192 + c;
        uint32_t d = (uint32_t)(r * QSTR + c) * 2;
        cp16(sQh + d, qhi + g);
        cp16(sQl + d, qlo + g);
    }
    cp_commit();

    float o[16][4];
#pragma unroll
    for (int i = 0; i < 16; i++)
#pragma unroll
        for (int f = 0; f < 4; f++) o[i][f] = 0.f;

    float m1 = -1e30f, m2 = -1e30f, l1 = 0.f, l2 = 0.f;
    const int l16 = lane & 15, lhi = (lane >> 4) * 8;
    const int qrow1 = qi * 128 + wp * 16 + (lane >> 2);
    const int qrow2 = qrow1 + 8;
    const int brofs = (lane & 7) + ((lane >> 4) & 1) * 8;   // K non-trans row
    const int bcofs = ((lane >> 3) & 1) * 8;                // K non-trans col

    const int nkt = 2 * qi + 2;
    for (int kt = 0; kt < nkt; kt++) {
        __syncthreads();   // prior reads done before refill
        for (int i = tid; i < 64 * 24; i += 256) {
            int r = i / 24, c = (i % 24) * 8;
            size_t g = (base + (size_t)kt * 64 + r) * 192 + c;
            uint32_t d = (uint32_t)(r * KSTR + c) * 2;
            cp16(sKh + d, khi + g);
            cp16(sKl + d, klo + g);
        }
        for (int i = tid; i < 64 * 16; i += 256) {
            int r = i / 16, c = (i % 16) * 8;
            size_t g = (base + (size_t)kt * 64 + r) * 128 + c;
            uint32_t d = (uint32_t)(r * VSTR + c) * 2;
            cp16(sVh + d, vhi + g);
            cp16(sVl + d, vlo + g);
        }
        cp_commit();
        cp_wait<0>();
        __syncthreads();

        // ---- S = Q K^T (compensated) ----
        float s[8][4];
#pragma unroll
        for (int j = 0; j < 8; j++)
#pragma unroll
            for (int f = 0; f < 4; f++) s[j][f] = 0.f;

#pragma unroll
        for (int kk = 0; kk < 12; kk++) {
            uint32_t ah[4], al[4];
            uint32_t aaddr = (uint32_t)((wp * 16 + l16) * QSTR + kk * 16 + lhi) * 2;
            ldm_x4(ah, sQh + aaddr);
            ldm_x4(al, sQl + aaddr);
#pragma unroll
            for (int j2 = 0; j2 < 4; j2++) {
                uint32_t baddr = (uint32_t)((j2 * 16 + brofs) * KSTR + kk * 16 + bcofs) * 2;
                uint32_t tb[4], tl[4];
                ldm_x4(tb, sKh + baddr);
                ldm_x4(tl, sKl + baddr);
                mma_bf16(s[2 * j2],     ah, tb);
                mma_bf16(s[2 * j2],     ah, tl);
                mma_bf16(s[2 * j2],     al, tb);
                mma_bf16(s[2 * j2 + 1], ah, tb + 2);
                mma_bf16(s[2 * j2 + 1], ah, tl + 2);
                mma_bf16(s[2 * j2 + 1], al, tb + 2);
            }
        }

        // ---- mask + online softmax (log2 domain) ----
#pragma unroll
        for (int j = 0; j < 8; j++) {
            int k0 = kt * 64 + j * 8 + 2 * (lane & 3);
            if (k0     > qrow1) s[j][0] = -1e30f;
            if (k0 + 1 > qrow1) s[j][1] = -1e30f;
            if (k0     > qrow2) s[j][2] = -1e30f;
            if (k0 + 1 > qrow2) s[j][3] = -1e30f;
        }
        float mr1 = -1e30f, mr2 = -1e30f;
#pragma unroll
        for (int j = 0; j < 8; j++) {
            mr1 = fmaxf(mr1, fmaxf(s[j][0], s[j][1]));
            mr2 = fmaxf(mr2, fmaxf(s[j][2], s[j][3]));
        }
        mr1 = fmaxf(mr1, __shfl_xor_sync(0xffffffffu, mr1, 1));
        mr1 = fmaxf(mr1, __shfl_xor_sync(0xffffffffu, mr1, 2));
        mr2 = fmaxf(mr2, __shfl_xor_sync(0xffffffffu, mr2, 1));
        mr2 = fmaxf(mr2, __shfl_xor_sync(0xffffffffu, mr2, 2));
        float mn1 = fmaxf(m1, mr1), mn2 = fmaxf(m2, mr2);
        float a1 = ex2f(m1 - mn1), a2 = ex2f(m2 - mn2);
        m1 = mn1; m2 = mn2;

        uint32_t ph[8][2], pl[8][2];
        float rs1 = 0.f, rs2 = 0.f;
#pragma unroll
        for (int j = 0; j < 8; j++) {
            float p0 = ex2f(s[j][0] - mn1), p1 = ex2f(s[j][1] - mn1);
            float p2 = ex2f(s[j][2] - mn2), p3 = ex2f(s[j][3] - mn2);
            rs1 += p0 + p1; rs2 += p2 + p3;
            ph[j][0] = packbf2(p0, p1);
            ph[j][1] = packbf2(p2, p3);
            float q0 = p0 - __bfloat162float(__float2bfloat16(p0));
            float q1 = p1 - __bfloat162float(__float2bfloat16(p1));
            float q2 = p2 - __bfloat162float(__float2bfloat16(p2));
            float q3 = p3 - __bfloat162float(__float2bfloat16(p3));
            pl[j][0] = packbf2(q0, q1);
            pl[j][1] = packbf2(q2, q3);
        }
        rs1 += __shfl_xor_sync(0xffffffffu, rs1, 1);
        rs1 += __shfl_xor_sync(0xffffffffu, rs1, 2);
        rs2 += __shfl_xor_sync(0xffffffffu, rs2, 1);
        rs2 += __shfl_xor_sync(0xffffffffu, rs2, 2);
        l1 = l1 * a1 + rs1;
        l2 = l2 * a2 + rs2;
#pragma unroll
        for (int t16 = 0; t16 < 16; t16++) {
            o[t16][0] *= a1; o[t16][1] *= a1;
            o[t16][2] *= a2; o[t16][3] *= a2;
        }

        // ---- O += P V (compensated) ----
#pragma unroll
        for (int kt2 = 0; kt2 < 4; kt2++) {
            uint32_t pa_h[4] = {ph[2 * kt2][0], ph[2 * kt2][1],
                                ph[2 * kt2 + 1][0], ph[2 * kt2 + 1][1]};
            uint32_t pa_l[4] = {pl[2 * kt2][0], pl[2 * kt2][1],
                                pl[2 * kt2 + 1][0], pl[2 * kt2 + 1][1]};
            uint32_t vrow = (uint32_t)((kt2 * 16 + l16) * VSTR) * 2;
#pragma unroll
            for (int j2 = 0; j2 < 8; j2++) {
                uint32_t vaddr = vrow + (uint32_t)(j2 * 16 + lhi) * 2;
                uint32_t tv[4], tw[4];
                ldm_x4t(tv, sVh + vaddr);
                ldm_x4t(tw, sVl + vaddr);
                mma_bf16(o[2 * j2],     pa_h, tv);
                mma_bf16(o[2 * j2],     pa_h, tw);
                mma_bf16(o[2 * j2],     pa_l, tv);
                mma_bf16(o[2 * j2 + 1], pa_h, tv + 2);
                mma_bf16(o[2 * j2 + 1], pa_h, tw + 2);
                mma_bf16(o[2 * j2 + 1], pa_l, tv + 2);
            }
        }
    }

    // ---- epilogue ----
    float inv1 = 1.f / l1, inv2 = 1.f / l2;
    size_t row1 = (size_t)(b * TT + qrow1) * 2048 + h * 128;
    size_t row2 = (size_t)(b * TT + qrow2) * 2048 + h * 128;
#pragma unroll
    for (int t16 = 0; t16 < 16; t16++) {
        int col = t16 * 8 + 2 * (lane & 3);
        float2 v1 = {o[t16][0] * inv1, o[t16][1] * inv1};
        float2 v2 = {o[t16][2] * inv2, o[t16][3] * inv2};
        *(float2*)&out[row1 + col] = v1;
        *(float2*)&out[row2 + col] = v2;
    }
}

// ---------------------------------------------------------------------------
// Host launcher
// ---------------------------------------------------------------------------
extern "C" void kernel_launch(void* const* d_in, const int* in_sizes, int n_in,
                              void* d_out, int out_size)
{
    (void)in_sizes; (void)n_in; (void)out_size;

    const float* x     = (const float*)d_in[0];
    const float* W_dkv = (const float*)d_in[1];
    const float* b_dkv = (const float*)d_in[2];
    const float* W_kr  = (const float*)d_in[3];
    const float* b_kr  = (const float*)d_in[4];
    const float* W_qr  = (const float*)d_in[5];
    const float* b_qr  = (const float*)d_in[6];
    const float* W_uv  = (const float*)d_in[7];
    const float* b_uv  = (const float*)d_in[8];
    const float* W_uq  = (const float*)d_in[9];
    const float* b_uq  = (const float*)d_in[10];
    const float* W_o   = (const float*)d_in[11];
    const float* b_o   = (const float*)d_in[12];
    float* out = (float*)d_out;

    float *h, *kr, *qr, *kvb, *qb, *attn;
    bf16 *x2, *h2, *attn2, *wdkv2, *wqr2, *wuv2, *wuq2, *wo2;
    bf16 *qhi, *qlo, *khi, *klo, *vhi, *vlo;
    cudaGetSymbolAddress((void**)&h,    g_h);
    cudaGetSymbolAddress((void**)&kr,   g_kr);
    cudaGetSymbolAddress((void**)&qr,   g_qr);
    cudaGetSymbolAddress((void**)&kvb,  g_kv);
    cudaGetSymbolAddress((void**)&qb,   g_q);
    cudaGetSymbolAddress((void**)&attn, g_attn);
    cudaGetSymbolAddress((void**)&x2,    g_x2);
    cudaGetSymbolAddress((void**)&h2,    g_h2);
    cudaGetSymbolAddress((void**)&attn2, g_attn2);
    cudaGetSymbolAddress((void**)&wdkv2, g_wdkv2);
    cudaGetSymbolAddress((void**)&wqr2,  g_wqr2);
    cudaGetSymbolAddress((void**)&wuv2,  g_wuv2);
    cudaGetSymbolAddress((void**)&wuq2,  g_wuq2);
    cudaGetSymbolAddress((void**)&wo2,   g_wo2);
    cudaGetSymbolAddress((void**)&qhi, g_qhi);
    cudaGetSymbolAddress((void**)&qlo, g_qlo);
    cudaGetSymbolAddress((void**)&khi, g_khi);
    cudaGetSymbolAddress((void**)&klo, g_klo);
    cudaGetSymbolAddress((void**)&vhi, g_vhi);
    cudaGetSymbolAddress((void**)&vlo, g_vlo);

    const int M = MROWS;  // 4096

    cudaFuncSetAttribute(attn_tc, cudaFuncAttributeMaxDynamicSharedMemorySize,
                         ATTN_SMEM);

    // 1) x -> x2
    convert_act<<<(M * 2048 + 255) / 256, 256>>>(x, 2048, 0, 2048, x2);
    // 2) W_dkv
    convert_w<<<(2048 * 1024 + 255) / 256, 256>>>(W_dkv, 2048, 1024, wdkv2);
    // 3) W_o (independent, placed here so the big GEMM is launch #4 for ncu)
    convert_w<<<(2048 * 2048 + 255) / 256, 256>>>(W_o, 2048, 2048, wo2);
    // 4) h = x @ W_dkv + b_dkv            [4096,1024]   <-- profiled launch
    gemm_bf16tc<<<dim3(1024 / 128, M / 128), 256>>>(x2, 6144, 0, wdkv2, 1024, 6144, b_dkv, h, 1024);
    // 5) kr_lin = h @ W_kr + b_kr         [4096,64]
    sgemm_bias<<<dim3(64 / GBN, M / GBM), 256>>>(h, 1024, 0, W_kr, b_kr, kr, 64, M, 64, 1024);
    // 6) h -> h2
    convert_act<<<(M * 1024 + 255) / 256, 256>>>(h, 1024, 0, 1024, h2);
    // 7) W_qr
    convert_w<<<(1024 * 1024 + 255) / 256, 256>>>(W_qr, 1024, 1024, wqr2);
    // 8) qr_lin = h @ W_qr + b_qr         [4096,1024]
    gemm_bf16tc<<<dim3(1024 / 128, M / 128), 256>>>(h2, 3072, 0, wqr2, 1024, 3072, b_qr, qr, 1024);
    // 9,10) RoPE
    rope_kernel<<<(M * 32 + 255) / 256, 256>>>(kr, M, 64);
    rope_kernel<<<(M * 512 + 255) / 256, 256>>>(qr, M, 1024);
    // 11,12) W_uv, W_uq
    convert_w<<<(512 * 4096 + 255) / 256, 256>>>(W_uv, 512, 4096, wuv2);
    convert_w<<<(512 * 2048 + 255) / 256, 256>>>(W_uq, 512, 2048, wuq2);
    // 13) kv = cKV @ W_uv + b_uv          [4096,4096]
    gemm_bf16tc<<<dim3(4096 / 128, M / 128), 256>>>(h2, 3072, 0, wuv2, 4096, 1536, b_uv, kvb, 4096);
    // 14) q = cq @ W_uq + b_uq            [4096,2048]
    gemm_bf16tc<<<dim3(2048 / 128, M / 128), 256>>>(h2, 3072, 1536, wuq2, 2048, 1536, b_uq, qb, 2048);
    // 15-17) attention hi/lo buffers
    build_q<<<(BB * NHH * TT * 192 + 255) / 256, 256>>>(qb, qr, qhi, qlo);
    build_k<<<(BB * NHH * TT * 192 + 255) / 256, 256>>>(kvb, kr, khi, klo);
    build_v<<<(BB * NHH * TT * 128 + 255) / 256, 256>>>(kvb, vhi, vlo);
    // 18) attention
    attn_tc<<<dim3(TT / 128, BB * NHH), 256, ATTN_SMEM>>>(qhi, qlo, khi, klo, vhi, vlo, attn);
    // 19) attn -> attn2
    convert_act<<<(M * 2048 + 255) / 256, 256>>>(attn, 2048, 0, 2048, attn2);
    // 20) out = attn @ W_o + b_o          [4096,2048]
    gemm_bf16tc<<<dim3(2048 / 128, M / 128), 256>>>(attn2, 6144, 0, wo2, 2048, 6144, b_o, out, 2048);
}

// round 8
// speedup vs baseline: 2.0679x; 1.1505x over previous
#include <cuda_runtime.h>
#include <cuda_bf16.h>
#include <math.h>
#include <stdint.h>

// Problem constants
#define BB   2
#define TT   2048
#define CC   2048
#define NHH  16
#define DKK  128
#define LATT 512
#define DHRR 64
#define MROWS (BB * TT)   // 4096

typedef __nv_bfloat16 bf16;

// ---------------------------------------------------------------------------
// Scratch (static device globals -- no allocation allowed)
// ---------------------------------------------------------------------------
__device__ float g_h   [(size_t)MROWS * 1024];
__device__ float g_kr  [(size_t)MROWS * 64];
__device__ float g_qr  [(size_t)MROWS * 1024];
__device__ float g_kv  [(size_t)MROWS * 4096];
__device__ float g_q   [(size_t)MROWS * 2048];
__device__ float g_attn[(size_t)MROWS * 2048];

// hi/lo split activations (row-major [M][K])
__device__ bf16 g_xhi [(size_t)MROWS * 2048];
__device__ bf16 g_xlo [(size_t)MROWS * 2048];
__device__ bf16 g_hhi [(size_t)MROWS * 1024];
__device__ bf16 g_hlo [(size_t)MROWS * 1024];
__device__ bf16 g_athi[(size_t)MROWS * 2048];
__device__ bf16 g_atlo[(size_t)MROWS * 2048];

// hi/lo split transposed weights ([N][K] K-major)
__device__ bf16 g_wdkvh[(size_t)1024 * 2048];
__device__ bf16 g_wdkvl[(size_t)1024 * 2048];
__device__ bf16 g_wqrh [(size_t)1024 * 1024];
__device__ bf16 g_wqrl [(size_t)1024 * 1024];
__device__ bf16 g_wuvh [(size_t)4096 * 512];
__device__ bf16 g_wuvl [(size_t)4096 * 512];
__device__ bf16 g_wuqh [(size_t)2048 * 512];
__device__ bf16 g_wuql [(size_t)2048 * 512];
__device__ bf16 g_woh  [(size_t)2048 * 2048];
__device__ bf16 g_wol  [(size_t)2048 * 2048];

// attention hi/lo buffers, per-head contiguous
__device__ bf16 g_qhi[(size_t)BB * NHH * TT * 192];
__device__ bf16 g_qlo[(size_t)BB * NHH * TT * 192];
__device__ bf16 g_khi[(size_t)BB * NHH * TT * 192];
__device__ bf16 g_klo[(size_t)BB * NHH * TT * 192];
__device__ bf16 g_vhi[(size_t)BB * NHH * TT * 128];
__device__ bf16 g_vlo[(size_t)BB * NHH * TT * 128];

// ---------------------------------------------------------------------------
// PTX helpers
// ---------------------------------------------------------------------------
__device__ __forceinline__ uint32_t smem_u32(const void* p)
{ return (uint32_t)__cvta_generic_to_shared(p); }

__device__ __forceinline__ void cp16(uint32_t dst, const void* src)
{ asm volatile("cp.async.cg.shared.global [%0], [%1], 16;\n" :: "r"(dst), "l"(src)); }

__device__ __forceinline__ void cp_commit()
{ asm volatile("cp.async.commit_group;\n"); }

template <int N>
__device__ __forceinline__ void cp_wait()
{ asm volatile("cp.async.wait_group %0;\n" :: "n"(N)); }

__device__ __forceinline__ void ldm_x4(uint32_t* r, uint32_t addr)
{
    asm volatile("ldmatrix.sync.aligned.m8n8.x4.shared.b16 {%0,%1,%2,%3}, [%4];\n"
        : "=r"(r[0]), "=r"(r[1]), "=r"(r[2]), "=r"(r[3]) : "r"(addr));
}
__device__ __forceinline__ void ldm_x4t(uint32_t* r, uint32_t addr)
{
    asm volatile("ldmatrix.sync.aligned.m8n8.x4.trans.shared.b16 {%0,%1,%2,%3}, [%4];\n"
        : "=r"(r[0]), "=r"(r[1]), "=r"(r[2]), "=r"(r[3]) : "r"(addr));
}
__device__ __forceinline__ void mma_bf16(float* d, const uint32_t* a, const uint32_t* b)
{
    asm volatile(
        "mma.sync.aligned.m16n8k16.row.col.f32.bf16.bf16.f32 "
        "{%0,%1,%2,%3}, {%4,%5,%6,%7}, {%8,%9}, {%0,%1,%2,%3};\n"
        : "+f"(d[0]), "+f"(d[1]), "+f"(d[2]), "+f"(d[3])
        : "r"(a[0]), "r"(a[1]), "r"(a[2]), "r"(a[3]), "r"(b[0]), "r"(b[1]));
}
__device__ __forceinline__ float ex2f(float x)
{ float y; asm("ex2.approx.f32 %0, %1;" : "=f"(y) : "f"(x)); return y; }

__device__ __forceinline__ uint32_t packbf2(float lo, float hi)
{ uint32_t d; asm("cvt.rn.bf16x2.f32 %0, %1, %2;" : "=r"(d) : "f"(hi), "f"(lo)); return d; }

// ---------------------------------------------------------------------------
// Conversion: fp32 activation -> hi/lo bf16 (coalesced, vectorized)
// ---------------------------------------------------------------------------
__global__ void split_act(const float* __restrict__ A, int lda, int aoff, int Kw,
                          bf16* __restrict__ hi, bf16* __restrict__ lo)
{
    int idx = blockIdx.x * blockDim.x + threadIdx.x;
    int total = MROWS * (Kw / 4);
    if (idx >= total) return;
    int m = idx / (Kw / 4), k4 = (idx - m * (Kw / 4)) * 4;
    float4 v = *(const float4*)&A[(size_t)m * lda + aoff + k4];
    float h0 = __bfloat162float(__float2bfloat16(v.x));
    float h1 = __bfloat162float(__float2bfloat16(v.y));
    float h2 = __bfloat162float(__float2bfloat16(v.z));
    float h3 = __bfloat162float(__float2bfloat16(v.w));
    uint2 ph, pl;
    ph.x = packbf2(h0, h1); ph.y = packbf2(h2, h3);
    pl.x = packbf2(v.x - h0, v.y - h1); pl.y = packbf2(v.z - h2, v.w - h3);
    *(uint2*)&hi[(size_t)m * Kw + k4] = ph;
    *(uint2*)&lo[(size_t)m * Kw + k4] = pl;
}

// Weight: W[K][N] fp32 -> hiT/loT [N][K] bf16 (tiled transpose)
__global__ void wsplit_t(const float* __restrict__ W, int K, int N,
                         bf16* __restrict__ hiT, bf16* __restrict__ loT)
{
    __shared__ float t[32][33];
    int tx = threadIdx.x & 31, ty = threadIdx.x >> 5;
    int k0 = blockIdx.y * 32, n0 = blockIdx.x * 32;
#pragma unroll
    for (int r = 0; r < 4; r++)
        t[ty + 8 * r][tx] = W[(size_t)(k0 + ty + 8 * r) * N + n0 + tx];
    __syncthreads();
#pragma unroll
    for (int r = 0; r < 4; r++) {
        float v = t[tx][ty + 8 * r];
        bf16 h = __float2bfloat16(v);
        size_t o = (size_t)(n0 + ty + 8 * r) * K + k0 + tx;
        hiT[o] = h;
        loT[o] = __float2bfloat16(v - __bfloat162float(h));
    }
}

// ---------------------------------------------------------------------------
// HMMA GEMM, compensated hi/lo: Y[M,N] = A @ W^T + bias.
// A hi/lo [M][K] (lda, aoff); B hi/lo [N][K] (ldb).
// Block 128x256x32, 256 threads (8 warps 2x4), warp tile 64x64,
// 3-stage cp.async pipeline. Requires M%128==0, N%256==0, K%32==0, K>=96.
// ---------------------------------------------------------------------------
#define TST 40                         // smem row stride (bf16): 32 + 8 pad
#define A_ELE (128 * TST)              // one A buffer (elems)
#define B_ELE (256 * TST)              // one B buffer (elems)
#define STG_ELE (2 * A_ELE + 2 * B_ELE)
#define GSMEM (3 * STG_ELE * 2)        // bytes

__global__ __launch_bounds__(256, 1)
void gemm_mma(const bf16* __restrict__ Ahi, const bf16* __restrict__ Alo,
              int lda, int aoff,
              const bf16* __restrict__ Bhi, const bf16* __restrict__ Blo,
              int ldb,
              const float* __restrict__ bias,
              float* __restrict__ Y, int ldy, int K)
{
    extern __shared__ bf16 dsm[];
    const uint32_t sb0 = smem_u32(dsm);

    const int tid = threadIdx.x, lane = tid & 31, wid = tid >> 5;
    const int brow = blockIdx.y * 128, bcol = blockIdx.x * 256;
    const int wm = (wid >> 2) * 64, wn = (wid & 3) * 64;

    // chunk mapping: r = c>>2, seg = (c&3)*8 (16B chunks of a 32-col row)
    const int ra = tid >> 2, sa = (tid & 3) * 8;

    auto issue = [&](int st, int kt) {
        uint32_t s = sb0 + (uint32_t)(st * STG_ELE) * 2;
        int ke = kt * 32;
        // A: 128 rows, 2 chunks/thread per buffer
#pragma unroll
        for (int i = 0; i < 2; i++) {
            int r = ra + i * 64;
            uint32_t d = (uint32_t)(r * TST + sa) * 2;
            cp16(s + d, Ahi + (size_t)(brow + r) * lda + aoff + ke + sa);
            cp16(s + (uint32_t)A_ELE * 2 + d,
                 Alo + (size_t)(brow + r) * lda + aoff + ke + sa);
        }
        // B: 256 rows, 4 chunks/thread per buffer
        uint32_t bbase = s + (uint32_t)(2 * A_ELE) * 2;
#pragma unroll
        for (int i = 0; i < 4; i++) {
            int r = ra + i * 64;
            uint32_t d = (uint32_t)(r * TST + sa) * 2;
            cp16(bbase + d, Bhi + (size_t)(bcol + r) * ldb + ke + sa);
            cp16(bbase + (uint32_t)B_ELE * 2 + d,
                 Blo + (size_t)(bcol + r) * ldb + ke + sa);
        }
        cp_commit();
    };

    float acc[4][8][4];
#pragma unroll
    for (int i = 0; i < 4; i++)
#pragma unroll
        for (int j = 0; j < 8; j++)
#pragma unroll
            for (int f = 0; f < 4; f++) acc[i][j][f] = 0.f;

    const int ntiles = K / 32;
    issue(0, 0);
    issue(1, 1);
    issue(2, 2);

    const int l16 = lane & 15, lhi = (lane >> 4) * 8;
    const int brofs = (lane & 7) + ((lane >> 4) & 1) * 8;   // B non-trans row
    const int bcofs = ((lane >> 3) & 1) * 8;                // B non-trans col

    for (int kt = 0; kt < ntiles; kt++) {
        cp_wait<2>();
        __syncthreads();
        int cur = kt - (kt / 3) * 3;
        uint32_t s = sb0 + (uint32_t)(cur * STG_ELE) * 2;
        uint32_t sAh = s, sAl = s + (uint32_t)A_ELE * 2;
        uint32_t sBh = s + (uint32_t)(2 * A_ELE) * 2;
        uint32_t sBl = sBh + (uint32_t)B_ELE * 2;

#pragma unroll
        for (int kk = 0; kk < 32; kk += 16) {
            uint32_t ah[4][4], al[4][4];
#pragma unroll
            for (int i = 0; i < 4; i++) {
                uint32_t aaddr = (uint32_t)((wm + i * 16 + l16) * TST + kk + lhi) * 2;
                ldm_x4(ah[i], sAh + aaddr);
                ldm_x4(al[i], sAl + aaddr);
            }
#pragma unroll
            for (int j2 = 0; j2 < 4; j2++) {
                uint32_t baddr =
                    (uint32_t)((wn + j2 * 16 + brofs) * TST + kk + bcofs) * 2;
                uint32_t bh[4], bl[4];
                ldm_x4(bh, sBh + baddr);
                ldm_x4(bl, sBl + baddr);
#pragma unroll
                for (int i = 0; i < 4; i++) {
                    mma_bf16(acc[i][2 * j2],     ah[i], bh);
                    mma_bf16(acc[i][2 * j2],     ah[i], bl);
                    mma_bf16(acc[i][2 * j2],     al[i], bh);
                    mma_bf16(acc[i][2 * j2 + 1], ah[i], bh + 2);
                    mma_bf16(acc[i][2 * j2 + 1], ah[i], bl + 2);
                    mma_bf16(acc[i][2 * j2 + 1], al[i], bh + 2);
                }
            }
        }
        __syncthreads();
        if (kt + 3 < ntiles) issue(cur, kt + 3);
    }

    // epilogue: bias + fp32 store
#pragma unroll
    for (int i = 0; i < 4; i++) {
#pragma unroll
        for (int j = 0; j < 8; j++) {
            int r0 = brow + wm + i * 16 + (lane >> 2);
            int c0 = bcol + wn + j * 8 + (lane & 3) * 2;
            float b0 = bias[c0], b1 = bias[c0 + 1];
            float2 v0 = {acc[i][j][0] + b0, acc[i][j][1] + b1};
            float2 v1 = {acc[i][j][2] + b0, acc[i][j][3] + b1};
            *(float2*)&Y[(size_t)r0 * ldy + c0] = v0;
            *(float2*)&Y[(size_t)(r0 + 8) * ldy + c0] = v1;
        }
    }
}

// ---------------------------------------------------------------------------
// Small SGEMM (N=64 W_kr projection only)
// ---------------------------------------------------------------------------
#define GBM 64
#define GBN 64
#define GBK 16

__global__ __launch_bounds__(256)
void sgemm_bias(const float* __restrict__ A, int lda, int aoff,
                const float* __restrict__ W,
                const float* __restrict__ bias,
                float* __restrict__ Y, int ldy,
                int M, int N, int K)
{
    __shared__ float As[GBK][GBM];
    __shared__ float Bs[GBK][GBN];

    const int tid = threadIdx.x;
    const int brow = blockIdx.y * GBM;
    const int bcol = blockIdx.x * GBN;
    const int tr = (tid / 16) * 4;
    const int tc = (tid % 16) * 4;

    float acc[4][4];
#pragma unroll
    for (int i = 0; i < 4; i++)
#pragma unroll
        for (int j = 0; j < 4; j++) acc[i][j] = 0.f;

    for (int k0 = 0; k0 < K; k0 += GBK) {
#pragma unroll
        for (int it = 0; it < (GBM * GBK) / 256; it++) {
            int i = tid + it * 256;
            int m = i / GBK, kk = i % GBK;
            As[kk][m] = A[(size_t)(brow + m) * lda + aoff + k0 + kk];
        }
#pragma unroll
        for (int it = 0; it < (GBK * GBN) / 256; it++) {
            int i = tid + it * 256;
            int kk = i / GBN, n = i % GBN;
            Bs[kk][n] = W[(size_t)(k0 + kk) * N + bcol + n];
        }
        __syncthreads();

#pragma unroll
        for (int kk = 0; kk < GBK; kk++) {
            float a[4], b[4];
#pragma unroll
            for (int i = 0; i < 4; i++) a[i] = As[kk][tr + i];
#pragma unroll
            for (int j = 0; j < 4; j++) b[j] = Bs[kk][tc + j];
#pragma unroll
            for (int i = 0; i < 4; i++)
#pragma unroll
                for (int j = 0; j < 4; j++) acc[i][j] = fmaf(a[i], b[j], acc[i][j]);
        }
        __syncthreads();
    }

#pragma unroll
    for (int i = 0; i < 4; i++)
#pragma unroll
        for (int j = 0; j < 4; j++)
            Y[(size_t)(brow + tr + i) * ldy + bcol + tc + j] =
                acc[i][j] + bias[bcol + tc + j];
}

// ---------------------------------------------------------------------------
// Interleaved RoPE (double-precision trig)
// ---------------------------------------------------------------------------
__global__ void rope_kernel(float* __restrict__ buf, int rows, int c)
{
    const int pairs = c >> 1;
    const int idx = blockIdx.x * blockDim.x + threadIdx.x;
    if (idx >= rows * pairs) return;
    const int row = idx / pairs;
    const int i   = idx - row * pairs;
    const int t   = row & (TT - 1);

    float theta = (float)exp(-2.0 * (double)i / (double)c * log(10000.0));
    float angle = (float)(t + 1) * theta;
    double a = (double)angle;
    float cs = (float)cos(a);
    float sn = (float)sin(a);

    float* p = buf + (size_t)row * c + 2 * i;
    float x0 = p[0], x1 = p[1];
    p[0] = x0 * cs - x1 * sn;
    p[1] = x1 * cs + x0 * sn;
}

// ---------------------------------------------------------------------------
// Attention hi/lo builders
// ---------------------------------------------------------------------------
__global__ void build_q(const float* __restrict__ q, const float* __restrict__ qr,
                        bf16* __restrict__ qhi, bf16* __restrict__ qlo)
{
    const float SCL = (float)(0.08838834764831845 * 1.4426950408889634);
    int idx = blockIdx.x * blockDim.x + threadIdx.x;
    if (idx >= BB * NHH * TT * 192) return;
    int d = idx % 192; int r = idx / 192;
    int t = r % TT; int bh = r / TT; int h = bh & 15; int b = bh >> 4;
    float v;
    if (d < 128) v = q[((size_t)(b * TT + t)) * 2048 + h * 128 + d];
    else         v = qr[((size_t)(b * TT + t)) * 1024 + h * 64 + (d - 128)];
    v *= SCL;
    bf16 hi = __float2bfloat16(v);
    qhi[idx] = hi;
    qlo[idx] = __float2bfloat16(v - __bfloat162float(hi));
}

__global__ void build_k(const float* __restrict__ kv, const float* __restrict__ kr,
                        bf16* __restrict__ khi, bf16* __restrict__ klo)
{
    int idx = blockIdx.x * blockDim.x + threadIdx.x;
    if (idx >= BB * NHH * TT * 192) return;
    int d = idx % 192; int r = idx / 192;
    int t = r % TT; int bh = r / TT; int h = bh & 15; int b = bh >> 4;
    float v;
    if (d < 128) v = kv[((size_t)(b * TT + t)) * 4096 + h * 128 + d];
    else         v = kr[((size_t)(b * TT + t)) * 64 + (d - 128)];
    bf16 hi = __float2bfloat16(v);
    khi[idx] = hi;
    klo[idx] = __float2bfloat16(v - __bfloat162float(hi));
}

__global__ void build_v(const float* __restrict__ kv,
                        bf16* __restrict__ vhi, bf16* __restrict__ vlo)
{
    int idx = blockIdx.x * blockDim.x + threadIdx.x;
    if (idx >= BB * NHH * TT * 128) return;
    int d = idx % 128; int r = idx / 128;
    int t = r % TT; int bh = r / TT; int h = bh & 15; int b = bh >> 4;
    float v = kv[((size_t)(b * TT + t)) * 4096 + 2048 + h * 128 + d];
    bf16 hi = __float2bfloat16(v);
    vhi[idx] = hi;
    vlo[idx] = __float2bfloat16(v - __bfloat162float(hi));
}

// ---------------------------------------------------------------------------
// Tensor-core flash attention, compensated bf16 (unchanged from R6)
// ---------------------------------------------------------------------------
#define QSTR 200
#define KSTR 200
#define VSTR 136
#define ATTN_SMEM ((2*128*QSTR + 2*64*KSTR + 2*64*VSTR) * 2)

__global__ __launch_bounds__(256, 1)
void attn_tc(const bf16* __restrict__ qhi, const bf16* __restrict__ qlo,
             const bf16* __restrict__ khi, const bf16* __restrict__ klo,
             const bf16* __restrict__ vhi, const bf16* __restrict__ vlo,
             float* __restrict__ out)
{
    extern __shared__ bf16 smA[];
    bf16* Qh = smA;
    bf16* Ql = Qh + 128 * QSTR;
    bf16* Kh = Ql + 128 * QSTR;
    bf16* Kl = Kh + 64 * KSTR;
    bf16* Vh = Kl + 64 * KSTR;
    bf16* Vl = Vh + 64 * VSTR;

    const int tid = threadIdx.x, lane = tid & 31, wp = tid >> 5;
    const int bh = blockIdx.y;
    const int qi = gridDim.x - 1 - blockIdx.x;
    const int b = bh >> 4, h = bh & 15;
    const size_t base = (size_t)bh * TT;

    const uint32_t sQh = smem_u32(Qh), sQl = smem_u32(Ql);
    const uint32_t sKh = smem_u32(Kh), sKl = smem_u32(Kl);
    const uint32_t sVh = smem_u32(Vh), sVl = smem_u32(Vl);

    for (int i = tid; i < 128 * 24; i += 256) {
        int r = i / 24, c = (i % 24) * 8;
        size_t g = (base + (size_t)qi * 128 + r) * 192 + c;
        uint32_t d = (uint32_t)(r * QSTR + c) * 2;
        cp16(sQh + d, qhi + g);
        cp16(sQl + d, qlo + g);
    }
    cp_commit();

    float o[16][4];
#pragma unroll
    for (int i = 0; i < 16; i++)
#pragma unroll
        for (int f = 0; f < 4; f++) o[i][f] = 0.f;

    float m1 = -1e30f, m2 = -1e30f, l1 = 0.f, l2 = 0.f;
    const int l16 = lane & 15, lhi = (lane >> 4) * 8;
    const int qrow1 = qi * 128 + wp * 16 + (lane >> 2);
    const int qrow2 = qrow1 + 8;
    const int brofs = (lane & 7) + ((lane >> 4) & 1) * 8;
    const int bcofs = ((lane >> 3) & 1) * 8;

    const int nkt = 2 * qi + 2;
    for (int kt = 0; kt < nkt; kt++) {
        __syncthreads();
        for (int i = tid; i < 64 * 24; i += 256) {
            int r = i / 24, c = (i % 24) * 8;
            size_t g = (base + (size_t)kt * 64 + r) * 192 + c;
            uint32_t d = (uint32_t)(r * KSTR + c) * 2;
            cp16(sKh + d, khi + g);
            cp16(sKl + d, klo + g);
        }
        for (int i = tid; i < 64 * 16; i += 256) {
            int r = i / 16, c = (i % 16) * 8;
            size_t g = (base + (size_t)kt * 64 + r) * 128 + c;
            uint32_t d = (uint32_t)(r * VSTR + c) * 2;
            cp16(sVh + d, vhi + g);
            cp16(sVl + d, vlo + g);
        }
        cp_commit();
        cp_wait<0>();
        __syncthreads();

        float s[8][4];
#pragma unroll
        for (int j = 0; j < 8; j++)
#pragma unroll
            for (int f = 0; f < 4; f++) s[j][f] = 0.f;

#pragma unroll
        for (int kk = 0; kk < 12; kk++) {
            uint32_t ah[4], al[4];
            uint32_t aaddr = (uint32_t)((wp * 16 + l16) * QSTR + kk * 16 + lhi) * 2;
            ldm_x4(ah, sQh + aaddr);
            ldm_x4(al, sQl + aaddr);
#pragma unroll
            for (int j2 = 0; j2 < 4; j2++) {
                uint32_t baddr = (uint32_t)((j2 * 16 + brofs) * KSTR + kk * 16 + bcofs) * 2;
                uint32_t tbv[4], tl[4];
                ldm_x4(tbv, sKh + baddr);
                ldm_x4(tl, sKl + baddr);
                mma_bf16(s[2 * j2],     ah, tbv);
                mma_bf16(s[2 * j2],     ah, tl);
                mma_bf16(s[2 * j2],     al, tbv);
                mma_bf16(s[2 * j2 + 1], ah, tbv + 2);
                mma_bf16(s[2 * j2 + 1], ah, tl + 2);
                mma_bf16(s[2 * j2 + 1], al, tbv + 2);
            }
        }

#pragma unroll
        for (int j = 0; j < 8; j++) {
            int k0 = kt * 64 + j * 8 + 2 * (lane & 3);
            if (k0     > qrow1) s[j][0] = -1e30f;
            if (k0 + 1 > qrow1) s[j][1] = -1e30f;
            if (k0     > qrow2) s[j][2] = -1e30f;
            if (k0 + 1 > qrow2) s[j][3] = -1e30f;
        }
        float mr1 = -1e30f, mr2 = -1e30f;
#pragma unroll
        for (int j = 0; j < 8; j++) {
            mr1 = fmaxf(mr1, fmaxf(s[j][0], s[j][1]));
            mr2 = fmaxf(mr2, fmaxf(s[j][2], s[j][3]));
        }
        mr1 = fmaxf(mr1, __shfl_xor_sync(0xffffffffu, mr1, 1));
        mr1 = fmaxf(mr1, __shfl_xor_sync(0xffffffffu, mr1, 2));
        mr2 = fmaxf(mr2, __shfl_xor_sync(0xffffffffu, mr2, 1));
        mr2 = fmaxf(mr2, __shfl_xor_sync(0xffffffffu, mr2, 2));
        float mn1 = fmaxf(m1, mr1), mn2 = fmaxf(m2, mr2);
        float a1 = ex2f(m1 - mn1), a2 = ex2f(m2 - mn2);
        m1 = mn1; m2 = mn2;

        uint32_t phx[8][2], plx[8][2];
        float rs1 = 0.f, rs2 = 0.f;
#pragma unroll
        for (int j = 0; j < 8; j++) {
            float p0 = ex2f(s[j][0] - mn1), p1 = ex2f(s[j][1] - mn1);
            float p2 = ex2f(s[j][2] - mn2), p3 = ex2f(s[j][3] - mn2);
            rs1 += p0 + p1; rs2 += p2 + p3;
            phx[j][0] = packbf2(p0, p1);
            phx[j][1] = packbf2(p2, p3);
            float q0 = p0 - __bfloat162float(__float2bfloat16(p0));
            float q1 = p1 - __bfloat162float(__float2bfloat16(p1));
            float q2 = p2 - __bfloat162float(__float2bfloat16(p2));
            float q3 = p3 - __bfloat162float(__float2bfloat16(p3));
            plx[j][0] = packbf2(q0, q1);
            plx[j][1] = packbf2(q2, q3);
        }
        rs1 += __shfl_xor_sync(0xffffffffu, rs1, 1);
        rs1 += __shfl_xor_sync(0xffffffffu, rs1, 2);
        rs2 += __shfl_xor_sync(0xffffffffu, rs2, 1);
        rs2 += __shfl_xor_sync(0xffffffffu, rs2, 2);
        l1 = l1 * a1 + rs1;
        l2 = l2 * a2 + rs2;
#pragma unroll
        for (int t16 = 0; t16 < 16; t16++) {
            o[t16][0] *= a1; o[t16][1] *= a1;
            o[t16][2] *= a2; o[t16][3] *= a2;
        }

#pragma unroll
        for (int kt2 = 0; kt2 < 4; kt2++) {
            uint32_t pa_h[4] = {phx[2 * kt2][0], phx[2 * kt2][1],
                                phx[2 * kt2 + 1][0], phx[2 * kt2 + 1][1]};
            uint32_t pa_l[4] = {plx[2 * kt2][0], plx[2 * kt2][1],
                                plx[2 * kt2 + 1][0], plx[2 * kt2 + 1][1]};
            uint32_t vrow = (uint32_t)((kt2 * 16 + l16) * VSTR) * 2;
#pragma unroll
            for (int j2 = 0; j2 < 8; j2++) {
                uint32_t vaddr = vrow + (uint32_t)(j2 * 16 + lhi) * 2;
                uint32_t tv[4], tw[4];
                ldm_x4t(tv, sVh + vaddr);
                ldm_x4t(tw, sVl + vaddr);
                mma_bf16(o[2 * j2],     pa_h, tv);
                mma_bf16(o[2 * j2],     pa_h, tw);
                mma_bf16(o[2 * j2],     pa_l, tv);
                mma_bf16(o[2 * j2 + 1], pa_h, tv + 2);
                mma_bf16(o[2 * j2 + 1], pa_h, tw + 2);
                mma_bf16(o[2 * j2 + 1], pa_l, tv + 2);
            }
        }
    }

    float inv1 = 1.f / l1, inv2 = 1.f / l2;
    size_t row1 = (size_t)(b * TT + qrow1) * 2048 + h * 128;
    size_t row2 = (size_t)(b * TT + qrow2) * 2048 + h * 128;
#pragma unroll
    for (int t16 = 0; t16 < 16; t16++) {
        int col = t16 * 8 + 2 * (lane & 3);
        float2 v1 = {o[t16][0] * inv1, o[t16][1] * inv1};
        float2 v2 = {o[t16][2] * inv2, o[t16][3] * inv2};
        *(float2*)&out[row1 + col] = v1;
        *(float2*)&out[row2 + col] = v2;
    }
}

// ---------------------------------------------------------------------------
// Host launcher
// ---------------------------------------------------------------------------
extern "C" void kernel_launch(void* const* d_in, const int* in_sizes, int n_in,
                              void* d_out, int out_size)
{
    (void)in_sizes; (void)n_in; (void)out_size;

    const float* x     = (const float*)d_in[0];
    const float* W_dkv = (const float*)d_in[1];
    const float* b_dkv = (const float*)d_in[2];
    const float* W_kr  = (const float*)d_in[3];
    const float* b_kr  = (const float*)d_in[4];
    const float* W_qr  = (const float*)d_in[5];
    const float* b_qr  = (const float*)d_in[6];
    const float* W_uv  = (const float*)d_in[7];
    const float* b_uv  = (const float*)d_in[8];
    const float* W_uq  = (const float*)d_in[9];
    const float* b_uq  = (const float*)d_in[10];
    const float* W_o   = (const float*)d_in[11];
    const float* b_o   = (const float*)d_in[12];
    float* out = (float*)d_out;

    float *h, *kr, *qr, *kvb, *qb, *attn;
    bf16 *xhi, *xlo, *hhi, *hlo, *athi, *atlo;
    bf16 *wdkvh, *wdkvl, *wqrh, *wqrl, *wuvh, *wuvl, *wuqh, *wuql, *woh, *wol;
    bf16 *qhi, *qlo, *khi, *klo, *vhi, *vlo;
    cudaGetSymbolAddress((void**)&h,    g_h);
    cudaGetSymbolAddress((void**)&kr,   g_kr);
    cudaGetSymbolAddress((void**)&qr,   g_qr);
    cudaGetSymbolAddress((void**)&kvb,  g_kv);
    cudaGetSymbolAddress((void**)&qb,   g_q);
    cudaGetSymbolAddress((void**)&attn, g_attn);
    cudaGetSymbolAddress((void**)&xhi,  g_xhi);
    cudaGetSymbolAddress((void**)&xlo,  g_xlo);
    cudaGetSymbolAddress((void**)&hhi,  g_hhi);
    cudaGetSymbolAddress((void**)&hlo,  g_hlo);
    cudaGetSymbolAddress((void**)&athi, g_athi);
    cudaGetSymbolAddress((void**)&atlo, g_atlo);
    cudaGetSymbolAddress((void**)&wdkvh, g_wdkvh);
    cudaGetSymbolAddress((void**)&wdkvl, g_wdkvl);
    cudaGetSymbolAddress((void**)&wqrh, g_wqrh);
    cudaGetSymbolAddress((void**)&wqrl, g_wqrl);
    cudaGetSymbolAddress((void**)&wuvh, g_wuvh);
    cudaGetSymbolAddress((void**)&wuvl, g_wuvl);
    cudaGetSymbolAddress((void**)&wuqh, g_wuqh);
    cudaGetSymbolAddress((void**)&wuql, g_wuql);
    cudaGetSymbolAddress((void**)&woh,  g_woh);
    cudaGetSymbolAddress((void**)&wol,  g_wol);
    cudaGetSymbolAddress((void**)&qhi, g_qhi);
    cudaGetSymbolAddress((void**)&qlo, g_qlo);
    cudaGetSymbolAddress((void**)&khi, g_khi);
    cudaGetSymbolAddress((void**)&klo, g_klo);
    cudaGetSymbolAddress((void**)&vhi, g_vhi);
    cudaGetSymbolAddress((void**)&vlo, g_vlo);

    const int M = MROWS;  // 4096

    cudaFuncSetAttribute(gemm_mma, cudaFuncAttributeMaxDynamicSharedMemorySize, GSMEM);
    cudaFuncSetAttribute(attn_tc, cudaFuncAttributeMaxDynamicSharedMemorySize, ATTN_SMEM);

    // 1) x -> hi/lo
    split_act<<<(M * 512 + 255) / 256, 256>>>(x, 2048, 0, 2048, xhi, xlo);
    // 2) W_dkv -> [1024][2048]
    wsplit_t<<<dim3(1024 / 32, 2048 / 32), 256>>>(W_dkv, 2048, 1024, wdkvh, wdkvl);
    // 3) W_o -> [2048][2048]
    wsplit_t<<<dim3(2048 / 32, 2048 / 32), 256>>>(W_o, 2048, 2048, woh, wol);
    // 4) h = x @ W_dkv + b_dkv    [4096,1024]   <-- profiled launch
    gemm_mma<<<dim3(4, 32), 256, GSMEM>>>(xhi, xlo, 2048, 0, wdkvh, wdkvl, 2048,
                                          b_dkv, h, 1024, 2048);
    // 5) kr
    sgemm_bias<<<dim3(1, 64), 256>>>(h, 1024, 0, W_kr, b_kr, kr, 64, M, 64, 1024);
    // 6) h -> hi/lo
    split_act<<<(M * 256 + 255) / 256, 256>>>(h, 1024, 0, 1024, hhi, hlo);
    // 7) W_qr
    wsplit_t<<<dim3(1024 / 32, 1024 / 32), 256>>>(W_qr, 1024, 1024, wqrh, wqrl);
    // 8) qr = h @ W_qr
    gemm_mma<<<dim3(4, 32), 256, GSMEM>>>(hhi, hlo, 1024, 0, wqrh, wqrl, 1024,
                                          b_qr, qr, 1024, 1024);
    // 9,10) RoPE
    rope_kernel<<<(M * 32 + 255) / 256, 256>>>(kr, M, 64);
    rope_kernel<<<(M * 512 + 255) / 256, 256>>>(qr, M, 1024);
    // 11,12) W_uv, W_uq
    wsplit_t<<<dim3(4096 / 32, 512 / 32), 256>>>(W_uv, 512, 4096, wuvh, wuvl);
    wsplit_t<<<dim3(2048 / 32, 512 / 32), 256>>>(W_uq, 512, 2048, wuqh, wuql);
    // 13) kv = cKV @ W_uv   [4096,4096]
    gemm_mma<<<dim3(16, 32), 256, GSMEM>>>(hhi, hlo, 1024, 0, wuvh, wuvl, 512,
                                           b_uv, kvb, 4096, 512);
    // 14) q = cq @ W_uq     [4096,2048]
    gemm_mma<<<dim3(8, 32), 256, GSMEM>>>(hhi, hlo, 1024, 512, wuqh, wuql, 512,
                                          b_uq, qb, 2048, 512);
    // 15-17) attention hi/lo buffers
    build_q<<<(BB * NHH * TT * 192 + 255) / 256, 256>>>(qb, qr, qhi, qlo);
    build_k<<<(BB * NHH * TT * 192 + 255) / 256, 256>>>(kvb, kr, khi, klo);
    build_v<<<(BB * NHH * TT * 128 + 255) / 256, 256>>>(kvb, vhi, vlo);
    // 18) attention
    attn_tc<<<dim3(TT / 128, BB * NHH), 256, ATTN_SMEM>>>(qhi, qlo, khi, klo, vhi, vlo, attn);
    // 19) attn -> hi/lo
    split_act<<<(M * 512 + 255) / 256, 256>>>(attn, 2048, 0, 2048, athi, atlo);
    // 20) out = attn @ W_o + b_o   [4096,2048]
    gemm_mma<<<dim3(8, 32), 256, GSMEM>>>(athi, atlo, 2048, 0, woh, wol, 2048,
                                          b_o, out, 2048, 2048);
}

// round 9
// speedup vs baseline: 2.1405x; 1.0351x over previous
#include <cuda_runtime.h>
#include <cuda_bf16.h>
#include <math.h>
#include <stdint.h>

// Problem constants
#define BB   2
#define TT   2048
#define CC   2048
#define NHH  16
#define DKK  128
#define LATT 512
#define DHRR 64
#define MROWS (BB * TT)   // 4096

typedef __nv_bfloat16 bf16;

// ---------------------------------------------------------------------------
// Scratch (static device globals -- no allocation allowed)
// ---------------------------------------------------------------------------
__device__ float g_h   [(size_t)MROWS * 1024];
__device__ float g_kr  [(size_t)MROWS * 64];
__device__ float g_qr  [(size_t)MROWS * 1024];
__device__ float g_kv  [(size_t)MROWS * 4096];
__device__ float g_q   [(size_t)MROWS * 2048];
__device__ float g_attn[(size_t)MROWS * 2048];

// hi/lo split activations (row-major [M][K])
__device__ bf16 g_xhi [(size_t)MROWS * 2048];
__device__ bf16 g_xlo [(size_t)MROWS * 2048];
__device__ bf16 g_hhi [(size_t)MROWS * 1024];
__device__ bf16 g_hlo [(size_t)MROWS * 1024];
__device__ bf16 g_athi[(size_t)MROWS * 2048];
__device__ bf16 g_atlo[(size_t)MROWS * 2048];

// hi/lo split transposed weights ([N][K] K-major)
__device__ bf16 g_wdkvh[(size_t)1024 * 2048];
__device__ bf16 g_wdkvl[(size_t)1024 * 2048];
__device__ bf16 g_wqrh [(size_t)1024 * 1024];
__device__ bf16 g_wqrl [(size_t)1024 * 1024];
__device__ bf16 g_wuvh [(size_t)4096 * 512];
__device__ bf16 g_wuvl [(size_t)4096 * 512];
__device__ bf16 g_wuqh [(size_t)2048 * 512];
__device__ bf16 g_wuql [(size_t)2048 * 512];
__device__ bf16 g_woh  [(size_t)2048 * 2048];
__device__ bf16 g_wol  [(size_t)2048 * 2048];

// attention hi/lo buffers, per-head contiguous
__device__ bf16 g_qhi[(size_t)BB * NHH * TT * 192];
__device__ bf16 g_qlo[(size_t)BB * NHH * TT * 192];
__device__ bf16 g_khi[(size_t)BB * NHH * TT * 192];
__device__ bf16 g_klo[(size_t)BB * NHH * TT * 192];
__device__ bf16 g_vhi[(size_t)BB * NHH * TT * 128];
__device__ bf16 g_vlo[(size_t)BB * NHH * TT * 128];

// ---------------------------------------------------------------------------
// PTX helpers
// ---------------------------------------------------------------------------
__device__ __forceinline__ uint32_t smem_u32(const void* p)
{ return (uint32_t)__cvta_generic_to_shared(p); }

__device__ __forceinline__ void cp16(uint32_t dst, const void* src)
{ asm volatile("cp.async.cg.shared.global [%0], [%1], 16;\n" :: "r"(dst), "l"(src)); }

__device__ __forceinline__ void cp_commit()
{ asm volatile("cp.async.commit_group;\n"); }

template <int N>
__device__ __forceinline__ void cp_wait()
{ asm volatile("cp.async.wait_group %0;\n" :: "n"(N)); }

__device__ __forceinline__ void ldm_x4(uint32_t* r, uint32_t addr)
{
    asm volatile("ldmatrix.sync.aligned.m8n8.x4.shared.b16 {%0,%1,%2,%3}, [%4];\n"
        : "=r"(r[0]), "=r"(r[1]), "=r"(r[2]), "=r"(r[3]) : "r"(addr));
}
__device__ __forceinline__ void ldm_x4t(uint32_t* r, uint32_t addr)
{
    asm volatile("ldmatrix.sync.aligned.m8n8.x4.trans.shared.b16 {%0,%1,%2,%3}, [%4];\n"
        : "=r"(r[0]), "=r"(r[1]), "=r"(r[2]), "=r"(r[3]) : "r"(addr));
}
__device__ __forceinline__ void mma_bf16(float* d, const uint32_t* a, const uint32_t* b)
{
    asm volatile(
        "mma.sync.aligned.m16n8k16.row.col.f32.bf16.bf16.f32 "
        "{%0,%1,%2,%3}, {%4,%5,%6,%7}, {%8,%9}, {%0,%1,%2,%3};\n"
        : "+f"(d[0]), "+f"(d[1]), "+f"(d[2]), "+f"(d[3])
        : "r"(a[0]), "r"(a[1]), "r"(a[2]), "r"(a[3]), "r"(b[0]), "r"(b[1]));
}
__device__ __forceinline__ float ex2f(float x)
{ float y; asm("ex2.approx.f32 %0, %1;" : "=f"(y) : "f"(x)); return y; }

__device__ __forceinline__ uint32_t packbf2(float lo, float hi)
{ uint32_t d; asm("cvt.rn.bf16x2.f32 %0, %1, %2;" : "=r"(d) : "f"(hi), "f"(lo)); return d; }

// ---------------------------------------------------------------------------
// Conversion: fp32 activation -> hi/lo bf16 (coalesced, vectorized)
// ---------------------------------------------------------------------------
__global__ void split_act(const float* __restrict__ A, int lda, int aoff, int Kw,
                          bf16* __restrict__ hi, bf16* __restrict__ lo)
{
    int idx = blockIdx.x * blockDim.x + threadIdx.x;
    int total = MROWS * (Kw / 4);
    if (idx >= total) return;
    int m = idx / (Kw / 4), k4 = (idx - m * (Kw / 4)) * 4;
    float4 v = *(const float4*)&A[(size_t)m * lda + aoff + k4];
    float h0 = __bfloat162float(__float2bfloat16(v.x));
    float h1 = __bfloat162float(__float2bfloat16(v.y));
    float h2 = __bfloat162float(__float2bfloat16(v.z));
    float h3 = __bfloat162float(__float2bfloat16(v.w));
    uint2 ph, pl;
    ph.x = packbf2(h0, h1); ph.y = packbf2(h2, h3);
    pl.x = packbf2(v.x - h0, v.y - h1); pl.y = packbf2(v.z - h2, v.w - h3);
    *(uint2*)&hi[(size_t)m * Kw + k4] = ph;
    *(uint2*)&lo[(size_t)m * Kw + k4] = pl;
}

// Weight: W[K][N] fp32 -> hiT/loT [N][K] bf16 (tiled transpose)
__global__ void wsplit_t(const float* __restrict__ W, int K, int N,
                         bf16* __restrict__ hiT, bf16* __restrict__ loT)
{
    __shared__ float t[32][33];
    int tx = threadIdx.x & 31, ty = threadIdx.x >> 5;
    int k0 = blockIdx.y * 32, n0 = blockIdx.x * 32;
#pragma unroll
    for (int r = 0; r < 4; r++)
        t[ty + 8 * r][tx] = W[(size_t)(k0 + ty + 8 * r) * N + n0 + tx];
    __syncthreads();
#pragma unroll
    for (int r = 0; r < 4; r++) {
        float v = t[tx][ty + 8 * r];
        bf16 h = __float2bfloat16(v);
        size_t o = (size_t)(n0 + ty + 8 * r) * K + k0 + tx;
        hiT[o] = h;
        loT[o] = __float2bfloat16(v - __bfloat162float(h));
    }
}

// ---------------------------------------------------------------------------
// HMMA GEMM, compensated hi/lo: Y[M,N] = A @ W^T + bias.
// A hi/lo [M][K] (lda, aoff); B hi/lo [N][K] (ldb).
// Block 128x128x32, 128 threads (4 warps 2x2), warp tile 64x64,
// 2-stage cp.async pipeline, 2 CTAs/SM. Requires M%128==0, N%128==0, K%32==0.
// ---------------------------------------------------------------------------
#define TST 40                         // smem row stride (bf16): 32 + 8 pad
#define A_ELE (128 * TST)
#define B_ELE (128 * TST)
#define STG_ELE (2 * A_ELE + 2 * B_ELE)
#define GSMEM (2 * STG_ELE * 2)        // 2 stages, bytes = 81920

__global__ __launch_bounds__(128, 2)
void gemm_mma(const bf16* __restrict__ Ahi, const bf16* __restrict__ Alo,
              int lda, int aoff,
              const bf16* __restrict__ Bhi, const bf16* __restrict__ Blo,
              int ldb,
              const float* __restrict__ bias,
              float* __restrict__ Y, int ldy, int K)
{
    extern __shared__ bf16 dsm[];
    const uint32_t sb0 = smem_u32(dsm);

    const int tid = threadIdx.x, lane = tid & 31, wid = tid >> 5;
    const int brow = blockIdx.y * 128, bcol = blockIdx.x * 128;
    const int wm = (wid >> 1) * 64, wn = (wid & 1) * 64;

    auto issue = [&](int st, int kt) {
        uint32_t s = sb0 + (uint32_t)(st * STG_ELE) * 2;
        int ke = kt * 32;
        // 512 16B-chunks per buffer; 128 threads -> 4 chunks each
#pragma unroll
        for (int i = 0; i < 4; i++) {
            int c = tid + i * 128;
            int r = c >> 2, sg = (c & 3) * 8;
            uint32_t d = (uint32_t)(r * TST + sg) * 2;
            cp16(s + d, Ahi + (size_t)(brow + r) * lda + aoff + ke + sg);
            cp16(s + (uint32_t)A_ELE * 2 + d,
                 Alo + (size_t)(brow + r) * lda + aoff + ke + sg);
            cp16(s + (uint32_t)(2 * A_ELE) * 2 + d,
                 Bhi + (size_t)(bcol + r) * ldb + ke + sg);
            cp16(s + (uint32_t)(2 * A_ELE + B_ELE) * 2 + d,
                 Blo + (size_t)(bcol + r) * ldb + ke + sg);
        }
        cp_commit();
    };

    float acc[4][8][4];
#pragma unroll
    for (int i = 0; i < 4; i++)
#pragma unroll
        for (int j = 0; j < 8; j++)
#pragma unroll
            for (int f = 0; f < 4; f++) acc[i][j][f] = 0.f;

    const int ntiles = K / 32;
    issue(0, 0);
    issue(1, 1);

    const int l16 = lane & 15, lhi = (lane >> 4) * 8;
    const int brofs = (lane & 7) + ((lane >> 4) & 1) * 8;   // B non-trans row
    const int bcofs = ((lane >> 3) & 1) * 8;                // B non-trans col

    for (int kt = 0; kt < ntiles; kt++) {
        if (kt + 1 < ntiles) { cp_wait<1>(); } else { cp_wait<0>(); }
        __syncthreads();
        int cur = kt & 1;
        uint32_t s = sb0 + (uint32_t)(cur * STG_ELE) * 2;
        uint32_t sAh = s, sAl = s + (uint32_t)A_ELE * 2;
        uint32_t sBh = s + (uint32_t)(2 * A_ELE) * 2;
        uint32_t sBl = sBh + (uint32_t)B_ELE * 2;

#pragma unroll
        for (int kk = 0; kk < 32; kk += 16) {
            uint32_t ah[4][4], al[4][4];
#pragma unroll
            for (int i = 0; i < 4; i++) {
                uint32_t aaddr = (uint32_t)((wm + i * 16 + l16) * TST + kk + lhi) * 2;
                ldm_x4(ah[i], sAh + aaddr);
                ldm_x4(al[i], sAl + aaddr);
            }
#pragma unroll
            for (int j2 = 0; j2 < 4; j2++) {
                uint32_t baddr =
                    (uint32_t)((wn + j2 * 16 + brofs) * TST + kk + bcofs) * 2;
                uint32_t bh[4], bl[4];
                ldm_x4(bh, sBh + baddr);
                ldm_x4(bl, sBl + baddr);
#pragma unroll
                for (int i = 0; i < 4; i++) {
                    mma_bf16(acc[i][2 * j2],     ah[i], bh);
                    mma_bf16(acc[i][2 * j2],     ah[i], bl);
                    mma_bf16(acc[i][2 * j2],     al[i], bh);
                    mma_bf16(acc[i][2 * j2 + 1], ah[i], bh + 2);
                    mma_bf16(acc[i][2 * j2 + 1], ah[i], bl + 2);
                    mma_bf16(acc[i][2 * j2 + 1], al[i], bh + 2);
                }
            }
        }
        __syncthreads();
        if (kt + 2 < ntiles) issue(cur, kt + 2);
    }

    // epilogue: bias + fp32 store
#pragma unroll
    for (int i = 0; i < 4; i++) {
#pragma unroll
        for (int j = 0; j < 8; j++) {
            int r0 = brow + wm + i * 16 + (lane >> 2);
            int c0 = bcol + wn + j * 8 + (lane & 3) * 2;
            float b0 = bias[c0], b1 = bias[c0 + 1];
            float2 v0 = {acc[i][j][0] + b0, acc[i][j][1] + b1};
            float2 v1 = {acc[i][j][2] + b0, acc[i][j][3] + b1};
            *(float2*)&Y[(size_t)r0 * ldy + c0] = v0;
            *(float2*)&Y[(size_t)(r0 + 8) * ldy + c0] = v1;
        }
    }
}

// ---------------------------------------------------------------------------
// Small SGEMM (N=64 W_kr projection only)
// ---------------------------------------------------------------------------
#define GBM 64
#define GBN 64
#define GBK 16

__global__ __launch_bounds__(256)
void sgemm_bias(const float* __restrict__ A, int lda, int aoff,
                const float* __restrict__ W,
                const float* __restrict__ bias,
                float* __restrict__ Y, int ldy,
                int M, int N, int K)
{
    __shared__ float As[GBK][GBM];
    __shared__ float Bs[GBK][GBN];

    const int tid = threadIdx.x;
    const int brow = blockIdx.y * GBM;
    const int bcol = blockIdx.x * GBN;
    const int tr = (tid / 16) * 4;
    const int tc = (tid % 16) * 4;

    float acc[4][4];
#pragma unroll
    for (int i = 0; i < 4; i++)
#pragma unroll
        for (int j = 0; j < 4; j++) acc[i][j] = 0.f;

    for (int k0 = 0; k0 < K; k0 += GBK) {
#pragma unroll
        for (int it = 0; it < (GBM * GBK) / 256; it++) {
            int i = tid + it * 256;
            int m = i / GBK, kk = i % GBK;
            As[kk][m] = A[(size_t)(brow + m) * lda + aoff + k0 + kk];
        }
#pragma unroll
        for (int it = 0; it < (GBK * GBN) / 256; it++) {
            int i = tid + it * 256;
            int kk = i / GBN, n = i % GBN;
            Bs[kk][n] = W[(size_t)(k0 + kk) * N + bcol + n];
        }
        __syncthreads();

#pragma unroll
        for (int kk = 0; kk < GBK; kk++) {
            float a[4], b[4];
#pragma unroll
            for (int i = 0; i < 4; i++) a[i] = As[kk][tr + i];
#pragma unroll
            for (int j = 0; j < 4; j++) b[j] = Bs[kk][tc + j];
#pragma unroll
            for (int i = 0; i < 4; i++)
#pragma unroll
                for (int j = 0; j < 4; j++) acc[i][j] = fmaf(a[i], b[j], acc[i][j]);
        }
        __syncthreads();
    }

#pragma unroll
    for (int i = 0; i < 4; i++)
#pragma unroll
        for (int j = 0; j < 4; j++)
            Y[(size_t)(brow + tr + i) * ldy + bcol + tc + j] =
                acc[i][j] + bias[bcol + tc + j];
}

// ---------------------------------------------------------------------------
// Interleaved RoPE (double-precision trig)
// ---------------------------------------------------------------------------
__global__ void rope_kernel(float* __restrict__ buf, int rows, int c)
{
    const int pairs = c >> 1;
    const int idx = blockIdx.x * blockDim.x + threadIdx.x;
    if (idx >= rows * pairs) return;
    const int row = idx / pairs;
    const int i   = idx - row * pairs;
    const int t   = row & (TT - 1);

    float theta = (float)exp(-2.0 * (double)i / (double)c * log(10000.0));
    float angle = (float)(t + 1) * theta;
    double a = (double)angle;
    float cs = (float)cos(a);
    float sn = (float)sin(a);

    float* p = buf + (size_t)row * c + 2 * i;
    float x0 = p[0], x1 = p[1];
    p[0] = x0 * cs - x1 * sn;
    p[1] = x1 * cs + x0 * sn;
}

// ---------------------------------------------------------------------------
// Attention hi/lo builders
// ---------------------------------------------------------------------------
__global__ void build_q(const float* __restrict__ q, const float* __restrict__ qr,
                        bf16* __restrict__ qhi, bf16* __restrict__ qlo)
{
    const float SCL = (float)(0.08838834764831845 * 1.4426950408889634);
    int idx = blockIdx.x * blockDim.x + threadIdx.x;
    if (idx >= BB * NHH * TT * 192) return;
    int d = idx % 192; int r = idx / 192;
    int t = r % TT; int bh = r / TT; int h = bh & 15; int b = bh >> 4;
    float v;
    if (d < 128) v = q[((size_t)(b * TT + t)) * 2048 + h * 128 + d];
    else         v = qr[((size_t)(b * TT + t)) * 1024 + h * 64 + (d - 128)];
    v *= SCL;
    bf16 hi = __float2bfloat16(v);
    qhi[idx] = hi;
    qlo[idx] = __float2bfloat16(v - __bfloat162float(hi));
}

__global__ void build_k(const float* __restrict__ kv, const float* __restrict__ kr,
                        bf16* __restrict__ khi, bf16* __restrict__ klo)
{
    int idx = blockIdx.x * blockDim.x + threadIdx.x;
    if (idx >= BB * NHH * TT * 192) return;
    int d = idx % 192; int r = idx / 192;
    int t = r % TT; int bh = r / TT; int h = bh & 15; int b = bh >> 4;
    float v;
    if (d < 128) v = kv[((size_t)(b * TT + t)) * 4096 + h * 128 + d];
    else         v = kr[((size_t)(b * TT + t)) * 64 + (d - 128)];
    bf16 hi = __float2bfloat16(v);
    khi[idx] = hi;
    klo[idx] = __float2bfloat16(v - __bfloat162float(hi));
}

__global__ void build_v(const float* __restrict__ kv,
                        bf16* __restrict__ vhi, bf16* __restrict__ vlo)
{
    int idx = blockIdx.x * blockDim.x + threadIdx.x;
    if (idx >= BB * NHH * TT * 128) return;
    int d = idx % 128; int r = idx / 128;
    int t = r % TT; int bh = r / TT; int h = bh & 15; int b = bh >> 4;
    float v = kv[((size_t)(b * TT + t)) * 4096 + 2048 + h * 128 + d];
    bf16 hi = __float2bfloat16(v);
    vhi[idx] = hi;
    vlo[idx] = __float2bfloat16(v - __bfloat162float(hi));
}

// ---------------------------------------------------------------------------
// Tensor-core flash attention, compensated bf16 (unchanged from R6/R8)
// ---------------------------------------------------------------------------
#define QSTR 200
#define KSTR 200
#define VSTR 136
#define ATTN_SMEM ((2*128*QSTR + 2*64*KSTR + 2*64*VSTR) * 2)

__global__ __launch_bounds__(256, 1)
void attn_tc(const bf16* __restrict__ qhi, const bf16* __restrict__ qlo,
             const bf16* __restrict__ khi, const bf16* __restrict__ klo,
             const bf16* __restrict__ vhi, const bf16* __restrict__ vlo,
             float* __restrict__ out)
{
    extern __shared__ bf16 smA[];
    bf16* Qh = smA;
    bf16* Ql = Qh + 128 * QSTR;
    bf16* Kh = Ql + 128 * QSTR;
    bf16* Kl = Kh + 64 * KSTR;
    bf16* Vh = Kl + 64 * KSTR;
    bf16* Vl = Vh + 64 * VSTR;

    const int tid = threadIdx.x, lane = tid & 31, wp = tid >> 5;
    const int bh = blockIdx.y;
    const int qi = gridDim.x - 1 - blockIdx.x;
    const int b = bh >> 4, h = bh & 15;
    const size_t base = (size_t)bh * TT;

    const uint32_t sQh = smem_u32(Qh), sQl = smem_u32(Ql);
    const uint32_t sKh = smem_u32(Kh), sKl = smem_u32(Kl);
    const uint32_t sVh = smem_u32(Vh), sVl = smem_u32(Vl);

    for (int i = tid; i < 128 * 24; i += 256) {
        int r = i / 24, c = (i % 24) * 8;
        size_t g = (base + (size_t)qi * 128 + r) * 192 + c;
        uint32_t d = (uint32_t)(r * QSTR + c) * 2;
        cp16(sQh + d, qhi + g);
        cp16(sQl + d, qlo + g);
    }
    cp_commit();

    float o[16][4];
#pragma unroll
    for (int i = 0; i < 16; i++)
#pragma unroll
        for (int f = 0; f < 4; f++) o[i][f] = 0.f;

    float m1 = -1e30f, m2 = -1e30f, l1 = 0.f, l2 = 0.f;
    const int l16 = lane & 15, lhi = (lane >> 4) * 8;
    const int qrow1 = qi * 128 + wp * 16 + (lane >> 2);
    const int qrow2 = qrow1 + 8;
    const int brofs = (lane & 7) + ((lane >> 4) & 1) * 8;
    const int bcofs = ((lane >> 3) & 1) * 8;

    const int nkt = 2 * qi + 2;
    for (int kt = 0; kt < nkt; kt++) {
        __syncthreads();
        for (int i = tid; i < 64 * 24; i += 256) {
            int r = i / 24, c = (i % 24) * 8;
            size_t g = (base + (size_t)kt * 64 + r) * 192 + c;
            uint32_t d = (uint32_t)(r * KSTR + c) * 2;
            cp16(sKh + d, khi + g);
            cp16(sKl + d, klo + g);
        }
        for (int i = tid; i < 64 * 16; i += 256) {
            int r = i / 16, c = (i % 16) * 8;
            size_t g = (base + (size_t)kt * 64 + r) * 128 + c;
            uint32_t d = (uint32_t)(r * VSTR + c) * 2;
            cp16(sVh + d, vhi + g);
            cp16(sVl + d, vlo + g);
        }
        cp_commit();
        cp_wait<0>();
        __syncthreads();

        float s[8][4];
#pragma unroll
        for (int j = 0; j < 8; j++)
#pragma unroll
            for (int f = 0; f < 4; f++) s[j][f] = 0.f;

#pragma unroll
        for (int kk = 0; kk < 12; kk++) {
            uint32_t ah[4], al[4];
            uint32_t aaddr = (uint32_t)((wp * 16 + l16) * QSTR + kk * 16 + lhi) * 2;
            ldm_x4(ah, sQh + aaddr);
            ldm_x4(al, sQl + aaddr);
#pragma unroll
            for (int j2 = 0; j2 < 4; j2++) {
                uint32_t baddr = (uint32_t)((j2 * 16 + brofs) * KSTR + kk * 16 + bcofs) * 2;
                uint32_t tbv[4], tl[4];
                ldm_x4(tbv, sKh + baddr);
                ldm_x4(tl, sKl + baddr);
                mma_bf16(s[2 * j2],     ah, tbv);
                mma_bf16(s[2 * j2],     ah, tl);
                mma_bf16(s[2 * j2],     al, tbv);
                mma_bf16(s[2 * j2 + 1], ah, tbv + 2);
                mma_bf16(s[2 * j2 + 1], ah, tl + 2);
                mma_bf16(s[2 * j2 + 1], al, tbv + 2);
            }
        }

#pragma unroll
        for (int j = 0; j < 8; j++) {
            int k0 = kt * 64 + j * 8 + 2 * (lane & 3);
            if (k0     > qrow1) s[j][0] = -1e30f;
            if (k0 + 1 > qrow1) s[j][1] = -1e30f;
            if (k0     > qrow2) s[j][2] = -1e30f;
            if (k0 + 1 > qrow2) s[j][3] = -1e30f;
        }
        float mr1 = -1e30f, mr2 = -1e30f;
#pragma unroll
        for (int j = 0; j < 8; j++) {
            mr1 = fmaxf(mr1, fmaxf(s[j][0], s[j][1]));
            mr2 = fmaxf(mr2, fmaxf(s[j][2], s[j][3]));
        }
        mr1 = fmaxf(mr1, __shfl_xor_sync(0xffffffffu, mr1, 1));
        mr1 = fmaxf(mr1, __shfl_xor_sync(0xffffffffu, mr1, 2));
        mr2 = fmaxf(mr2, __shfl_xor_sync(0xffffffffu, mr2, 1));
        mr2 = fmaxf(mr2, __shfl_xor_sync(0xffffffffu, mr2, 2));
        float mn1 = fmaxf(m1, mr1), mn2 = fmaxf(m2, mr2);
        float a1 = ex2f(m1 - mn1), a2 = ex2f(m2 - mn2);
        m1 = mn1; m2 = mn2;

        uint32_t phx[8][2], plx[8][2];
        float rs1 = 0.f, rs2 = 0.f;
#pragma unroll
        for (int j = 0; j < 8; j++) {
            float p0 = ex2f(s[j][0] - mn1), p1 = ex2f(s[j][1] - mn1);
            float p2 = ex2f(s[j][2] - mn2), p3 = ex2f(s[j][3] - mn2);
            rs1 += p0 + p1; rs2 += p2 + p3;
            phx[j][0] = packbf2(p0, p1);
            phx[j][1] = packbf2(p2, p3);
            float q0 = p0 - __bfloat162float(__float2bfloat16(p0));
            float q1 = p1 - __bfloat162float(__float2bfloat16(p1));
            float q2 = p2 - __bfloat162float(__float2bfloat16(p2));
            float q3 = p3 - __bfloat162float(__float2bfloat16(p3));
            plx[j][0] = packbf2(q0, q1);
            plx[j][1] = packbf2(q2, q3);
        }
        rs1 += __shfl_xor_sync(0xffffffffu, rs1, 1);
        rs1 += __shfl_xor_sync(0xffffffffu, rs1, 2);
        rs2 += __shfl_xor_sync(0xffffffffu, rs2, 1);
        rs2 += __shfl_xor_sync(0xffffffffu, rs2, 2);
        l1 = l1 * a1 + rs1;
        l2 = l2 * a2 + rs2;
#pragma unroll
        for (int t16 = 0; t16 < 16; t16++) {
            o[t16][0] *= a1; o[t16][1] *= a1;
            o[t16][2] *= a2; o[t16][3] *= a2;
        }

#pragma unroll
        for (int kt2 = 0; kt2 < 4; kt2++) {
            uint32_t pa_h[4] = {phx[2 * kt2][0], phx[2 * kt2][1],
                                phx[2 * kt2 + 1][0], phx[2 * kt2 + 1][1]};
            uint32_t pa_l[4] = {plx[2 * kt2][0], plx[2 * kt2][1],
                                plx[2 * kt2 + 1][0], plx[2 * kt2 + 1][1]};
            uint32_t vrow = (uint32_t)((kt2 * 16 + l16) * VSTR) * 2;
#pragma unroll
            for (int j2 = 0; j2 < 8; j2++) {
                uint32_t vaddr = vrow + (uint32_t)(j2 * 16 + lhi) * 2;
                uint32_t tv[4], tw[4];
                ldm_x4t(tv, sVh + vaddr);
                ldm_x4t(tw, sVl + vaddr);
                mma_bf16(o[2 * j2],     pa_h, tv);
                mma_bf16(o[2 * j2],     pa_h, tw);
                mma_bf16(o[2 * j2],     pa_l, tv);
                mma_bf16(o[2 * j2 + 1], pa_h, tv + 2);
                mma_bf16(o[2 * j2 + 1], pa_h, tw + 2);
                mma_bf16(o[2 * j2 + 1], pa_l, tv + 2);
            }
        }
    }

    float inv1 = 1.f / l1, inv2 = 1.f / l2;
    size_t row1 = (size_t)(b * TT + qrow1) * 2048 + h * 128;
    size_t row2 = (size_t)(b * TT + qrow2) * 2048 + h * 128;
#pragma unroll
    for (int t16 = 0; t16 < 16; t16++) {
        int col = t16 * 8 + 2 * (lane & 3);
        float2 v1 = {o[t16][0] * inv1, o[t16][1] * inv1};
        float2 v2 = {o[t16][2] * inv2, o[t16][3] * inv2};
        *(float2*)&out[row1 + col] = v1;
        *(float2*)&out[row2 + col] = v2;
    }
}

// ---------------------------------------------------------------------------
// Host launcher
// ---------------------------------------------------------------------------
extern "C" void kernel_launch(void* const* d_in, const int* in_sizes, int n_in,
                              void* d_out, int out_size)
{
    (void)in_sizes; (void)n_in; (void)out_size;

    const float* x     = (const float*)d_in[0];
    const float* W_dkv = (const float*)d_in[1];
    const float* b_dkv = (const float*)d_in[2];
    const float* W_kr  = (const float*)d_in[3];
    const float* b_kr  = (const float*)d_in[4];
    const float* W_qr  = (const float*)d_in[5];
    const float* b_qr  = (const float*)d_in[6];
    const float* W_uv  = (const float*)d_in[7];
    const float* b_uv  = (const float*)d_in[8];
    const float* W_uq  = (const float*)d_in[9];
    const float* b_uq  = (const float*)d_in[10];
    const float* W_o   = (const float*)d_in[11];
    const float* b_o   = (const float*)d_in[12];
    float* out = (float*)d_out;

    float *h, *kr, *qr, *kvb, *qb, *attn;
    bf16 *xhi, *xlo, *hhi, *hlo, *athi, *atlo;
    bf16 *wdkvh, *wdkvl, *wqrh, *wqrl, *wuvh, *wuvl, *wuqh, *wuql, *woh, *wol;
    bf16 *qhi, *qlo, *khi, *klo, *vhi, *vlo;
    cudaGetSymbolAddress((void**)&h,    g_h);
    cudaGetSymbolAddress((void**)&kr,   g_kr);
    cudaGetSymbolAddress((void**)&qr,   g_qr);
    cudaGetSymbolAddress((void**)&kvb,  g_kv);
    cudaGetSymbolAddress((void**)&qb,   g_q);
    cudaGetSymbolAddress((void**)&attn, g_attn);
    cudaGetSymbolAddress((void**)&xhi,  g_xhi);
    cudaGetSymbolAddress((void**)&xlo,  g_xlo);
    cudaGetSymbolAddress((void**)&hhi,  g_hhi);
    cudaGetSymbolAddress((void**)&hlo,  g_hlo);
    cudaGetSymbolAddress((void**)&athi, g_athi);
    cudaGetSymbolAddress((void**)&atlo, g_atlo);
    cudaGetSymbolAddress((void**)&wdkvh, g_wdkvh);
    cudaGetSymbolAddress((void**)&wdkvl, g_wdkvl);
    cudaGetSymbolAddress((void**)&wqrh, g_wqrh);
    cudaGetSymbolAddress((void**)&wqrl, g_wqrl);
    cudaGetSymbolAddress((void**)&wuvh, g_wuvh);
    cudaGetSymbolAddress((void**)&wuvl, g_wuvl);
    cudaGetSymbolAddress((void**)&wuqh, g_wuqh);
    cudaGetSymbolAddress((void**)&wuql, g_wuql);
    cudaGetSymbolAddress((void**)&woh,  g_woh);
    cudaGetSymbolAddress((void**)&wol,  g_wol);
    cudaGetSymbolAddress((void**)&qhi, g_qhi);
    cudaGetSymbolAddress((void**)&qlo, g_qlo);
    cudaGetSymbolAddress((void**)&khi, g_khi);
    cudaGetSymbolAddress((void**)&klo, g_klo);
    cudaGetSymbolAddress((void**)&vhi, g_vhi);
    cudaGetSymbolAddress((void**)&vlo, g_vlo);

    const int M = MROWS;  // 4096

    cudaFuncSetAttribute(gemm_mma, cudaFuncAttributeMaxDynamicSharedMemorySize, GSMEM);
    cudaFuncSetAttribute(attn_tc, cudaFuncAttributeMaxDynamicSharedMemorySize, ATTN_SMEM);

    // 1) x -> hi/lo
    split_act<<<(M * 512 + 255) / 256, 256>>>(x, 2048, 0, 2048, xhi, xlo);
    // 2) W_dkv -> [1024][2048]
    wsplit_t<<<dim3(1024 / 32, 2048 / 32), 256>>>(W_dkv, 2048, 1024, wdkvh, wdkvl);
    // 3) W_o -> [2048][2048]
    wsplit_t<<<dim3(2048 / 32, 2048 / 32), 256>>>(W_o, 2048, 2048, woh, wol);
    // 4) h = x @ W_dkv + b_dkv    [4096,1024]   <-- profiled launch
    gemm_mma<<<dim3(8, 32), 128, GSMEM>>>(xhi, xlo, 2048, 0, wdkvh, wdkvl, 2048,
                                          b_dkv, h, 1024, 2048);
    // 5) kr
    sgemm_bias<<<dim3(1, 64), 256>>>(h, 1024, 0, W_kr, b_kr, kr, 64, M, 64, 1024);
    // 6) h -> hi/lo
    split_act<<<(M * 256 + 255) / 256, 256>>>(h, 1024, 0, 1024, hhi, hlo);
    // 7) W_qr
    wsplit_t<<<dim3(1024 / 32, 1024 / 32), 256>>>(W_qr, 1024, 1024, wqrh, wqrl);
    // 8) qr = h @ W_qr
    gemm_mma<<<dim3(8, 32), 128, GSMEM>>>(hhi, hlo, 1024, 0, wqrh, wqrl, 1024,
                                          b_qr, qr, 1024, 1024);
    // 9,10) RoPE
    rope_kernel<<<(M * 32 + 255) / 256, 256>>>(kr, M, 64);
    rope_kernel<<<(M * 512 + 255) / 256, 256>>>(qr, M, 1024);
    // 11,12) W_uv, W_uq
    wsplit_t<<<dim3(4096 / 32, 512 / 32), 256>>>(W_uv, 512, 4096, wuvh, wuvl);
    wsplit_t<<<dim3(2048 / 32, 512 / 32), 256>>>(W_uq, 512, 2048, wuqh, wuql);
    // 13) kv = cKV @ W_uv   [4096,4096]
    gemm_mma<<<dim3(32, 32), 128, GSMEM>>>(hhi, hlo, 1024, 0, wuvh, wuvl, 512,
                                           b_uv, kvb, 4096, 512);
    // 14) q = cq @ W_uq     [4096,2048]
    gemm_mma<<<dim3(16, 32), 128, GSMEM>>>(hhi, hlo, 1024, 512, wuqh, wuql, 512,
                                           b_uq, qb, 2048, 512);
    // 15-17) attention hi/lo buffers
    build_q<<<(BB * NHH * TT * 192 + 255) / 256, 256>>>(qb, qr, qhi, qlo);
    build_k<<<(BB * NHH * TT * 192 + 255) / 256, 256>>>(kvb, kr, khi, klo);
    build_v<<<(BB * NHH * TT * 128 + 255) / 256, 256>>>(kvb, vhi, vlo);
    // 18) attention
    attn_tc<<<dim3(TT / 128, BB * NHH), 256, ATTN_SMEM>>>(qhi, qlo, khi, klo, vhi, vlo, attn);
    // 19) attn -> hi/lo
    split_act<<<(M * 512 + 255) / 256, 256>>>(attn, 2048, 0, 2048, athi, atlo);
    // 20) out = attn @ W_o + b_o   [4096,2048]
    gemm_mma<<<dim3(16, 32), 128, GSMEM>>>(athi, atlo, 2048, 0, woh, wol, 2048,
                                           b_o, out, 2048, 2048);
}

// round 10
// speedup vs baseline: 2.2734x; 1.0621x over previous
#include <cuda_runtime.h>
#include <cuda_bf16.h>
#include <math.h>
#include <stdint.h>

// Problem constants
#define BB   2
#define TT   2048
#define CC   2048
#define NHH  16
#define DKK  128
#define LATT 512
#define DHRR 64
#define MROWS (BB * TT)   // 4096

typedef __nv_bfloat16 bf16;

// ---------------------------------------------------------------------------
// Scratch (static device globals -- no allocation allowed)
// ---------------------------------------------------------------------------
__device__ float g_h   [(size_t)MROWS * 1024];
__device__ float g_kr  [(size_t)MROWS * 64];
__device__ float g_qr  [(size_t)MROWS * 1024];

// hi/lo split activations (row-major [M][K])
__device__ bf16 g_xhi [(size_t)MROWS * 2048];
__device__ bf16 g_xlo [(size_t)MROWS * 2048];
__device__ bf16 g_hhi [(size_t)MROWS * 1024];
__device__ bf16 g_hlo [(size_t)MROWS * 1024];
__device__ bf16 g_athi[(size_t)MROWS * 2048];
__device__ bf16 g_atlo[(size_t)MROWS * 2048];

// hi/lo split transposed weights ([N][K] K-major)
__device__ bf16 g_wdkvh[(size_t)1024 * 2048];
__device__ bf16 g_wdkvl[(size_t)1024 * 2048];
__device__ bf16 g_wqrh [(size_t)1024 * 1024];
__device__ bf16 g_wqrl [(size_t)1024 * 1024];
__device__ bf16 g_wuvh [(size_t)4096 * 512];
__device__ bf16 g_wuvl [(size_t)4096 * 512];
__device__ bf16 g_wuqh [(size_t)2048 * 512];
__device__ bf16 g_wuql [(size_t)2048 * 512];
__device__ bf16 g_woh  [(size_t)2048 * 2048];
__device__ bf16 g_wol  [(size_t)2048 * 2048];

// attention hi/lo buffers, per-head contiguous [(b*NH+h)*T + t][dim]
__device__ bf16 g_qhi[(size_t)BB * NHH * TT * 192];
__device__ bf16 g_qlo[(size_t)BB * NHH * TT * 192];
__device__ bf16 g_khi[(size_t)BB * NHH * TT * 192];
__device__ bf16 g_klo[(size_t)BB * NHH * TT * 192];
__device__ bf16 g_vhi[(size_t)BB * NHH * TT * 128];
__device__ bf16 g_vlo[(size_t)BB * NHH * TT * 128];

#define SCLQ 0.12754984837627695f   // 1/sqrt(128) * log2(e)

// ---------------------------------------------------------------------------
// PTX helpers
// ---------------------------------------------------------------------------
__device__ __forceinline__ uint32_t smem_u32(const void* p)
{ return (uint32_t)__cvta_generic_to_shared(p); }

__device__ __forceinline__ void cp16(uint32_t dst, const void* src)
{ asm volatile("cp.async.cg.shared.global [%0], [%1], 16;\n" :: "r"(dst), "l"(src)); }

__device__ __forceinline__ void cp_commit()
{ asm volatile("cp.async.commit_group;\n"); }

template <int N>
__device__ __forceinline__ void cp_wait()
{ asm volatile("cp.async.wait_group %0;\n" :: "n"(N)); }

__device__ __forceinline__ void ldm_x4(uint32_t* r, uint32_t addr)
{
    asm volatile("ldmatrix.sync.aligned.m8n8.x4.shared.b16 {%0,%1,%2,%3}, [%4];\n"
        : "=r"(r[0]), "=r"(r[1]), "=r"(r[2]), "=r"(r[3]) : "r"(addr));
}
__device__ __forceinline__ void ldm_x4t(uint32_t* r, uint32_t addr)
{
    asm volatile("ldmatrix.sync.aligned.m8n8.x4.trans.shared.b16 {%0,%1,%2,%3}, [%4];\n"
        : "=r"(r[0]), "=r"(r[1]), "=r"(r[2]), "=r"(r[3]) : "r"(addr));
}
__device__ __forceinline__ void mma_bf16(float* d, const uint32_t* a, const uint32_t* b)
{
    asm volatile(
        "mma.sync.aligned.m16n8k16.row.col.f32.bf16.bf16.f32 "
        "{%0,%1,%2,%3}, {%4,%5,%6,%7}, {%8,%9}, {%0,%1,%2,%3};\n"
        : "+f"(d[0]), "+f"(d[1]), "+f"(d[2]), "+f"(d[3])
        : "r"(a[0]), "r"(a[1]), "r"(a[2]), "r"(a[3]), "r"(b[0]), "r"(b[1]));
}
__device__ __forceinline__ float ex2f(float x)
{ float y; asm("ex2.approx.f32 %0, %1;" : "=f"(y) : "f"(x)); return y; }

__device__ __forceinline__ uint32_t packbf2(float lo, float hi)
{ uint32_t d; asm("cvt.rn.bf16x2.f32 %0, %1, %2;" : "=r"(d) : "f"(hi), "f"(lo)); return d; }

__device__ __forceinline__ float bfround(float v)
{ return __bfloat162float(__float2bfloat16(v)); }

// ---------------------------------------------------------------------------
// Conversion: fp32 activation -> hi/lo bf16 (used only for x now)
// ---------------------------------------------------------------------------
__global__ void split_act(const float* __restrict__ A, int lda, int aoff, int Kw,
                          bf16* __restrict__ hi, bf16* __restrict__ lo)
{
    int idx = blockIdx.x * blockDim.x + threadIdx.x;
    int total = MROWS * (Kw / 4);
    if (idx >= total) return;
    int m = idx / (Kw / 4), k4 = (idx - m * (Kw / 4)) * 4;
    float4 v = *(const float4*)&A[(size_t)m * lda + aoff + k4];
    float h0 = bfround(v.x), h1 = bfround(v.y);
    float h2 = bfround(v.z), h3 = bfround(v.w);
    uint2 ph, pl;
    ph.x = packbf2(h0, h1); ph.y = packbf2(h2, h3);
    pl.x = packbf2(v.x - h0, v.y - h1); pl.y = packbf2(v.z - h2, v.w - h3);
    *(uint2*)&hi[(size_t)m * Kw + k4] = ph;
    *(uint2*)&lo[(size_t)m * Kw + k4] = pl;
}

// Weight: W[K][N] fp32 -> hiT/loT [N][K] bf16 (tiled transpose)
__global__ void wsplit_t(const float* __restrict__ W, int K, int N,
                         bf16* __restrict__ hiT, bf16* __restrict__ loT)
{
    __shared__ float t[32][33];
    int tx = threadIdx.x & 31, ty = threadIdx.x >> 5;
    int k0 = blockIdx.y * 32, n0 = blockIdx.x * 32;
#pragma unroll
    for (int r = 0; r < 4; r++)
        t[ty + 8 * r][tx] = W[(size_t)(k0 + ty + 8 * r) * N + n0 + tx];
    __syncthreads();
#pragma unroll
    for (int r = 0; r < 4; r++) {
        float v = t[tx][ty + 8 * r];
        bf16 h = __float2bfloat16(v);
        size_t o = (size_t)(n0 + ty + 8 * r) * K + k0 + tx;
        hiT[o] = h;
        loT[o] = __float2bfloat16(v - __bfloat162float(h));
    }
}

// ---------------------------------------------------------------------------
// HMMA GEMM, compensated hi/lo, fused epilogues.
// mode 0: fp32 Y only
// mode 1: fp32 Y + row-major hi/lo (stride ldy)
// mode 2: kv layout -> khi/klo (cols<2048, d<128 of K) + vhi/vlo (cols>=2048)
// mode 3: q layout  -> qhi/qlo (scaled by SCLQ), d<128 per head
// Block 128x128x32, 128 threads (4 warps 2x2), warp tile 64x64, 2 CTAs/SM.
// ---------------------------------------------------------------------------
#define TST 40
#define A_ELE (128 * TST)
#define B_ELE (128 * TST)
#define STG_ELE (2 * A_ELE + 2 * B_ELE)
#define GSMEM (2 * STG_ELE * 2)

__global__ __launch_bounds__(128, 2)
void gemm_mma(const bf16* __restrict__ Ahi, const bf16* __restrict__ Alo,
              int lda, int aoff,
              const bf16* __restrict__ Bhi, const bf16* __restrict__ Blo,
              int ldb,
              const float* __restrict__ bias,
              float* __restrict__ Y, int ldy, int K,
              bf16* __restrict__ ho, bf16* __restrict__ lo_,
              bf16* __restrict__ ho2, bf16* __restrict__ lo2, int mode)
{
    extern __shared__ bf16 dsm[];
    const uint32_t sb0 = smem_u32(dsm);

    const int tid = threadIdx.x, lane = tid & 31, wid = tid >> 5;
    const int brow = blockIdx.y * 128, bcol = blockIdx.x * 128;
    const int wm = (wid >> 1) * 64, wn = (wid & 1) * 64;

    auto issue = [&](int st, int kt) {
        uint32_t s = sb0 + (uint32_t)(st * STG_ELE) * 2;
        int ke = kt * 32;
#pragma unroll
        for (int i = 0; i < 4; i++) {
            int c = tid + i * 128;
            int r = c >> 2, sg = (c & 3) * 8;
            uint32_t d = (uint32_t)(r * TST + sg) * 2;
            cp16(s + d, Ahi + (size_t)(brow + r) * lda + aoff + ke + sg);
            cp16(s + (uint32_t)A_ELE * 2 + d,
                 Alo + (size_t)(brow + r) * lda + aoff + ke + sg);
            cp16(s + (uint32_t)(2 * A_ELE) * 2 + d,
                 Bhi + (size_t)(bcol + r) * ldb + ke + sg);
            cp16(s + (uint32_t)(2 * A_ELE + B_ELE) * 2 + d,
                 Blo + (size_t)(bcol + r) * ldb + ke + sg);
        }
        cp_commit();
    };

    float acc[4][8][4];
#pragma unroll
    for (int i = 0; i < 4; i++)
#pragma unroll
        for (int j = 0; j < 8; j++)
#pragma unroll
            for (int f = 0; f < 4; f++) acc[i][j][f] = 0.f;

    const int ntiles = K / 32;
    issue(0, 0);
    issue(1, 1);

    const int l16 = lane & 15, lhi = (lane >> 4) * 8;
    const int brofs = (lane & 7) + ((lane >> 4) & 1) * 8;
    const int bcofs = ((lane >> 3) & 1) * 8;

    for (int kt = 0; kt < ntiles; kt++) {
        if (kt + 1 < ntiles) { cp_wait<1>(); } else { cp_wait<0>(); }
        __syncthreads();
        int cur = kt & 1;
        uint32_t s = sb0 + (uint32_t)(cur * STG_ELE) * 2;
        uint32_t sAh = s, sAl = s + (uint32_t)A_ELE * 2;
        uint32_t sBh = s + (uint32_t)(2 * A_ELE) * 2;
        uint32_t sBl = sBh + (uint32_t)B_ELE * 2;

#pragma unroll
        for (int kk = 0; kk < 32; kk += 16) {
            // preload ALL B fragments for this kk16
            uint32_t bh[4][4], bl[4][4];
#pragma unroll
            for (int j2 = 0; j2 < 4; j2++) {
                uint32_t baddr =
                    (uint32_t)((wn + j2 * 16 + brofs) * TST + kk + bcofs) * 2;
                ldm_x4(bh[j2], sBh + baddr);
                ldm_x4(bl[j2], sBl + baddr);
            }
            // per-i: load A frags, run 24-MMA block
#pragma unroll
            for (int i = 0; i < 4; i++) {
                uint32_t ah[4], al[4];
                uint32_t aaddr = (uint32_t)((wm + i * 16 + l16) * TST + kk + lhi) * 2;
                ldm_x4(ah, sAh + aaddr);
                ldm_x4(al, sAl + aaddr);
#pragma unroll
                for (int j2 = 0; j2 < 4; j2++) {
                    mma_bf16(acc[i][2 * j2],     ah, bh[j2]);
                    mma_bf16(acc[i][2 * j2],     ah, bl[j2]);
                    mma_bf16(acc[i][2 * j2],     al, bh[j2]);
                    mma_bf16(acc[i][2 * j2 + 1], ah, bh[j2] + 2);
                    mma_bf16(acc[i][2 * j2 + 1], ah, bl[j2] + 2);
                    mma_bf16(acc[i][2 * j2 + 1], al, bh[j2] + 2);
                }
            }
        }
        __syncthreads();
        if (kt + 2 < ntiles) issue(cur, kt + 2);
    }

    // ---- fused epilogue ----
#pragma unroll
    for (int i = 0; i < 4; i++) {
#pragma unroll
        for (int j = 0; j < 8; j++) {
            int r0 = brow + wm + i * 16 + (lane >> 2);
            int c0 = bcol + wn + j * 8 + (lane & 3) * 2;
            float b0 = bias[c0], b1 = bias[c0 + 1];
            float v00 = acc[i][j][0] + b0, v01 = acc[i][j][1] + b1;
            float v10 = acc[i][j][2] + b0, v11 = acc[i][j][3] + b1;

            if (mode <= 1) {
                *(float2*)&Y[(size_t)r0 * ldy + c0]       = make_float2(v00, v01);
                *(float2*)&Y[(size_t)(r0 + 8) * ldy + c0] = make_float2(v10, v11);
            }
            if (mode == 1) {
                float f00 = bfround(v00), f01 = bfround(v01);
                float f10 = bfround(v10), f11 = bfround(v11);
                *(uint32_t*)&ho [(size_t)r0 * ldy + c0]       = packbf2(f00, f01);
                *(uint32_t*)&lo_[(size_t)r0 * ldy + c0]       = packbf2(v00 - f00, v01 - f01);
                *(uint32_t*)&ho [(size_t)(r0 + 8) * ldy + c0] = packbf2(f10, f11);
                *(uint32_t*)&lo_[(size_t)(r0 + 8) * ldy + c0] = packbf2(v10 - f10, v11 - f11);
            } else if (mode == 2) {
#pragma unroll
                for (int rr = 0; rr < 2; rr++) {
                    int r = r0 + rr * 8;
                    float va = rr ? v10 : v00, vb = rr ? v11 : v01;
                    int b = r >> 11, t = r & 2047;
                    float fa = bfround(va), fb = bfround(vb);
                    if (c0 < 2048) {
                        int hh = c0 >> 7, d = c0 & 127;
                        size_t base = ((size_t)(b * NHH + hh) * TT + t) * 192 + d;
                        *(uint32_t*)&ho [base] = packbf2(fa, fb);
                        *(uint32_t*)&lo_[base] = packbf2(va - fa, vb - fb);
                    } else {
                        int c2 = c0 - 2048;
                        int hh = c2 >> 7, d = c2 & 127;
                        size_t base = ((size_t)(b * NHH + hh) * TT + t) * 128 + d;
                        *(uint32_t*)&ho2[base] = packbf2(fa, fb);
                        *(uint32_t*)&lo2[base] = packbf2(va - fa, vb - fb);
                    }
                }
            } else if (mode == 3) {
#pragma unroll
                for (int rr = 0; rr < 2; rr++) {
                    int r = r0 + rr * 8;
                    float va = (rr ? v10 : v00) * SCLQ, vb = (rr ? v11 : v01) * SCLQ;
                    int b = r >> 11, t = r & 2047;
                    int hh = c0 >> 7, d = c0 & 127;
                    size_t base = ((size_t)(b * NHH + hh) * TT + t) * 192 + d;
                    float fa = bfround(va), fb = bfround(vb);
                    *(uint32_t*)&ho [base] = packbf2(fa, fb);
                    *(uint32_t*)&lo_[base] = packbf2(va - fa, vb - fb);
                }
            }
        }
    }
}

// ---------------------------------------------------------------------------
// Small SGEMM (N=64 W_kr projection only)
// ---------------------------------------------------------------------------
#define GBM 64
#define GBN 64
#define GBK 16

__global__ __launch_bounds__(256)
void sgemm_bias(const float* __restrict__ A, int lda, int aoff,
                const float* __restrict__ W,
                const float* __restrict__ bias,
                float* __restrict__ Y, int ldy,
                int M, int N, int K)
{
    __shared__ float As[GBK][GBM];
    __shared__ float Bs[GBK][GBN];

    const int tid = threadIdx.x;
    const int brow = blockIdx.y * GBM;
    const int bcol = blockIdx.x * GBN;
    const int tr = (tid / 16) * 4;
    const int tc = (tid % 16) * 4;

    float acc[4][4];
#pragma unroll
    for (int i = 0; i < 4; i++)
#pragma unroll
        for (int j = 0; j < 4; j++) acc[i][j] = 0.f;

    for (int k0 = 0; k0 < K; k0 += GBK) {
#pragma unroll
        for (int it = 0; it < (GBM * GBK) / 256; it++) {
            int i = tid + it * 256;
            int m = i / GBK, kk = i % GBK;
            As[kk][m] = A[(size_t)(brow + m) * lda + aoff + k0 + kk];
        }
#pragma unroll
        for (int it = 0; it < (GBK * GBN) / 256; it++) {
            int i = tid + it * 256;
            int kk = i / GBN, n = i % GBN;
            Bs[kk][n] = W[(size_t)(k0 + kk) * N + bcol + n];
        }
        __syncthreads();

#pragma unroll
        for (int kk = 0; kk < GBK; kk++) {
            float a[4], b[4];
#pragma unroll
            for (int i = 0; i < 4; i++) a[i] = As[kk][tr + i];
#pragma unroll
            for (int j = 0; j < 4; j++) b[j] = Bs[kk][tc + j];
#pragma unroll
            for (int i = 0; i < 4; i++)
#pragma unroll
                for (int j = 0; j < 4; j++) acc[i][j] = fmaf(a[i], b[j], acc[i][j]);
        }
        __syncthreads();
    }

#pragma unroll
    for (int i = 0; i < 4; i++)
#pragma unroll
        for (int j = 0; j < 4; j++)
            Y[(size_t)(brow + tr + i) * ldy + bcol + tc + j] =
                acc[i][j] + bias[bcol + tc + j];
}

// ---------------------------------------------------------------------------
// Interleaved RoPE (double-precision trig)
// ---------------------------------------------------------------------------
__global__ void rope_kernel(float* __restrict__ buf, int rows, int c)
{
    const int pairs = c >> 1;
    const int idx = blockIdx.x * blockDim.x + threadIdx.x;
    if (idx >= rows * pairs) return;
    const int row = idx / pairs;
    const int i   = idx - row * pairs;
    const int t   = row & (TT - 1);

    float theta = (float)exp(-2.0 * (double)i / (double)c * log(10000.0));
    float angle = (float)(t + 1) * theta;
    double a = (double)angle;
    float cs = (float)cos(a);
    float sn = (float)sin(a);

    float* p = buf + (size_t)row * c + 2 * i;
    float x0 = p[0], x1 = p[1];
    p[0] = x0 * cs - x1 * sn;
    p[1] = x1 * cs + x0 * sn;
}

// ---------------------------------------------------------------------------
// Fill RoPE slices of attention buffers (d in [128,192))
// ---------------------------------------------------------------------------
__global__ void build_kr(const float* __restrict__ kr,
                         bf16* __restrict__ khi, bf16* __restrict__ klo)
{
    int idx = blockIdx.x * blockDim.x + threadIdx.x;
    if (idx >= BB * NHH * TT * 64) return;
    int d = idx & 63; int r = idx >> 6;
    int t = r % TT; int bh = r / TT; int b = bh >> 4;
    float v = kr[((size_t)(b * TT + t)) * 64 + d];
    size_t base = ((size_t)bh * TT + t) * 192 + 128 + d;
    float f = bfround(v);
    khi[base] = __float2bfloat16(f);
    klo[base] = __float2bfloat16(v - f);
}

__global__ void build_qr(const float* __restrict__ qr,
                         bf16* __restrict__ qhi, bf16* __restrict__ qlo)
{
    int idx = blockIdx.x * blockDim.x + threadIdx.x;
    if (idx >= BB * NHH * TT * 64) return;
    int d = idx & 63; int r = idx >> 6;
    int t = r % TT; int bh = r / TT; int h = bh & 15; int b = bh >> 4;
    float v = qr[((size_t)(b * TT + t)) * 1024 + h * 64 + d] * SCLQ;
    size_t base = ((size_t)bh * TT + t) * 192 + 128 + d;
    float f = bfround(v);
    qhi[base] = __float2bfloat16(f);
    qlo[base] = __float2bfloat16(v - f);
}

// ---------------------------------------------------------------------------
// Tensor-core flash attention, compensated bf16; epilogue emits hi/lo
// ---------------------------------------------------------------------------
#define QSTR 200
#define KSTR 200
#define VSTR 136
#define ATTN_SMEM ((2*128*QSTR + 2*64*KSTR + 2*64*VSTR) * 2)

__global__ __launch_bounds__(256, 1)
void attn_tc(const bf16* __restrict__ qhi, const bf16* __restrict__ qlo,
             const bf16* __restrict__ khi, const bf16* __restrict__ klo,
             const bf16* __restrict__ vhi, const bf16* __restrict__ vlo,
             bf16* __restrict__ ohi, bf16* __restrict__ olo)
{
    extern __shared__ bf16 smA[];
    bf16* Qh = smA;
    bf16* Ql = Qh + 128 * QSTR;
    bf16* Kh = Ql + 128 * QSTR;
    bf16* Kl = Kh + 64 * KSTR;
    bf16* Vh = Kl + 64 * KSTR;
    bf16* Vl = Vh + 64 * VSTR;

    const int tid = threadIdx.x, lane = tid & 31, wp = tid >> 5;
    const int bh = blockIdx.y;
    const int qi = gridDim.x - 1 - blockIdx.x;
    const int b = bh >> 4, h = bh & 15;
    const size_t base = (size_t)bh * TT;

    const uint32_t sQh = smem_u32(Qh), sQl = smem_u32(Ql);
    const uint32_t sKh = smem_u32(Kh), sKl = smem_u32(Kl);
    const uint32_t sVh = smem_u32(Vh), sVl = smem_u32(Vl);

    for (int i = tid; i < 128 * 24; i += 256) {
        int r = i / 24, c = (i % 24) * 8;
        size_t g = (base + (size_t)qi * 128 + r) * 192 + c;
        uint32_t d = (uint32_t)(r * QSTR + c) * 2;
        cp16(sQh + d, qhi + g);
        cp16(sQl + d, qlo + g);
    }
    cp_commit();

    float o[16][4];
#pragma unroll
    for (int i = 0; i < 16; i++)
#pragma unroll
        for (int f = 0; f < 4; f++) o[i][f] = 0.f;

    float m1 = -1e30f, m2 = -1e30f, l1 = 0.f, l2 = 0.f;
    const int l16 = lane & 15, lhi = (lane >> 4) * 8;
    const int qrow1 = qi * 128 + wp * 16 + (lane >> 2);
    const int qrow2 = qrow1 + 8;
    const int brofs = (lane & 7) + ((lane >> 4) & 1) * 8;
    const int bcofs = ((lane >> 3) & 1) * 8;

    const int nkt = 2 * qi + 2;
    for (int kt = 0; kt < nkt; kt++) {
        __syncthreads();
        for (int i = tid; i < 64 * 24; i += 256) {
            int r = i / 24, c = (i % 24) * 8;
            size_t g = (base + (size_t)kt * 64 + r) * 192 + c;
            uint32_t d = (uint32_t)(r * KSTR + c) * 2;
            cp16(sKh + d, khi + g);
            cp16(sKl + d, klo + g);
        }
        for (int i = tid; i < 64 * 16; i += 256) {
            int r = i / 16, c = (i % 16) * 8;
            size_t g = (base + (size_t)kt * 64 + r) * 128 + c;
            uint32_t d = (uint32_t)(r * VSTR + c) * 2;
            cp16(sVh + d, vhi + g);
            cp16(sVl + d, vlo + g);
        }
        cp_commit();
        cp_wait<0>();
        __syncthreads();

        float s[8][4];
#pragma unroll
        for (int j = 0; j < 8; j++)
#pragma unroll
            for (int f = 0; f < 4; f++) s[j][f] = 0.f;

#pragma unroll
        for (int kk = 0; kk < 12; kk++) {
            uint32_t ah[4], al[4];
            uint32_t aaddr = (uint32_t)((wp * 16 + l16) * QSTR + kk * 16 + lhi) * 2;
            ldm_x4(ah, sQh + aaddr);
            ldm_x4(al, sQl + aaddr);
#pragma unroll
            for (int j2 = 0; j2 < 4; j2++) {
                uint32_t baddr = (uint32_t)((j2 * 16 + brofs) * KSTR + kk * 16 + bcofs) * 2;
                uint32_t tbv[4], tl[4];
                ldm_x4(tbv, sKh + baddr);
                ldm_x4(tl, sKl + baddr);
                mma_bf16(s[2 * j2],     ah, tbv);
                mma_bf16(s[2 * j2],     ah, tl);
                mma_bf16(s[2 * j2],     al, tbv);
                mma_bf16(s[2 * j2 + 1], ah, tbv + 2);
                mma_bf16(s[2 * j2 + 1], ah, tl + 2);
                mma_bf16(s[2 * j2 + 1], al, tbv + 2);
            }
        }

#pragma unroll
        for (int j = 0; j < 8; j++) {
            int k0 = kt * 64 + j * 8 + 2 * (lane & 3);
            if (k0     > qrow1) s[j][0] = -1e30f;
            if (k0 + 1 > qrow1) s[j][1] = -1e30f;
            if (k0     > qrow2) s[j][2] = -1e30f;
            if (k0 + 1 > qrow2) s[j][3] = -1e30f;
        }
        float mr1 = -1e30f, mr2 = -1e30f;
#pragma unroll
        for (int j = 0; j < 8; j++) {
            mr1 = fmaxf(mr1, fmaxf(s[j][0], s[j][1]));
            mr2 = fmaxf(mr2, fmaxf(s[j][2], s[j][3]));
        }
        mr1 = fmaxf(mr1, __shfl_xor_sync(0xffffffffu, mr1, 1));
        mr1 = fmaxf(mr1, __shfl_xor_sync(0xffffffffu, mr1, 2));
        mr2 = fmaxf(mr2, __shfl_xor_sync(0xffffffffu, mr2, 1));
        mr2 = fmaxf(mr2, __shfl_xor_sync(0xffffffffu, mr2, 2));
        float mn1 = fmaxf(m1, mr1), mn2 = fmaxf(m2, mr2);
        float a1 = ex2f(m1 - mn1), a2 = ex2f(m2 - mn2);
        m1 = mn1; m2 = mn2;

        uint32_t phx[8][2], plx[8][2];
        float rs1 = 0.f, rs2 = 0.f;
#pragma unroll
        for (int j = 0; j < 8; j++) {
            float p0 = ex2f(s[j][0] - mn1), p1 = ex2f(s[j][1] - mn1);
            float p2 = ex2f(s[j][2] - mn2), p3 = ex2f(s[j][3] - mn2);
            rs1 += p0 + p1; rs2 += p2 + p3;
            phx[j][0] = packbf2(p0, p1);
            phx[j][1] = packbf2(p2, p3);
            float q0 = p0 - bfround(p0);
            float q1 = p1 - bfround(p1);
            float q2 = p2 - bfround(p2);
            float q3 = p3 - bfround(p3);
            plx[j][0] = packbf2(q0, q1);
            plx[j][1] = packbf2(q2, q3);
        }
        rs1 += __shfl_xor_sync(0xffffffffu, rs1, 1);
        rs1 += __shfl_xor_sync(0xffffffffu, rs1, 2);
        rs2 += __shfl_xor_sync(0xffffffffu, rs2, 1);
        rs2 += __shfl_xor_sync(0xffffffffu, rs2, 2);
        l1 = l1 * a1 + rs1;
        l2 = l2 * a2 + rs2;
#pragma unroll
        for (int t16 = 0; t16 < 16; t16++) {
            o[t16][0] *= a1; o[t16][1] *= a1;
            o[t16][2] *= a2; o[t16][3] *= a2;
        }

#pragma unroll
        for (int kt2 = 0; kt2 < 4; kt2++) {
            uint32_t pa_h[4] = {phx[2 * kt2][0], phx[2 * kt2][1],
                                phx[2 * kt2 + 1][0], phx[2 * kt2 + 1][1]};
            uint32_t pa_l[4] = {plx[2 * kt2][0], plx[2 * kt2][1],
                                plx[2 * kt2 + 1][0], plx[2 * kt2 + 1][1]};
            uint32_t vrow = (uint32_t)((kt2 * 16 + l16) * VSTR) * 2;
#pragma unroll
            for (int j2 = 0; j2 < 8; j2++) {
                uint32_t vaddr = vrow + (uint32_t)(j2 * 16 + lhi) * 2;
                uint32_t tv[4], tw[4];
                ldm_x4t(tv, sVh + vaddr);
                ldm_x4t(tw, sVl + vaddr);
                mma_bf16(o[2 * j2],     pa_h, tv);
                mma_bf16(o[2 * j2],     pa_h, tw);
                mma_bf16(o[2 * j2],     pa_l, tv);
                mma_bf16(o[2 * j2 + 1], pa_h, tv + 2);
                mma_bf16(o[2 * j2 + 1], pa_h, tw + 2);
                mma_bf16(o[2 * j2 + 1], pa_l, tv + 2);
            }
        }
    }

    // ---- epilogue: normalized output split to hi/lo bf16 ----
    float inv1 = 1.f / l1, inv2 = 1.f / l2;
    size_t row1 = (size_t)(b * TT + qrow1) * 2048 + h * 128;
    size_t row2 = (size_t)(b * TT + qrow2) * 2048 + h * 128;
#pragma unroll
    for (int t16 = 0; t16 < 16; t16++) {
        int col = t16 * 8 + 2 * (lane & 3);
        float v0 = o[t16][0] * inv1, v1 = o[t16][1] * inv1;
        float v2 = o[t16][2] * inv2, v3 = o[t16][3] * inv2;
        float f0 = bfround(v0), f1 = bfround(v1);
        float f2 = bfround(v2), f3 = bfround(v3);
        *(uint32_t*)&ohi[row1 + col] = packbf2(f0, f1);
        *(uint32_t*)&olo[row1 + col] = packbf2(v0 - f0, v1 - f1);
        *(uint32_t*)&ohi[row2 + col] = packbf2(f2, f3);
        *(uint32_t*)&olo[row2 + col] = packbf2(v2 - f2, v3 - f3);
    }
}

// ---------------------------------------------------------------------------
// Host launcher
// ---------------------------------------------------------------------------
extern "C" void kernel_launch(void* const* d_in, const int* in_sizes, int n_in,
                              void* d_out, int out_size)
{
    (void)in_sizes; (void)n_in; (void)out_size;

    const float* x     = (const float*)d_in[0];
    const float* W_dkv = (const float*)d_in[1];
    const float* b_dkv = (const float*)d_in[2];
    const float* W_kr  = (const float*)d_in[3];
    const float* b_kr  = (const float*)d_in[4];
    const float* W_qr  = (const float*)d_in[5];
    const float* b_qr  = (const float*)d_in[6];
    const float* W_uv  = (const float*)d_in[7];
    const float* b_uv  = (const float*)d_in[8];
    const float* W_uq  = (const float*)d_in[9];
    const float* b_uq  = (const float*)d_in[10];
    const float* W_o   = (const float*)d_in[11];
    const float* b_o   = (const float*)d_in[12];
    float* out = (float*)d_out;

    float *h, *kr, *qr;
    bf16 *xhi, *xlo, *hhi, *hlo, *athi, *atlo;
    bf16 *wdkvh, *wdkvl, *wqrh, *wqrl, *wuvh, *wuvl, *wuqh, *wuql, *woh, *wol;
    bf16 *qhi, *qlo, *khi, *klo, *vhi, *vlo;
    cudaGetSymbolAddress((void**)&h,    g_h);
    cudaGetSymbolAddress((void**)&kr,   g_kr);
    cudaGetSymbolAddress((void**)&qr,   g_qr);
    cudaGetSymbolAddress((void**)&xhi,  g_xhi);
    cudaGetSymbolAddress((void**)&xlo,  g_xlo);
    cudaGetSymbolAddress((void**)&hhi,  g_hhi);
    cudaGetSymbolAddress((void**)&hlo,  g_hlo);
    cudaGetSymbolAddress((void**)&athi, g_athi);
    cudaGetSymbolAddress((void**)&atlo, g_atlo);
    cudaGetSymbolAddress((void**)&wdkvh, g_wdkvh);
    cudaGetSymbolAddress((void**)&wdkvl, g_wdkvl);
    cudaGetSymbolAddress((void**)&wqrh, g_wqrh);
    cudaGetSymbolAddress((void**)&wqrl, g_wqrl);
    cudaGetSymbolAddress((void**)&wuvh, g_wuvh);
    cudaGetSymbolAddress((void**)&wuvl, g_wuvl);
    cudaGetSymbolAddress((void**)&wuqh, g_wuqh);
    cudaGetSymbolAddress((void**)&wuql, g_wuql);
    cudaGetSymbolAddress((void**)&woh,  g_woh);
    cudaGetSymbolAddress((void**)&wol,  g_wol);
    cudaGetSymbolAddress((void**)&qhi, g_qhi);
    cudaGetSymbolAddress((void**)&qlo, g_qlo);
    cudaGetSymbolAddress((void**)&khi, g_khi);
    cudaGetSymbolAddress((void**)&klo, g_klo);
    cudaGetSymbolAddress((void**)&vhi, g_vhi);
    cudaGetSymbolAddress((void**)&vlo, g_vlo);

    const int M = MROWS;  // 4096

    cudaFuncSetAttribute(gemm_mma, cudaFuncAttributeMaxDynamicSharedMemorySize, GSMEM);
    cudaFuncSetAttribute(attn_tc, cudaFuncAttributeMaxDynamicSharedMemorySize, ATTN_SMEM);

    // 1) x -> hi/lo
    split_act<<<(M * 512 + 255) / 256, 256>>>(x, 2048, 0, 2048, xhi, xlo);
    // 2) W_dkv
    wsplit_t<<<dim3(1024 / 32, 2048 / 32), 256>>>(W_dkv, 2048, 1024, wdkvh, wdkvl);
    // 3) W_o
    wsplit_t<<<dim3(2048 / 32, 2048 / 32), 256>>>(W_o, 2048, 2048, woh, wol);
    // 4) h = x @ W_dkv + b_dkv  (mode 1: fp32 h + hhi/hlo)   <-- profiled launch
    gemm_mma<<<dim3(8, 32), 128, GSMEM>>>(xhi, xlo, 2048, 0, wdkvh, wdkvl, 2048,
                                          b_dkv, h, 1024, 2048, hhi, hlo, 0, 0, 1);
    // 5) kr projection
    sgemm_bias<<<dim3(1, 64), 256>>>(h, 1024, 0, W_kr, b_kr, kr, 64, M, 64, 1024);
    // 6) W_qr
    wsplit_t<<<dim3(1024 / 32, 1024 / 32), 256>>>(W_qr, 1024, 1024, wqrh, wqrl);
    // 7) qr = h @ W_qr (mode 0 fp32)
    gemm_mma<<<dim3(8, 32), 128, GSMEM>>>(hhi, hlo, 1024, 0, wqrh, wqrl, 1024,
                                          b_qr, qr, 1024, 1024, 0, 0, 0, 0, 0);
    // 8,9) RoPE
    rope_kernel<<<(M * 32 + 255) / 256, 256>>>(kr, M, 64);
    rope_kernel<<<(M * 512 + 255) / 256, 256>>>(qr, M, 1024);
    // 10,11) W_uv, W_uq
    wsplit_t<<<dim3(4096 / 32, 512 / 32), 256>>>(W_uv, 512, 4096, wuvh, wuvl);
    wsplit_t<<<dim3(2048 / 32, 512 / 32), 256>>>(W_uq, 512, 2048, wuqh, wuql);
    // 12) kv GEMM (mode 2: khi/klo + vhi/vlo, per-head layout)
    gemm_mma<<<dim3(32, 32), 128, GSMEM>>>(hhi, hlo, 1024, 0, wuvh, wuvl, 512,
                                           b_uv, 0, 0, 512, khi, klo, vhi, vlo, 2);
    // 13) q GEMM (mode 3: qhi/qlo scaled, per-head layout)
    gemm_mma<<<dim3(16, 32), 128, GSMEM>>>(hhi, hlo, 1024, 512, wuqh, wuql, 512,
                                           b_uq, 0, 0, 512, qhi, qlo, 0, 0, 3);
    // 14,15) RoPE slices into attention buffers
    build_kr<<<(BB * NHH * TT * 64 + 255) / 256, 256>>>(kr, khi, klo);
    build_qr<<<(BB * NHH * TT * 64 + 255) / 256, 256>>>(qr, qhi, qlo);
    // 16) attention -> athi/atlo
    attn_tc<<<dim3(TT / 128, BB * NHH), 256, ATTN_SMEM>>>(qhi, qlo, khi, klo,
                                                          vhi, vlo, athi, atlo);
    // 17) out = attn @ W_o + b_o (mode 0 fp32)
    gemm_mma<<<dim3(16, 32), 128, GSMEM>>>(athi, atlo, 2048, 0, woh, wol, 2048,
                                           b_o, out, 2048, 2048, 0, 0, 0, 0, 0);
}

// round 11
// speedup vs baseline: 2.3228x; 1.0218x over previous
#include <cuda_runtime.h>
#include <cuda_bf16.h>
#include <math.h>
#include <stdint.h>

// Problem constants
#define BB   2
#define TT   2048
#define CC   2048
#define NHH  16
#define DKK  128
#define LATT 512
#define DHRR 64
#define MROWS (BB * TT)   // 4096

typedef __nv_bfloat16 bf16;

// ---------------------------------------------------------------------------
// Scratch (static device globals -- no allocation allowed)
// ---------------------------------------------------------------------------
__device__ float g_h   [(size_t)MROWS * 1024];
__device__ float g_kr  [(size_t)MROWS * 64];
__device__ float g_qr  [(size_t)MROWS * 1024];

__device__ bf16 g_xhi [(size_t)MROWS * 2048];
__device__ bf16 g_xlo [(size_t)MROWS * 2048];
__device__ bf16 g_hhi [(size_t)MROWS * 1024];
__device__ bf16 g_hlo [(size_t)MROWS * 1024];
__device__ bf16 g_athi[(size_t)MROWS * 2048];
__device__ bf16 g_atlo[(size_t)MROWS * 2048];

__device__ bf16 g_wdkvh[(size_t)1024 * 2048];
__device__ bf16 g_wdkvl[(size_t)1024 * 2048];
__device__ bf16 g_wqrh [(size_t)1024 * 1024];
__device__ bf16 g_wqrl [(size_t)1024 * 1024];
__device__ bf16 g_wuvh [(size_t)4096 * 512];
__device__ bf16 g_wuvl [(size_t)4096 * 512];
__device__ bf16 g_wuqh [(size_t)2048 * 512];
__device__ bf16 g_wuql [(size_t)2048 * 512];
__device__ bf16 g_woh  [(size_t)2048 * 2048];
__device__ bf16 g_wol  [(size_t)2048 * 2048];

__device__ bf16 g_qhi[(size_t)BB * NHH * TT * 192];
__device__ bf16 g_qlo[(size_t)BB * NHH * TT * 192];
__device__ bf16 g_khi[(size_t)BB * NHH * TT * 192];
__device__ bf16 g_klo[(size_t)BB * NHH * TT * 192];
__device__ bf16 g_vhi[(size_t)BB * NHH * TT * 128];
__device__ bf16 g_vlo[(size_t)BB * NHH * TT * 128];

#define SCLQ 0.12754984837627695f   // 1/sqrt(128) * log2(e)

// ---------------------------------------------------------------------------
// PTX helpers
// ---------------------------------------------------------------------------
__device__ __forceinline__ uint32_t smem_u32(const void* p)
{ return (uint32_t)__cvta_generic_to_shared(p); }

__device__ __forceinline__ void cp16(uint32_t dst, const void* src)
{ asm volatile("cp.async.cg.shared.global [%0], [%1], 16;\n" :: "r"(dst), "l"(src)); }

__device__ __forceinline__ void cp_commit()
{ asm volatile("cp.async.commit_group;\n"); }

template <int N>
__device__ __forceinline__ void cp_wait()
{ asm volatile("cp.async.wait_group %0;\n" :: "n"(N)); }

__device__ __forceinline__ void ldm_x4(uint32_t* r, uint32_t addr)
{
    asm volatile("ldmatrix.sync.aligned.m8n8.x4.shared.b16 {%0,%1,%2,%3}, [%4];\n"
        : "=r"(r[0]), "=r"(r[1]), "=r"(r[2]), "=r"(r[3]) : "r"(addr));
}
__device__ __forceinline__ void ldm_x4t(uint32_t* r, uint32_t addr)
{
    asm volatile("ldmatrix.sync.aligned.m8n8.x4.trans.shared.b16 {%0,%1,%2,%3}, [%4];\n"
        : "=r"(r[0]), "=r"(r[1]), "=r"(r[2]), "=r"(r[3]) : "r"(addr));
}
__device__ __forceinline__ void mma_bf16(float* d, const uint32_t* a, const uint32_t* b)
{
    asm volatile(
        "mma.sync.aligned.m16n8k16.row.col.f32.bf16.bf16.f32 "
        "{%0,%1,%2,%3}, {%4,%5,%6,%7}, {%8,%9}, {%0,%1,%2,%3};\n"
        : "+f"(d[0]), "+f"(d[1]), "+f"(d[2]), "+f"(d[3])
        : "r"(a[0]), "r"(a[1]), "r"(a[2]), "r"(a[3]), "r"(b[0]), "r"(b[1]));
}
__device__ __forceinline__ float ex2f(float x)
{ float y; asm("ex2.approx.f32 %0, %1;" : "=f"(y) : "f"(x)); return y; }

__device__ __forceinline__ uint32_t packbf2(float lo, float hi)
{ uint32_t d; asm("cvt.rn.bf16x2.f32 %0, %1, %2;" : "=r"(d) : "f"(hi), "f"(lo)); return d; }

__device__ __forceinline__ float bfround(float v)
{ return __bfloat162float(__float2bfloat16(v)); }

// ---------------------------------------------------------------------------
// Conversion kernels
// ---------------------------------------------------------------------------
__global__ void split_act(const float* __restrict__ A, int lda, int aoff, int Kw,
                          bf16* __restrict__ hi, bf16* __restrict__ lo)
{
    int idx = blockIdx.x * blockDim.x + threadIdx.x;
    int total = MROWS * (Kw / 4);
    if (idx >= total) return;
    int m = idx / (Kw / 4), k4 = (idx - m * (Kw / 4)) * 4;
    float4 v = *(const float4*)&A[(size_t)m * lda + aoff + k4];
    float h0 = bfround(v.x), h1 = bfround(v.y);
    float h2 = bfround(v.z), h3 = bfround(v.w);
    uint2 ph, pl;
    ph.x = packbf2(h0, h1); ph.y = packbf2(h2, h3);
    pl.x = packbf2(v.x - h0, v.y - h1); pl.y = packbf2(v.z - h2, v.w - h3);
    *(uint2*)&hi[(size_t)m * Kw + k4] = ph;
    *(uint2*)&lo[(size_t)m * Kw + k4] = pl;
}

__global__ void wsplit_t(const float* __restrict__ W, int K, int N,
                         bf16* __restrict__ hiT, bf16* __restrict__ loT)
{
    __shared__ float t[32][33];
    int tx = threadIdx.x & 31, ty = threadIdx.x >> 5;
    int k0 = blockIdx.y * 32, n0 = blockIdx.x * 32;
#pragma unroll
    for (int r = 0; r < 4; r++)
        t[ty + 8 * r][tx] = W[(size_t)(k0 + ty + 8 * r) * N + n0 + tx];
    __syncthreads();
#pragma unroll
    for (int r = 0; r < 4; r++) {
        float v = t[tx][ty + 8 * r];
        bf16 h = __float2bfloat16(v);
        size_t o = (size_t)(n0 + ty + 8 * r) * K + k0 + tx;
        hiT[o] = h;
        loT[o] = __float2bfloat16(v - __bfloat162float(h));
    }
}

// ---------------------------------------------------------------------------
// HMMA GEMM, compensated hi/lo, fused epilogues (unchanged from R10)
// ---------------------------------------------------------------------------
#define TST 40
#define A_ELE (128 * TST)
#define B_ELE (128 * TST)
#define STG_ELE (2 * A_ELE + 2 * B_ELE)
#define GSMEM (2 * STG_ELE * 2)

__global__ __launch_bounds__(128, 2)
void gemm_mma(const bf16* __restrict__ Ahi, const bf16* __restrict__ Alo,
              int lda, int aoff,
              const bf16* __restrict__ Bhi, const bf16* __restrict__ Blo,
              int ldb,
              const float* __restrict__ bias,
              float* __restrict__ Y, int ldy, int K,
              bf16* __restrict__ ho, bf16* __restrict__ lo_,
              bf16* __restrict__ ho2, bf16* __restrict__ lo2, int mode)
{
    extern __shared__ bf16 dsm[];
    const uint32_t sb0 = smem_u32(dsm);

    const int tid = threadIdx.x, lane = tid & 31, wid = tid >> 5;
    const int brow = blockIdx.y * 128, bcol = blockIdx.x * 128;
    const int wm = (wid >> 1) * 64, wn = (wid & 1) * 64;

    auto issue = [&](int st, int kt) {
        uint32_t s = sb0 + (uint32_t)(st * STG_ELE) * 2;
        int ke = kt * 32;
#pragma unroll
        for (int i = 0; i < 4; i++) {
            int c = tid + i * 128;
            int r = c >> 2, sg = (c & 3) * 8;
            uint32_t d = (uint32_t)(r * TST + sg) * 2;
            cp16(s + d, Ahi + (size_t)(brow + r) * lda + aoff + ke + sg);
            cp16(s + (uint32_t)A_ELE * 2 + d,
                 Alo + (size_t)(brow + r) * lda + aoff + ke + sg);
            cp16(s + (uint32_t)(2 * A_ELE) * 2 + d,
                 Bhi + (size_t)(bcol + r) * ldb + ke + sg);
            cp16(s + (uint32_t)(2 * A_ELE + B_ELE) * 2 + d,
                 Blo + (size_t)(bcol + r) * ldb + ke + sg);
        }
        cp_commit();
    };

    float acc[4][8][4];
#pragma unroll
    for (int i = 0; i < 4; i++)
#pragma unroll
        for (int j = 0; j < 8; j++)
#pragma unroll
            for (int f = 0; f < 4; f++) acc[i][j][f] = 0.f;

    const int ntiles = K / 32;
    issue(0, 0);
    issue(1, 1);

    const int l16 = lane & 15, lhi = (lane >> 4) * 8;
    const int brofs = (lane & 7) + ((lane >> 4) & 1) * 8;
    const int bcofs = ((lane >> 3) & 1) * 8;

    for (int kt = 0; kt < ntiles; kt++) {
        if (kt + 1 < ntiles) { cp_wait<1>(); } else { cp_wait<0>(); }
        __syncthreads();
        int cur = kt & 1;
        uint32_t s = sb0 + (uint32_t)(cur * STG_ELE) * 2;
        uint32_t sAh = s, sAl = s + (uint32_t)A_ELE * 2;
        uint32_t sBh = s + (uint32_t)(2 * A_ELE) * 2;
        uint32_t sBl = sBh + (uint32_t)B_ELE * 2;

#pragma unroll
        for (int kk = 0; kk < 32; kk += 16) {
            uint32_t bh[4][4], bl[4][4];
#pragma unroll
            for (int j2 = 0; j2 < 4; j2++) {
                uint32_t baddr =
                    (uint32_t)((wn + j2 * 16 + brofs) * TST + kk + bcofs) * 2;
                ldm_x4(bh[j2], sBh + baddr);
                ldm_x4(bl[j2], sBl + baddr);
            }
#pragma unroll
            for (int i = 0; i < 4; i++) {
                uint32_t ah[4], al[4];
                uint32_t aaddr = (uint32_t)((wm + i * 16 + l16) * TST + kk + lhi) * 2;
                ldm_x4(ah, sAh + aaddr);
                ldm_x4(al, sAl + aaddr);
#pragma unroll
                for (int j2 = 0; j2 < 4; j2++) {
                    mma_bf16(acc[i][2 * j2],     ah, bh[j2]);
                    mma_bf16(acc[i][2 * j2],     ah, bl[j2]);
                    mma_bf16(acc[i][2 * j2],     al, bh[j2]);
                    mma_bf16(acc[i][2 * j2 + 1], ah, bh[j2] + 2);
                    mma_bf16(acc[i][2 * j2 + 1], ah, bl[j2] + 2);
                    mma_bf16(acc[i][2 * j2 + 1], al, bh[j2] + 2);
                }
            }
        }
        __syncthreads();
        if (kt + 2 < ntiles) issue(cur, kt + 2);
    }

#pragma unroll
    for (int i = 0; i < 4; i++) {
#pragma unroll
        for (int j = 0; j < 8; j++) {
            int r0 = brow + wm + i * 16 + (lane >> 2);
            int c0 = bcol + wn + j * 8 + (lane & 3) * 2;
            float b0 = bias[c0], b1 = bias[c0 + 1];
            float v00 = acc[i][j][0] + b0, v01 = acc[i][j][1] + b1;
            float v10 = acc[i][j][2] + b0, v11 = acc[i][j][3] + b1;

            if (mode <= 1) {
                *(float2*)&Y[(size_t)r0 * ldy + c0]       = make_float2(v00, v01);
                *(float2*)&Y[(size_t)(r0 + 8) * ldy + c0] = make_float2(v10, v11);
            }
            if (mode == 1) {
                float f00 = bfround(v00), f01 = bfround(v01);
                float f10 = bfround(v10), f11 = bfround(v11);
                *(uint32_t*)&ho [(size_t)r0 * ldy + c0]       = packbf2(f00, f01);
                *(uint32_t*)&lo_[(size_t)r0 * ldy + c0]       = packbf2(v00 - f00, v01 - f01);
                *(uint32_t*)&ho [(size_t)(r0 + 8) * ldy + c0] = packbf2(f10, f11);
                *(uint32_t*)&lo_[(size_t)(r0 + 8) * ldy + c0] = packbf2(v10 - f10, v11 - f11);
            } else if (mode == 2) {
#pragma unroll
                for (int rr = 0; rr < 2; rr++) {
                    int r = r0 + rr * 8;
                    float va = rr ? v10 : v00, vb = rr ? v11 : v01;
                    int b = r >> 11, t = r & 2047;
                    float fa = bfround(va), fb = bfround(vb);
                    if (c0 < 2048) {
                        int hh = c0 >> 7, d = c0 & 127;
                        size_t base = ((size_t)(b * NHH + hh) * TT + t) * 192 + d;
                        *(uint32_t*)&ho [base] = packbf2(fa, fb);
                        *(uint32_t*)&lo_[base] = packbf2(va - fa, vb - fb);
                    } else {
                        int c2 = c0 - 2048;
                        int hh = c2 >> 7, d = c2 & 127;
                        size_t base = ((size_t)(b * NHH + hh) * TT + t) * 128 + d;
                        *(uint32_t*)&ho2[base] = packbf2(fa, fb);
                        *(uint32_t*)&lo2[base] = packbf2(va - fa, vb - fb);
                    }
                }
            } else if (mode == 3) {
#pragma unroll
                for (int rr = 0; rr < 2; rr++) {
                    int r = r0 + rr * 8;
                    float va = (rr ? v10 : v00) * SCLQ, vb = (rr ? v11 : v01) * SCLQ;
                    int b = r >> 11, t = r & 2047;
                    int hh = c0 >> 7, d = c0 & 127;
                    size_t base = ((size_t)(b * NHH + hh) * TT + t) * 192 + d;
                    float fa = bfround(va), fb = bfround(vb);
                    *(uint32_t*)&ho [base] = packbf2(fa, fb);
                    *(uint32_t*)&lo_[base] = packbf2(va - fa, vb - fb);
                }
            }
        }
    }
}

// ---------------------------------------------------------------------------
// Small SGEMM (N=64 W_kr projection only)
// ---------------------------------------------------------------------------
#define GBM 64
#define GBN 64
#define GBK 16

__global__ __launch_bounds__(256)
void sgemm_bias(const float* __restrict__ A, int lda, int aoff,
                const float* __restrict__ W,
                const float* __restrict__ bias,
                float* __restrict__ Y, int ldy,
                int M, int N, int K)
{
    __shared__ float As[GBK][GBM];
    __shared__ float Bs[GBK][GBN];

    const int tid = threadIdx.x;
    const int brow = blockIdx.y * GBM;
    const int bcol = blockIdx.x * GBN;
    const int tr = (tid / 16) * 4;
    const int tc = (tid % 16) * 4;

    float acc[4][4];
#pragma unroll
    for (int i = 0; i < 4; i++)
#pragma unroll
        for (int j = 0; j < 4; j++) acc[i][j] = 0.f;

    for (int k0 = 0; k0 < K; k0 += GBK) {
#pragma unroll
        for (int it = 0; it < (GBM * GBK) / 256; it++) {
            int i = tid + it * 256;
            int m = i / GBK, kk = i % GBK;
            As[kk][m] = A[(size_t)(brow + m) * lda + aoff + k0 + kk];
        }
#pragma unroll
        for (int it = 0; it < (GBK * GBN) / 256; it++) {
            int i = tid + it * 256;
            int kk = i / GBN, n = i % GBN;
            Bs[kk][n] = W[(size_t)(k0 + kk) * N + bcol + n];
        }
        __syncthreads();

#pragma unroll
        for (int kk = 0; kk < GBK; kk++) {
            float a[4], b[4];
#pragma unroll
            for (int i = 0; i < 4; i++) a[i] = As[kk][tr + i];
#pragma unroll
            for (int j = 0; j < 4; j++) b[j] = Bs[kk][tc + j];
#pragma unroll
            for (int i = 0; i < 4; i++)
#pragma unroll
                for (int j = 0; j < 4; j++) acc[i][j] = fmaf(a[i], b[j], acc[i][j]);
        }
        __syncthreads();
    }

#pragma unroll
    for (int i = 0; i < 4; i++)
#pragma unroll
        for (int j = 0; j < 4; j++)
            Y[(size_t)(brow + tr + i) * ldy + bcol + tc + j] =
                acc[i][j] + bias[bcol + tc + j];
}

// ---------------------------------------------------------------------------
// Interleaved RoPE (double-precision trig)
// ---------------------------------------------------------------------------
__global__ void rope_kernel(float* __restrict__ buf, int rows, int c)
{
    const int pairs = c >> 1;
    const int idx = blockIdx.x * blockDim.x + threadIdx.x;
    if (idx >= rows * pairs) return;
    const int row = idx / pairs;
    const int i   = idx - row * pairs;
    const int t   = row & (TT - 1);

    float theta = (float)exp(-2.0 * (double)i / (double)c * log(10000.0));
    float angle = (float)(t + 1) * theta;
    double a = (double)angle;
    float cs = (float)cos(a);
    float sn = (float)sin(a);

    float* p = buf + (size_t)row * c + 2 * i;
    float x0 = p[0], x1 = p[1];
    p[0] = x0 * cs - x1 * sn;
    p[1] = x1 * cs + x0 * sn;
}

// ---------------------------------------------------------------------------
// Fill RoPE slices of attention buffers (d in [128,192))
// ---------------------------------------------------------------------------
__global__ void build_kr(const float* __restrict__ kr,
                         bf16* __restrict__ khi, bf16* __restrict__ klo)
{
    int idx = blockIdx.x * blockDim.x + threadIdx.x;
    if (idx >= BB * NHH * TT * 64) return;
    int d = idx & 63; int r = idx >> 6;
    int t = r % TT; int bh = r / TT; int b = bh >> 4;
    float v = kr[((size_t)(b * TT + t)) * 64 + d];
    size_t base = ((size_t)bh * TT + t) * 192 + 128 + d;
    float f = bfround(v);
    khi[base] = __float2bfloat16(f);
    klo[base] = __float2bfloat16(v - f);
}

__global__ void build_qr(const float* __restrict__ qr,
                         bf16* __restrict__ qhi, bf16* __restrict__ qlo)
{
    int idx = blockIdx.x * blockDim.x + threadIdx.x;
    if (idx >= BB * NHH * TT * 64) return;
    int d = idx & 63; int r = idx >> 6;
    int t = r % TT; int bh = r / TT; int h = bh & 15; int b = bh >> 4;
    float v = qr[((size_t)(b * TT + t)) * 1024 + h * 64 + d] * SCLQ;
    size_t base = ((size_t)bh * TT + t) * 192 + 128 + d;
    float f = bfround(v);
    qhi[base] = __float2bfloat16(f);
    qlo[base] = __float2bfloat16(v - f);
}

// ---------------------------------------------------------------------------
// Tensor-core flash attention, compensated bf16.
// Q-hi in smem; Q-lo hoisted to registers; K/V hi/lo DOUBLE-BUFFERED.
// smem: Qh 51200B | K stages 2x(Kh+Kl) 102400B | V stages 2x(Vh+Vl) 69632B
// ---------------------------------------------------------------------------
#define QSTR 200
#define KSTR 200
#define VSTR 136
#define Q_ELEMS (128 * QSTR)           // 25600
#define KST_ELEMS (64 * KSTR)          // 12800 per buf
#define VST_ELEMS (64 * VSTR)          // 8704 per buf
#define K_BASE Q_ELEMS                 // 25600
#define V_BASE (Q_ELEMS + 4 * KST_ELEMS)  // 76800
#define ATTN_SMEM ((Q_ELEMS + 4 * KST_ELEMS + 4 * VST_ELEMS) * 2)  // 223232 B

__global__ __launch_bounds__(256, 1)
void attn_tc(const bf16* __restrict__ qhi, const bf16* __restrict__ qlo,
             const bf16* __restrict__ khi, const bf16* __restrict__ klo,
             const bf16* __restrict__ vhi, const bf16* __restrict__ vlo,
             bf16* __restrict__ ohi, bf16* __restrict__ olo)
{
    extern __shared__ bf16 smA[];
    const uint32_t sQh = smem_u32(smA);
    const uint32_t sK  = sQh + K_BASE * 2;   // stage s: +s*2*KST_ELEMS*2
    const uint32_t sV  = sQh + V_BASE * 2;

    const int tid = threadIdx.x, lane = tid & 31, wp = tid >> 5;
    const int bh = blockIdx.y;
    const int qi = gridDim.x - 1 - blockIdx.x;
    const int b = bh >> 4, h = bh & 15;
    const size_t base = (size_t)bh * TT;

    const int l16 = lane & 15, lhi = (lane >> 4) * 8;

    // ---- initial Q loads: Qh -> smem; Qlo -> K-stage-0 staging ----
    for (int i = tid; i < 128 * 24; i += 256) {
        int r = i / 24, c = (i % 24) * 8;
        size_t g = (base + (size_t)qi * 128 + r) * 192 + c;
        uint32_t d = (uint32_t)(r * QSTR + c) * 2;
        cp16(sQh + d, qhi + g);
        cp16(sK + d, qlo + g);     // staging (covers both K stage-0 bufs)
    }
    cp_commit();
    cp_wait<0>();
    __syncthreads();

    // hoist Q-lo fragments into registers
    uint32_t qlof[12][4];
#pragma unroll
    for (int kk = 0; kk < 12; kk++) {
        uint32_t aaddr = (uint32_t)((wp * 16 + l16) * QSTR + kk * 16 + lhi) * 2;
        ldm_x4(qlof[kk], sK + aaddr);
    }
    __syncthreads();   // staging consumed; safe to overwrite with K stage 0

    auto issueKV = [&](int st, int kt) {
        uint32_t kb = sK + (uint32_t)(st * 2 * KST_ELEMS) * 2;
        uint32_t vb = sV + (uint32_t)(st * 2 * VST_ELEMS) * 2;
        for (int i = tid; i < 64 * 24; i += 256) {
            int r = i / 24, c = (i % 24) * 8;
            size_t g = (base + (size_t)kt * 64 + r) * 192 + c;
            uint32_t d = (uint32_t)(r * KSTR + c) * 2;
            cp16(kb + d, khi + g);
            cp16(kb + (uint32_t)KST_ELEMS * 2 + d, klo + g);
        }
        for (int i = tid; i < 64 * 16; i += 256) {
            int r = i / 16, c = (i % 16) * 8;
            size_t g = (base + (size_t)kt * 64 + r) * 128 + c;
            uint32_t d = (uint32_t)(r * VSTR + c) * 2;
            cp16(vb + d, vhi + g);
            cp16(vb + (uint32_t)VST_ELEMS * 2 + d, vlo + g);
        }
        cp_commit();
    };

    float o[16][4];
#pragma unroll
    for (int i = 0; i < 16; i++)
#pragma unroll
        for (int f = 0; f < 4; f++) o[i][f] = 0.f;

    float m1 = -1e30f, m2 = -1e30f, l1 = 0.f, l2 = 0.f;
    const int qrow1 = qi * 128 + wp * 16 + (lane >> 2);
    const int qrow2 = qrow1 + 8;
    const int brofs = (lane & 7) + ((lane >> 4) & 1) * 8;
    const int bcofs = ((lane >> 3) & 1) * 8;

    const int nkt = 2 * qi + 2;
    issueKV(0, 0);

    for (int kt = 0; kt < nkt; kt++) {
        if (kt + 1 < nkt) {
            issueKV((kt + 1) & 1, kt + 1);
            cp_wait<1>();
        } else {
            cp_wait<0>();
        }
        __syncthreads();

        const int st = kt & 1;
        const uint32_t sKh = sK + (uint32_t)(st * 2 * KST_ELEMS) * 2;
        const uint32_t sKl = sKh + (uint32_t)KST_ELEMS * 2;
        const uint32_t sVh = sV + (uint32_t)(st * 2 * VST_ELEMS) * 2;
        const uint32_t sVl = sVh + (uint32_t)VST_ELEMS * 2;

        float s[8][4];
#pragma unroll
        for (int j = 0; j < 8; j++)
#pragma unroll
            for (int f = 0; f < 4; f++) s[j][f] = 0.f;

#pragma unroll
        for (int kk = 0; kk < 12; kk++) {
            uint32_t ah[4];
            uint32_t aaddr = (uint32_t)((wp * 16 + l16) * QSTR + kk * 16 + lhi) * 2;
            ldm_x4(ah, sQh + aaddr);
            const uint32_t* al = qlof[kk];
#pragma unroll
            for (int j2 = 0; j2 < 4; j2++) {
                uint32_t baddr = (uint32_t)((j2 * 16 + brofs) * KSTR + kk * 16 + bcofs) * 2;
                uint32_t tbv[4], tl[4];
                ldm_x4(tbv, sKh + baddr);
                ldm_x4(tl, sKl + baddr);
                mma_bf16(s[2 * j2],     ah, tbv);
                mma_bf16(s[2 * j2],     ah, tl);
                mma_bf16(s[2 * j2],     al, tbv);
                mma_bf16(s[2 * j2 + 1], ah, tbv + 2);
                mma_bf16(s[2 * j2 + 1], ah, tl + 2);
                mma_bf16(s[2 * j2 + 1], al, tbv + 2);
            }
        }

#pragma unroll
        for (int j = 0; j < 8; j++) {
            int k0 = kt * 64 + j * 8 + 2 * (lane & 3);
            if (k0     > qrow1) s[j][0] = -1e30f;
            if (k0 + 1 > qrow1) s[j][1] = -1e30f;
            if (k0     > qrow2) s[j][2] = -1e30f;
            if (k0 + 1 > qrow2) s[j][3] = -1e30f;
        }
        float mr1 = -1e30f, mr2 = -1e30f;
#pragma unroll
        for (int j = 0; j < 8; j++) {
            mr1 = fmaxf(mr1, fmaxf(s[j][0], s[j][1]));
            mr2 = fmaxf(mr2, fmaxf(s[j][2], s[j][3]));
        }
        mr1 = fmaxf(mr1, __shfl_xor_sync(0xffffffffu, mr1, 1));
        mr1 = fmaxf(mr1, __shfl_xor_sync(0xffffffffu, mr1, 2));
        mr2 = fmaxf(mr2, __shfl_xor_sync(0xffffffffu, mr2, 1));
        mr2 = fmaxf(mr2, __shfl_xor_sync(0xffffffffu, mr2, 2));
        float mn1 = fmaxf(m1, mr1), mn2 = fmaxf(m2, mr2);
        float a1 = ex2f(m1 - mn1), a2 = ex2f(m2 - mn2);
        m1 = mn1; m2 = mn2;

        uint32_t phx[8][2], plx[8][2];
        float rs1 = 0.f, rs2 = 0.f;
#pragma unroll
        for (int j = 0; j < 8; j++) {
            float p0 = ex2f(s[j][0] - mn1), p1 = ex2f(s[j][1] - mn1);
            float p2 = ex2f(s[j][2] - mn2), p3 = ex2f(s[j][3] - mn2);
            rs1 += p0 + p1; rs2 += p2 + p3;
            phx[j][0] = packbf2(p0, p1);
            phx[j][1] = packbf2(p2, p3);
            float q0 = p0 - bfround(p0);
            float q1 = p1 - bfround(p1);
            float q2 = p2 - bfround(p2);
            float q3 = p3 - bfround(p3);
            plx[j][0] = packbf2(q0, q1);
            plx[j][1] = packbf2(q2, q3);
        }
        rs1 += __shfl_xor_sync(0xffffffffu, rs1, 1);
        rs1 += __shfl_xor_sync(0xffffffffu, rs1, 2);
        rs2 += __shfl_xor_sync(0xffffffffu, rs2, 1);
        rs2 += __shfl_xor_sync(0xffffffffu, rs2, 2);
        l1 = l1 * a1 + rs1;
        l2 = l2 * a2 + rs2;
#pragma unroll
        for (int t16 = 0; t16 < 16; t16++) {
            o[t16][0] *= a1; o[t16][1] *= a1;
            o[t16][2] *= a2; o[t16][3] *= a2;
        }

#pragma unroll
        for (int kt2 = 0; kt2 < 4; kt2++) {
            uint32_t pa_h[4] = {phx[2 * kt2][0], phx[2 * kt2][1],
                                phx[2 * kt2 + 1][0], phx[2 * kt2 + 1][1]};
            uint32_t pa_l[4] = {plx[2 * kt2][0], plx[2 * kt2][1],
                                plx[2 * kt2 + 1][0], plx[2 * kt2 + 1][1]};
            uint32_t vrow = (uint32_t)((kt2 * 16 + l16) * VSTR) * 2;
#pragma unroll
            for (int j2 = 0; j2 < 8; j2++) {
                uint32_t vaddr = vrow + (uint32_t)(j2 * 16 + lhi) * 2;
                uint32_t tv[4], tw[4];
                ldm_x4t(tv, sVh + vaddr);
                ldm_x4t(tw, sVl + vaddr);
                mma_bf16(o[2 * j2],     pa_h, tv);
                mma_bf16(o[2 * j2],     pa_h, tw);
                mma_bf16(o[2 * j2],     pa_l, tv);
                mma_bf16(o[2 * j2 + 1], pa_h, tv + 2);
                mma_bf16(o[2 * j2 + 1], pa_h, tw + 2);
                mma_bf16(o[2 * j2 + 1], pa_l, tv + 2);
            }
        }
        __syncthreads();   // all warps done with stage st before it is re-issued
    }

    // ---- epilogue: normalized output split to hi/lo bf16 ----
    float inv1 = 1.f / l1, inv2 = 1.f / l2;
    size_t row1 = (size_t)(b * TT + qrow1) * 2048 + h * 128;
    size_t row2 = (size_t)(b * TT + qrow2) * 2048 + h * 128;
#pragma unroll
    for (int t16 = 0; t16 < 16; t16++) {
        int col = t16 * 8 + 2 * (lane & 3);
        float v0 = o[t16][0] * inv1, v1 = o[t16][1] * inv1;
        float v2 = o[t16][2] * inv2, v3 = o[t16][3] * inv2;
        float f0 = bfround(v0), f1 = bfround(v1);
        float f2 = bfround(v2), f3 = bfround(v3);
        *(uint32_t*)&ohi[row1 + col] = packbf2(f0, f1);
        *(uint32_t*)&olo[row1 + col] = packbf2(v0 - f0, v1 - f1);
        *(uint32_t*)&ohi[row2 + col] = packbf2(f2, f3);
        *(uint32_t*)&olo[row2 + col] = packbf2(v2 - f2, v3 - f3);
    }
}

// ---------------------------------------------------------------------------
// Host launcher
// ---------------------------------------------------------------------------
extern "C" void kernel_launch(void* const* d_in, const int* in_sizes, int n_in,
                              void* d_out, int out_size)
{
    (void)in_sizes; (void)n_in; (void)out_size;

    const float* x     = (const float*)d_in[0];
    const float* W_dkv = (const float*)d_in[1];
    const float* b_dkv = (const float*)d_in[2];
    const float* W_kr  = (const float*)d_in[3];
    const float* b_kr  = (const float*)d_in[4];
    const float* W_qr  = (const float*)d_in[5];
    const float* b_qr  = (const float*)d_in[6];
    const float* W_uv  = (const float*)d_in[7];
    const float* b_uv  = (const float*)d_in[8];
    const float* W_uq  = (const float*)d_in[9];
    const float* b_uq  = (const float*)d_in[10];
    const float* W_o   = (const float*)d_in[11];
    const float* b_o   = (const float*)d_in[12];
    float* out = (float*)d_out;

    float *h, *kr, *qr;
    bf16 *xhi, *xlo, *hhi, *hlo, *athi, *atlo;
    bf16 *wdkvh, *wdkvl, *wqrh, *wqrl, *wuvh, *wuvl, *wuqh, *wuql, *woh, *wol;
    bf16 *qhi, *qlo, *khi, *klo, *vhi, *vlo;
    cudaGetSymbolAddress((void**)&h,    g_h);
    cudaGetSymbolAddress((void**)&kr,   g_kr);
    cudaGetSymbolAddress((void**)&qr,   g_qr);
    cudaGetSymbolAddress((void**)&xhi,  g_xhi);
    cudaGetSymbolAddress((void**)&xlo,  g_xlo);
    cudaGetSymbolAddress((void**)&hhi,  g_hhi);
    cudaGetSymbolAddress((void**)&hlo,  g_hlo);
    cudaGetSymbolAddress((void**)&athi, g_athi);
    cudaGetSymbolAddress((void**)&atlo, g_atlo);
    cudaGetSymbolAddress((void**)&wdkvh, g_wdkvh);
    cudaGetSymbolAddress((void**)&wdkvl, g_wdkvl);
    cudaGetSymbolAddress((void**)&wqrh, g_wqrh);
    cudaGetSymbolAddress((void**)&wqrl, g_wqrl);
    cudaGetSymbolAddress((void**)&wuvh, g_wuvh);
    cudaGetSymbolAddress((void**)&wuvl, g_wuvl);
    cudaGetSymbolAddress((void**)&wuqh, g_wuqh);
    cudaGetSymbolAddress((void**)&wuql, g_wuql);
    cudaGetSymbolAddress((void**)&woh,  g_woh);
    cudaGetSymbolAddress((void**)&wol,  g_wol);
    cudaGetSymbolAddress((void**)&qhi, g_qhi);
    cudaGetSymbolAddress((void**)&qlo, g_qlo);
    cudaGetSymbolAddress((void**)&khi, g_khi);
    cudaGetSymbolAddress((void**)&klo, g_klo);
    cudaGetSymbolAddress((void**)&vhi, g_vhi);
    cudaGetSymbolAddress((void**)&vlo, g_vlo);

    const int M = MROWS;  // 4096

    cudaFuncSetAttribute(gemm_mma, cudaFuncAttributeMaxDynamicSharedMemorySize, GSMEM);
    cudaFuncSetAttribute(attn_tc, cudaFuncAttributeMaxDynamicSharedMemorySize, ATTN_SMEM);

    // 1) x -> hi/lo
    split_act<<<(M * 512 + 255) / 256, 256>>>(x, 2048, 0, 2048, xhi, xlo);
    // 2) W_dkv
    wsplit_t<<<dim3(1024 / 32, 2048 / 32), 256>>>(W_dkv, 2048, 1024, wdkvh, wdkvl);
    // 3) W_o
    wsplit_t<<<dim3(2048 / 32, 2048 / 32), 256>>>(W_o, 2048, 2048, woh, wol);
    // 4) h = x @ W_dkv + b_dkv  (mode 1)   <-- profiled launch
    gemm_mma<<<dim3(8, 32), 128, GSMEM>>>(xhi, xlo, 2048, 0, wdkvh, wdkvl, 2048,
                                          b_dkv, h, 1024, 2048, hhi, hlo, 0, 0, 1);
    // 5) kr projection
    sgemm_bias<<<dim3(1, 64), 256>>>(h, 1024, 0, W_kr, b_kr, kr, 64, M, 64, 1024);
    // 6) W_qr
    wsplit_t<<<dim3(1024 / 32, 1024 / 32), 256>>>(W_qr, 1024, 1024, wqrh, wqrl);
    // 7) qr = h @ W_qr (mode 0)
    gemm_mma<<<dim3(8, 32), 128, GSMEM>>>(hhi, hlo, 1024, 0, wqrh, wqrl, 1024,
                                          b_qr, qr, 1024, 1024, 0, 0, 0, 0, 0);
    // 8,9) RoPE
    rope_kernel<<<(M * 32 + 255) / 256, 256>>>(kr, M, 64);
    rope_kernel<<<(M * 512 + 255) / 256, 256>>>(qr, M, 1024);
    // 10,11) W_uv, W_uq
    wsplit_t<<<dim3(4096 / 32, 512 / 32), 256>>>(W_uv, 512, 4096, wuvh, wuvl);
    wsplit_t<<<dim3(2048 / 32, 512 / 32), 256>>>(W_uq, 512, 2048, wuqh, wuql);
    // 12) kv GEMM (mode 2)
    gemm_mma<<<dim3(32, 32), 128, GSMEM>>>(hhi, hlo, 1024, 0, wuvh, wuvl, 512,
                                           b_uv, 0, 0, 512, khi, klo, vhi, vlo, 2);
    // 13) q GEMM (mode 3)
    gemm_mma<<<dim3(16, 32), 128, GSMEM>>>(hhi, hlo, 1024, 512, wuqh, wuql, 512,
                                           b_uq, 0, 0, 512, qhi, qlo, 0, 0, 3);
    // 14,15) RoPE slices
    build_kr<<<(BB * NHH * TT * 64 + 255) / 256, 256>>>(kr, khi, klo);
    build_qr<<<(BB * NHH * TT * 64 + 255) / 256, 256>>>(qr, qhi, qlo);
    // 16) attention -> athi/atlo
    attn_tc<<<dim3(TT / 128, BB * NHH), 256, ATTN_SMEM>>>(qhi, qlo, khi, klo,
                                                          vhi, vlo, athi, atlo);
    // 17) out = attn @ W_o + b_o (mode 0)
    gemm_mma<<<dim3(16, 32), 128, GSMEM>>>(athi, atlo, 2048, 0, woh, wol, 2048,
                                           b_o, out, 2048, 2048, 0, 0, 0, 0, 0);
}

// round 12
// speedup vs baseline: 2.3279x; 1.0022x over previous
#include <cuda_runtime.h>
#include <cuda_bf16.h>
#include <math.h>
#include <stdint.h>

// Problem constants
#define BB   2
#define TT   2048
#define CC   2048
#define NHH  16
#define DKK  128
#define LATT 512
#define DHRR 64
#define MROWS (BB * TT)   // 4096

typedef __nv_bfloat16 bf16;

// ---------------------------------------------------------------------------
// Scratch (static device globals -- no allocation allowed)
// ---------------------------------------------------------------------------
__device__ float g_h   [(size_t)MROWS * 1024];
__device__ float g_kr  [(size_t)MROWS * 64];
__device__ float g_qr  [(size_t)MROWS * 1024];

__device__ bf16 g_xhi [(size_t)MROWS * 2048];
__device__ bf16 g_xlo [(size_t)MROWS * 2048];
__device__ bf16 g_hhi [(size_t)MROWS * 1024];
__device__ bf16 g_hlo [(size_t)MROWS * 1024];
__device__ bf16 g_athi[(size_t)MROWS * 2048];
__device__ bf16 g_atlo[(size_t)MROWS * 2048];

__device__ bf16 g_wdkvh[(size_t)1024 * 2048];
__device__ bf16 g_wdkvl[(size_t)1024 * 2048];
__device__ bf16 g_wqrh [(size_t)1024 * 1024];
__device__ bf16 g_wqrl [(size_t)1024 * 1024];
__device__ bf16 g_wuvh [(size_t)4096 * 512];
__device__ bf16 g_wuvl [(size_t)4096 * 512];
__device__ bf16 g_wuqh [(size_t)2048 * 512];
__device__ bf16 g_wuql [(size_t)2048 * 512];
__device__ bf16 g_woh  [(size_t)2048 * 2048];
__device__ bf16 g_wol  [(size_t)2048 * 2048];

__device__ bf16 g_qhi[(size_t)BB * NHH * TT * 192];
__device__ bf16 g_qlo[(size_t)BB * NHH * TT * 192];
__device__ bf16 g_khi[(size_t)BB * NHH * TT * 192];
__device__ bf16 g_klo[(size_t)BB * NHH * TT * 192];
__device__ bf16 g_vhi[(size_t)BB * NHH * TT * 128];
__device__ bf16 g_vlo[(size_t)BB * NHH * TT * 128];

#define SCLQ 0.12754984837627695f   // 1/sqrt(128) * log2(e)

// ---------------------------------------------------------------------------
// PTX helpers
// ---------------------------------------------------------------------------
__device__ __forceinline__ uint32_t smem_u32(const void* p)
{ return (uint32_t)__cvta_generic_to_shared(p); }

__device__ __forceinline__ void cp16(uint32_t dst, const void* src)
{ asm volatile("cp.async.cg.shared.global [%0], [%1], 16;\n" :: "r"(dst), "l"(src)); }

__device__ __forceinline__ void cp_commit()
{ asm volatile("cp.async.commit_group;\n"); }

template <int N>
__device__ __forceinline__ void cp_wait()
{ asm volatile("cp.async.wait_group %0;\n" :: "n"(N)); }

__device__ __forceinline__ void ldm_x4(uint32_t* r, uint32_t addr)
{
    asm volatile("ldmatrix.sync.aligned.m8n8.x4.shared.b16 {%0,%1,%2,%3}, [%4];\n"
        : "=r"(r[0]), "=r"(r[1]), "=r"(r[2]), "=r"(r[3]) : "r"(addr));
}
__device__ __forceinline__ void ldm_x4t(uint32_t* r, uint32_t addr)
{
    asm volatile("ldmatrix.sync.aligned.m8n8.x4.trans.shared.b16 {%0,%1,%2,%3}, [%4];\n"
        : "=r"(r[0]), "=r"(r[1]), "=r"(r[2]), "=r"(r[3]) : "r"(addr));
}
__device__ __forceinline__ void mma_bf16(float* d, const uint32_t* a, const uint32_t* b)
{
    asm volatile(
        "mma.sync.aligned.m16n8k16.row.col.f32.bf16.bf16.f32 "
        "{%0,%1,%2,%3}, {%4,%5,%6,%7}, {%8,%9}, {%0,%1,%2,%3};\n"
        : "+f"(d[0]), "+f"(d[1]), "+f"(d[2]), "+f"(d[3])
        : "r"(a[0]), "r"(a[1]), "r"(a[2]), "r"(a[3]), "r"(b[0]), "r"(b[1]));
}
__device__ __forceinline__ float ex2f(float x)
{ float y; asm("ex2.approx.f32 %0, %1;" : "=f"(y) : "f"(x)); return y; }

__device__ __forceinline__ uint32_t packbf2(float lo, float hi)
{ uint32_t d; asm("cvt.rn.bf16x2.f32 %0, %1, %2;" : "=r"(d) : "f"(hi), "f"(lo)); return d; }

__device__ __forceinline__ float bfround(float v)
{ return __bfloat162float(__float2bfloat16(v)); }

// ---------------------------------------------------------------------------
// Conversion kernels
// ---------------------------------------------------------------------------
__global__ void split_act(const float* __restrict__ A, int lda, int aoff, int Kw,
                          bf16* __restrict__ hi, bf16* __restrict__ lo)
{
    int idx = blockIdx.x * blockDim.x + threadIdx.x;
    int total = MROWS * (Kw / 4);
    if (idx >= total) return;
    int m = idx / (Kw / 4), k4 = (idx - m * (Kw / 4)) * 4;
    float4 v = *(const float4*)&A[(size_t)m * lda + aoff + k4];
    float h0 = bfround(v.x), h1 = bfround(v.y);
    float h2 = bfround(v.z), h3 = bfround(v.w);
    uint2 ph, pl;
    ph.x = packbf2(h0, h1); ph.y = packbf2(h2, h3);
    pl.x = packbf2(v.x - h0, v.y - h1); pl.y = packbf2(v.z - h2, v.w - h3);
    *(uint2*)&hi[(size_t)m * Kw + k4] = ph;
    *(uint2*)&lo[(size_t)m * Kw + k4] = pl;
}

__global__ void wsplit_t(const float* __restrict__ W, int K, int N,
                         bf16* __restrict__ hiT, bf16* __restrict__ loT)
{
    __shared__ float t[32][33];
    int tx = threadIdx.x & 31, ty = threadIdx.x >> 5;
    int k0 = blockIdx.y * 32, n0 = blockIdx.x * 32;
#pragma unroll
    for (int r = 0; r < 4; r++)
        t[ty + 8 * r][tx] = W[(size_t)(k0 + ty + 8 * r) * N + n0 + tx];
    __syncthreads();
#pragma unroll
    for (int r = 0; r < 4; r++) {
        float v = t[tx][ty + 8 * r];
        bf16 h = __float2bfloat16(v);
        size_t o = (size_t)(n0 + ty + 8 * r) * K + k0 + tx;
        hiT[o] = h;
        loT[o] = __float2bfloat16(v - __bfloat162float(h));
    }
}

// ---------------------------------------------------------------------------
// HMMA GEMM, compensated hi/lo, fused epilogues.
// R12: MMA issue order restructured into 3 rounds of 8 independent MMAs
// (same per-accumulator term order -> bit-identical results).
// ---------------------------------------------------------------------------
#define TST 40
#define A_ELE (128 * TST)
#define B_ELE (128 * TST)
#define STG_ELE (2 * A_ELE + 2 * B_ELE)
#define GSMEM (2 * STG_ELE * 2)

__global__ __launch_bounds__(128, 2)
void gemm_mma(const bf16* __restrict__ Ahi, const bf16* __restrict__ Alo,
              int lda, int aoff,
              const bf16* __restrict__ Bhi, const bf16* __restrict__ Blo,
              int ldb,
              const float* __restrict__ bias,
              float* __restrict__ Y, int ldy, int K,
              bf16* __restrict__ ho, bf16* __restrict__ lo_,
              bf16* __restrict__ ho2, bf16* __restrict__ lo2, int mode)
{
    extern __shared__ bf16 dsm[];
    const uint32_t sb0 = smem_u32(dsm);

    const int tid = threadIdx.x, lane = tid & 31, wid = tid >> 5;
    const int brow = blockIdx.y * 128, bcol = blockIdx.x * 128;
    const int wm = (wid >> 1) * 64, wn = (wid & 1) * 64;

    auto issue = [&](int st, int kt) {
        uint32_t s = sb0 + (uint32_t)(st * STG_ELE) * 2;
        int ke = kt * 32;
#pragma unroll
        for (int i = 0; i < 4; i++) {
            int c = tid + i * 128;
            int r = c >> 2, sg = (c & 3) * 8;
            uint32_t d = (uint32_t)(r * TST + sg) * 2;
            cp16(s + d, Ahi + (size_t)(brow + r) * lda + aoff + ke + sg);
            cp16(s + (uint32_t)A_ELE * 2 + d,
                 Alo + (size_t)(brow + r) * lda + aoff + ke + sg);
            cp16(s + (uint32_t)(2 * A_ELE) * 2 + d,
                 Bhi + (size_t)(bcol + r) * ldb + ke + sg);
            cp16(s + (uint32_t)(2 * A_ELE + B_ELE) * 2 + d,
                 Blo + (size_t)(bcol + r) * ldb + ke + sg);
        }
        cp_commit();
    };

    float acc[4][8][4];
#pragma unroll
    for (int i = 0; i < 4; i++)
#pragma unroll
        for (int j = 0; j < 8; j++)
#pragma unroll
            for (int f = 0; f < 4; f++) acc[i][j][f] = 0.f;

    const int ntiles = K / 32;
    issue(0, 0);
    issue(1, 1);

    const int l16 = lane & 15, lhi = (lane >> 4) * 8;
    const int brofs = (lane & 7) + ((lane >> 4) & 1) * 8;
    const int bcofs = ((lane >> 3) & 1) * 8;

    for (int kt = 0; kt < ntiles; kt++) {
        if (kt + 1 < ntiles) { cp_wait<1>(); } else { cp_wait<0>(); }
        __syncthreads();
        int cur = kt & 1;
        uint32_t s = sb0 + (uint32_t)(cur * STG_ELE) * 2;
        uint32_t sAh = s, sAl = s + (uint32_t)A_ELE * 2;
        uint32_t sBh = s + (uint32_t)(2 * A_ELE) * 2;
        uint32_t sBl = sBh + (uint32_t)B_ELE * 2;

#pragma unroll
        for (int kk = 0; kk < 32; kk += 16) {
            uint32_t bh[4][4], bl[4][4];
#pragma unroll
            for (int j2 = 0; j2 < 4; j2++) {
                uint32_t baddr =
                    (uint32_t)((wn + j2 * 16 + brofs) * TST + kk + bcofs) * 2;
                ldm_x4(bh[j2], sBh + baddr);
                ldm_x4(bl[j2], sBl + baddr);
            }
#pragma unroll
            for (int i = 0; i < 4; i++) {
                uint32_t ah[4], al[4];
                uint32_t aaddr = (uint32_t)((wm + i * 16 + l16) * TST + kk + lhi) * 2;
                ldm_x4(ah, sAh + aaddr);
                ldm_x4(al, sAl + aaddr);
                // round 1: ah*bh into 8 distinct accumulators
#pragma unroll
                for (int j2 = 0; j2 < 4; j2++) {
                    mma_bf16(acc[i][2 * j2],     ah, bh[j2]);
                    mma_bf16(acc[i][2 * j2 + 1], ah, bh[j2] + 2);
                }
                // round 2: ah*bl
#pragma unroll
                for (int j2 = 0; j2 < 4; j2++) {
                    mma_bf16(acc[i][2 * j2],     ah, bl[j2]);
                    mma_bf16(acc[i][2 * j2 + 1], ah, bl[j2] + 2);
                }
                // round 3: al*bh
#pragma unroll
                for (int j2 = 0; j2 < 4; j2++) {
                    mma_bf16(acc[i][2 * j2],     al, bh[j2]);
                    mma_bf16(acc[i][2 * j2 + 1], al, bh[j2] + 2);
                }
            }
        }
        __syncthreads();
        if (kt + 2 < ntiles) issue(cur, kt + 2);
    }

#pragma unroll
    for (int i = 0; i < 4; i++) {
#pragma unroll
        for (int j = 0; j < 8; j++) {
            int r0 = brow + wm + i * 16 + (lane >> 2);
            int c0 = bcol + wn + j * 8 + (lane & 3) * 2;
            float b0 = bias[c0], b1 = bias[c0 + 1];
            float v00 = acc[i][j][0] + b0, v01 = acc[i][j][1] + b1;
            float v10 = acc[i][j][2] + b0, v11 = acc[i][j][3] + b1;

            if (mode <= 1) {
                *(float2*)&Y[(size_t)r0 * ldy + c0]       = make_float2(v00, v01);
                *(float2*)&Y[(size_t)(r0 + 8) * ldy + c0] = make_float2(v10, v11);
            }
            if (mode == 1) {
                float f00 = bfround(v00), f01 = bfround(v01);
                float f10 = bfround(v10), f11 = bfround(v11);
                *(uint32_t*)&ho [(size_t)r0 * ldy + c0]       = packbf2(f00, f01);
                *(uint32_t*)&lo_[(size_t)r0 * ldy + c0]       = packbf2(v00 - f00, v01 - f01);
                *(uint32_t*)&ho [(size_t)(r0 + 8) * ldy + c0] = packbf2(f10, f11);
                *(uint32_t*)&lo_[(size_t)(r0 + 8) * ldy + c0] = packbf2(v10 - f10, v11 - f11);
            } else if (mode == 2) {
#pragma unroll
                for (int rr = 0; rr < 2; rr++) {
                    int r = r0 + rr * 8;
                    float va = rr ? v10 : v00, vb = rr ? v11 : v01;
                    int b = r >> 11, t = r & 2047;
                    float fa = bfround(va), fb = bfround(vb);
                    if (c0 < 2048) {
                        int hh = c0 >> 7, d = c0 & 127;
                        size_t base = ((size_t)(b * NHH + hh) * TT + t) * 192 + d;
                        *(uint32_t*)&ho [base] = packbf2(fa, fb);
                        *(uint32_t*)&lo_[base] = packbf2(va - fa, vb - fb);
                    } else {
                        int c2 = c0 - 2048;
                        int hh = c2 >> 7, d = c2 & 127;
                        size_t base = ((size_t)(b * NHH + hh) * TT + t) * 128 + d;
                        *(uint32_t*)&ho2[base] = packbf2(fa, fb);
                        *(uint32_t*)&lo2[base] = packbf2(va - fa, vb - fb);
                    }
                }
            } else if (mode == 3) {
#pragma unroll
                for (int rr = 0; rr < 2; rr++) {
                    int r = r0 + rr * 8;
                    float va = (rr ? v10 : v00) * SCLQ, vb = (rr ? v11 : v01) * SCLQ;
                    int b = r >> 11, t = r & 2047;
                    int hh = c0 >> 7, d = c0 & 127;
                    size_t base = ((size_t)(b * NHH + hh) * TT + t) * 192 + d;
                    float fa = bfround(va), fb = bfround(vb);
                    *(uint32_t*)&ho [base] = packbf2(fa, fb);
                    *(uint32_t*)&lo_[base] = packbf2(va - fa, vb - fb);
                }
            }
        }
    }
}

// ---------------------------------------------------------------------------
// Small SGEMM (N=64 W_kr projection only)
// ---------------------------------------------------------------------------
#define GBM 64
#define GBN 64
#define GBK 16

__global__ __launch_bounds__(256)
void sgemm_bias(const float* __restrict__ A, int lda, int aoff,
                const float* __restrict__ W,
                const float* __restrict__ bias,
                float* __restrict__ Y, int ldy,
                int M, int N, int K)
{
    __shared__ float As[GBK][GBM];
    __shared__ float Bs[GBK][GBN];

    const int tid = threadIdx.x;
    const int brow = blockIdx.y * GBM;
    const int bcol = blockIdx.x * GBN;
    const int tr = (tid / 16) * 4;
    const int tc = (tid % 16) * 4;

    float acc[4][4];
#pragma unroll
    for (int i = 0; i < 4; i++)
#pragma unroll
        for (int j = 0; j < 4; j++) acc[i][j] = 0.f;

    for (int k0 = 0; k0 < K; k0 += GBK) {
#pragma unroll
        for (int it = 0; it < (GBM * GBK) / 256; it++) {
            int i = tid + it * 256;
            int m = i / GBK, kk = i % GBK;
            As[kk][m] = A[(size_t)(brow + m) * lda + aoff + k0 + kk];
        }
#pragma unroll
        for (int it = 0; it < (GBK * GBN) / 256; it++) {
            int i = tid + it * 256;
            int kk = i / GBN, n = i % GBN;
            Bs[kk][n] = W[(size_t)(k0 + kk) * N + bcol + n];
        }
        __syncthreads();

#pragma unroll
        for (int kk = 0; kk < GBK; kk++) {
            float a[4], b[4];
#pragma unroll
            for (int i = 0; i < 4; i++) a[i] = As[kk][tr + i];
#pragma unroll
            for (int j = 0; j < 4; j++) b[j] = Bs[kk][tc + j];
#pragma unroll
            for (int i = 0; i < 4; i++)
#pragma unroll
                for (int j = 0; j < 4; j++) acc[i][j] = fmaf(a[i], b[j], acc[i][j]);
        }
        __syncthreads();
    }

#pragma unroll
    for (int i = 0; i < 4; i++)
#pragma unroll
        for (int j = 0; j < 4; j++)
            Y[(size_t)(brow + tr + i) * ldy + bcol + tc + j] =
                acc[i][j] + bias[bcol + tc + j];
}

// ---------------------------------------------------------------------------
// Interleaved RoPE (double-precision trig)
// ---------------------------------------------------------------------------
__global__ void rope_kernel(float* __restrict__ buf, int rows, int c)
{
    const int pairs = c >> 1;
    const int idx = blockIdx.x * blockDim.x + threadIdx.x;
    if (idx >= rows * pairs) return;
    const int row = idx / pairs;
    const int i   = idx - row * pairs;
    const int t   = row & (TT - 1);

    float theta = (float)exp(-2.0 * (double)i / (double)c * log(10000.0));
    float angle = (float)(t + 1) * theta;
    double a = (double)angle;
    float cs = (float)cos(a);
    float sn = (float)sin(a);

    float* p = buf + (size_t)row * c + 2 * i;
    float x0 = p[0], x1 = p[1];
    p[0] = x0 * cs - x1 * sn;
    p[1] = x1 * cs + x0 * sn;
}

// ---------------------------------------------------------------------------
// Fill RoPE slices of attention buffers (d in [128,192))
// ---------------------------------------------------------------------------
__global__ void build_kr(const float* __restrict__ kr,
                         bf16* __restrict__ khi, bf16* __restrict__ klo)
{
    int idx = blockIdx.x * blockDim.x + threadIdx.x;
    if (idx >= BB * NHH * TT * 64) return;
    int d = idx & 63; int r = idx >> 6;
    int t = r % TT; int bh = r / TT; int b = bh >> 4;
    float v = kr[((size_t)(b * TT + t)) * 64 + d];
    size_t base = ((size_t)bh * TT + t) * 192 + 128 + d;
    float f = bfround(v);
    khi[base] = __float2bfloat16(f);
    klo[base] = __float2bfloat16(v - f);
}

__global__ void build_qr(const float* __restrict__ qr,
                         bf16* __restrict__ qhi, bf16* __restrict__ qlo)
{
    int idx = blockIdx.x * blockDim.x + threadIdx.x;
    if (idx >= BB * NHH * TT * 64) return;
    int d = idx & 63; int r = idx >> 6;
    int t = r % TT; int bh = r / TT; int h = bh & 15; int b = bh >> 4;
    float v = qr[((size_t)(b * TT + t)) * 1024 + h * 64 + d] * SCLQ;
    size_t base = ((size_t)bh * TT + t) * 192 + 128 + d;
    float f = bfround(v);
    qhi[base] = __float2bfloat16(f);
    qlo[base] = __float2bfloat16(v - f);
}

// ---------------------------------------------------------------------------
// Tensor-core flash attention, compensated bf16, double-buffered K/V.
// R12: pairwise-interleaved MMA issue (same per-acc order -> bit-identical).
// ---------------------------------------------------------------------------
#define QSTR 200
#define KSTR 200
#define VSTR 136
#define Q_ELEMS (128 * QSTR)
#define KST_ELEMS (64 * KSTR)
#define VST_ELEMS (64 * VSTR)
#define K_BASE Q_ELEMS
#define V_BASE (Q_ELEMS + 4 * KST_ELEMS)
#define ATTN_SMEM ((Q_ELEMS + 4 * KST_ELEMS + 4 * VST_ELEMS) * 2)

__global__ __launch_bounds__(256, 1)
void attn_tc(const bf16* __restrict__ qhi, const bf16* __restrict__ qlo,
             const bf16* __restrict__ khi, const bf16* __restrict__ klo,
             const bf16* __restrict__ vhi, const bf16* __restrict__ vlo,
             bf16* __restrict__ ohi, bf16* __restrict__ olo)
{
    extern __shared__ bf16 smA[];
    const uint32_t sQh = smem_u32(smA);
    const uint32_t sK  = sQh + K_BASE * 2;
    const uint32_t sV  = sQh + V_BASE * 2;

    const int tid = threadIdx.x, lane = tid & 31, wp = tid >> 5;
    const int bh = blockIdx.y;
    const int qi = gridDim.x - 1 - blockIdx.x;
    const int b = bh >> 4, h = bh & 15;
    const size_t base = (size_t)bh * TT;

    const int l16 = lane & 15, lhi = (lane >> 4) * 8;

    for (int i = tid; i < 128 * 24; i += 256) {
        int r = i / 24, c = (i % 24) * 8;
        size_t g = (base + (size_t)qi * 128 + r) * 192 + c;
        uint32_t d = (uint32_t)(r * QSTR + c) * 2;
        cp16(sQh + d, qhi + g);
        cp16(sK + d, qlo + g);
    }
    cp_commit();
    cp_wait<0>();
    __syncthreads();

    uint32_t qlof[12][4];
#pragma unroll
    for (int kk = 0; kk < 12; kk++) {
        uint32_t aaddr = (uint32_t)((wp * 16 + l16) * QSTR + kk * 16 + lhi) * 2;
        ldm_x4(qlof[kk], sK + aaddr);
    }
    __syncthreads();

    auto issueKV = [&](int st, int kt) {
        uint32_t kb = sK + (uint32_t)(st * 2 * KST_ELEMS) * 2;
        uint32_t vb = sV + (uint32_t)(st * 2 * VST_ELEMS) * 2;
        for (int i = tid; i < 64 * 24; i += 256) {
            int r = i / 24, c = (i % 24) * 8;
            size_t g = (base + (size_t)kt * 64 + r) * 192 + c;
            uint32_t d = (uint32_t)(r * KSTR + c) * 2;
            cp16(kb + d, khi + g);
            cp16(kb + (uint32_t)KST_ELEMS * 2 + d, klo + g);
        }
        for (int i = tid; i < 64 * 16; i += 256) {
            int r = i / 16, c = (i % 16) * 8;
            size_t g = (base + (size_t)kt * 64 + r) * 128 + c;
            uint32_t d = (uint32_t)(r * VSTR + c) * 2;
            cp16(vb + d, vhi + g);
            cp16(vb + (uint32_t)VST_ELEMS * 2 + d, vlo + g);
        }
        cp_commit();
    };

    float o[16][4];
#pragma unroll
    for (int i = 0; i < 16; i++)
#pragma unroll
        for (int f = 0; f < 4; f++) o[i][f] = 0.f;

    float m1 = -1e30f, m2 = -1e30f, l1 = 0.f, l2 = 0.f;
    const int qrow1 = qi * 128 + wp * 16 + (lane >> 2);
    const int qrow2 = qrow1 + 8;
    const int brofs = (lane & 7) + ((lane >> 4) & 1) * 8;
    const int bcofs = ((lane >> 3) & 1) * 8;

    const int nkt = 2 * qi + 2;
    issueKV(0, 0);

    for (int kt = 0; kt < nkt; kt++) {
        if (kt + 1 < nkt) {
            issueKV((kt + 1) & 1, kt + 1);
            cp_wait<1>();
        } else {
            cp_wait<0>();
        }
        __syncthreads();

        const int st = kt & 1;
        const uint32_t sKh = sK + (uint32_t)(st * 2 * KST_ELEMS) * 2;
        const uint32_t sKl = sKh + (uint32_t)KST_ELEMS * 2;
        const uint32_t sVh = sV + (uint32_t)(st * 2 * VST_ELEMS) * 2;
        const uint32_t sVl = sVh + (uint32_t)VST_ELEMS * 2;

        float s[8][4];
#pragma unroll
        for (int j = 0; j < 8; j++)
#pragma unroll
            for (int f = 0; f < 4; f++) s[j][f] = 0.f;

#pragma unroll
        for (int kk = 0; kk < 12; kk++) {
            uint32_t ah[4];
            uint32_t aaddr = (uint32_t)((wp * 16 + l16) * QSTR + kk * 16 + lhi) * 2;
            ldm_x4(ah, sQh + aaddr);
            const uint32_t* al = qlof[kk];
#pragma unroll
            for (int j2 = 0; j2 < 4; j2++) {
                uint32_t baddr = (uint32_t)((j2 * 16 + brofs) * KSTR + kk * 16 + bcofs) * 2;
                uint32_t tbv[4], tl[4];
                ldm_x4(tbv, sKh + baddr);
                ldm_x4(tl, sKl + baddr);
                // pairwise interleave (per-acc order hh, hl, lh preserved)
                mma_bf16(s[2 * j2],     ah, tbv);
                mma_bf16(s[2 * j2 + 1], ah, tbv + 2);
                mma_bf16(s[2 * j2],     ah, tl);
                mma_bf16(s[2 * j2 + 1], ah, tl + 2);
                mma_bf16(s[2 * j2],     al, tbv);
                mma_bf16(s[2 * j2 + 1], al, tbv + 2);
            }
        }

#pragma unroll
        for (int j = 0; j < 8; j++) {
            int k0 = kt * 64 + j * 8 + 2 * (lane & 3);
            if (k0     > qrow1) s[j][0] = -1e30f;
            if (k0 + 1 > qrow1) s[j][1] = -1e30f;
            if (k0     > qrow2) s[j][2] = -1e30f;
            if (k0 + 1 > qrow2) s[j][3] = -1e30f;
        }
        float mr1 = -1e30f, mr2 = -1e30f;
#pragma unroll
        for (int j = 0; j < 8; j++) {
            mr1 = fmaxf(mr1, fmaxf(s[j][0], s[j][1]));
            mr2 = fmaxf(mr2, fmaxf(s[j][2], s[j][3]));
        }
        mr1 = fmaxf(mr1, __shfl_xor_sync(0xffffffffu, mr1, 1));
        mr1 = fmaxf(mr1, __shfl_xor_sync(0xffffffffu, mr1, 2));
        mr2 = fmaxf(mr2, __shfl_xor_sync(0xffffffffu, mr2, 1));
        mr2 = fmaxf(mr2, __shfl_xor_sync(0xffffffffu, mr2, 2));
        float mn1 = fmaxf(m1, mr1), mn2 = fmaxf(m2, mr2);
        float a1 = ex2f(m1 - mn1), a2 = ex2f(m2 - mn2);
        m1 = mn1; m2 = mn2;

        uint32_t phx[8][2], plx[8][2];
        float rs1 = 0.f, rs2 = 0.f;
#pragma unroll
        for (int j = 0; j < 8; j++) {
            float p0 = ex2f(s[j][0] - mn1), p1 = ex2f(s[j][1] - mn1);
            float p2 = ex2f(s[j][2] - mn2), p3 = ex2f(s[j][3] - mn2);
            rs1 += p0 + p1; rs2 += p2 + p3;
            phx[j][0] = packbf2(p0, p1);
            phx[j][1] = packbf2(p2, p3);
            float q0 = p0 - bfround(p0);
            float q1 = p1 - bfround(p1);
            float q2 = p2 - bfround(p2);
            float q3 = p3 - bfround(p3);
            plx[j][0] = packbf2(q0, q1);
            plx[j][1] = packbf2(q2, q3);
        }
        rs1 += __shfl_xor_sync(0xffffffffu, rs1, 1);
        rs1 += __shfl_xor_sync(0xffffffffu, rs1, 2);
        rs2 += __shfl_xor_sync(0xffffffffu, rs2, 1);
        rs2 += __shfl_xor_sync(0xffffffffu, rs2, 2);
        l1 = l1 * a1 + rs1;
        l2 = l2 * a2 + rs2;
#pragma unroll
        for (int t16 = 0; t16 < 16; t16++) {
            o[t16][0] *= a1; o[t16][1] *= a1;
            o[t16][2] *= a2; o[t16][3] *= a2;
        }

#pragma unroll
        for (int kt2 = 0; kt2 < 4; kt2++) {
            uint32_t pa_h[4] = {phx[2 * kt2][0], phx[2 * kt2][1],
                                phx[2 * kt2 + 1][0], phx[2 * kt2 + 1][1]};
            uint32_t pa_l[4] = {plx[2 * kt2][0], plx[2 * kt2][1],
                                plx[2 * kt2 + 1][0], plx[2 * kt2 + 1][1]};
            uint32_t vrow = (uint32_t)((kt2 * 16 + l16) * VSTR) * 2;
#pragma unroll
            for (int j2 = 0; j2 < 8; j2++) {
                uint32_t vaddr = vrow + (uint32_t)(j2 * 16 + lhi) * 2;
                uint32_t tv[4], tw[4];
                ldm_x4t(tv, sVh + vaddr);
                ldm_x4t(tw, sVl + vaddr);
                // pairwise interleave (per-acc order preserved)
                mma_bf16(o[2 * j2],     pa_h, tv);
                mma_bf16(o[2 * j2 + 1], pa_h, tv + 2);
                mma_bf16(o[2 * j2],     pa_h, tw);
                mma_bf16(o[2 * j2 + 1], pa_h, tw + 2);
                mma_bf16(o[2 * j2],     pa_l, tv);
                mma_bf16(o[2 * j2 + 1], pa_l, tv + 2);
            }
        }
        __syncthreads();
    }

    float inv1 = 1.f / l1, inv2 = 1.f / l2;
    size_t row1 = (size_t)(b * TT + qrow1) * 2048 + h * 128;
    size_t row2 = (size_t)(b * TT + qrow2) * 2048 + h * 128;
#pragma unroll
    for (int t16 = 0; t16 < 16; t16++) {
        int col = t16 * 8 + 2 * (lane & 3);
        float v0 = o[t16][0] * inv1, v1 = o[t16][1] * inv1;
        float v2 = o[t16][2] * inv2, v3 = o[t16][3] * inv2;
        float f0 = bfround(v0), f1 = bfround(v1);
        float f2 = bfround(v2), f3 = bfround(v3);
        *(uint32_t*)&ohi[row1 + col] = packbf2(f0, f1);
        *(uint32_t*)&olo[row1 + col] = packbf2(v0 - f0, v1 - f1);
        *(uint32_t*)&ohi[row2 + col] = packbf2(f2, f3);
        *(uint32_t*)&olo[row2 + col] = packbf2(v2 - f2, v3 - f3);
    }
}

// ---------------------------------------------------------------------------
// Host launcher
// ---------------------------------------------------------------------------
extern "C" void kernel_launch(void* const* d_in, const int* in_sizes, int n_in,
                              void* d_out, int out_size)
{
    (void)in_sizes; (void)n_in; (void)out_size;

    const float* x     = (const float*)d_in[0];
    const float* W_dkv = (const float*)d_in[1];
    const float* b_dkv = (const float*)d_in[2];
    const float* W_kr  = (const float*)d_in[3];
    const float* b_kr  = (const float*)d_in[4];
    const float* W_qr  = (const float*)d_in[5];
    const float* b_qr  = (const float*)d_in[6];
    const float* W_uv  = (const float*)d_in[7];
    const float* b_uv  = (const float*)d_in[8];
    const float* W_uq  = (const float*)d_in[9];
    const float* b_uq  = (const float*)d_in[10];
    const float* W_o   = (const float*)d_in[11];
    const float* b_o   = (const float*)d_in[12];
    float* out = (float*)d_out;

    float *h, *kr, *qr;
    bf16 *xhi, *xlo, *hhi, *hlo, *athi, *atlo;
    bf16 *wdkvh, *wdkvl, *wqrh, *wqrl, *wuvh, *wuvl, *wuqh, *wuql, *woh, *wol;
    bf16 *qhi, *qlo, *khi, *klo, *vhi, *vlo;
    cudaGetSymbolAddress((void**)&h,    g_h);
    cudaGetSymbolAddress((void**)&kr,   g_kr);
    cudaGetSymbolAddress((void**)&qr,   g_qr);
    cudaGetSymbolAddress((void**)&xhi,  g_xhi);
    cudaGetSymbolAddress((void**)&xlo,  g_xlo);
    cudaGetSymbolAddress((void**)&hhi,  g_hhi);
    cudaGetSymbolAddress((void**)&hlo,  g_hlo);
    cudaGetSymbolAddress((void**)&athi, g_athi);
    cudaGetSymbolAddress((void**)&atlo, g_atlo);
    cudaGetSymbolAddress((void**)&wdkvh, g_wdkvh);
    cudaGetSymbolAddress((void**)&wdkvl, g_wdkvl);
    cudaGetSymbolAddress((void**)&wqrh, g_wqrh);
    cudaGetSymbolAddress((void**)&wqrl, g_wqrl);
    cudaGetSymbolAddress((void**)&wuvh, g_wuvh);
    cudaGetSymbolAddress((void**)&wuvl, g_wuvl);
    cudaGetSymbolAddress((void**)&wuqh, g_wuqh);
    cudaGetSymbolAddress((void**)&wuql, g_wuql);
    cudaGetSymbolAddress((void**)&woh,  g_woh);
    cudaGetSymbolAddress((void**)&wol,  g_wol);
    cudaGetSymbolAddress((void**)&qhi, g_qhi);
    cudaGetSymbolAddress((void**)&qlo, g_qlo);
    cudaGetSymbolAddress((void**)&khi, g_khi);
    cudaGetSymbolAddress((void**)&klo, g_klo);
    cudaGetSymbolAddress((void**)&vhi, g_vhi);
    cudaGetSymbolAddress((void**)&vlo, g_vlo);

    const int M = MROWS;  // 4096

    cudaFuncSetAttribute(gemm_mma, cudaFuncAttributeMaxDynamicSharedMemorySize, GSMEM);
    cudaFuncSetAttribute(attn_tc, cudaFuncAttributeMaxDynamicSharedMemorySize, ATTN_SMEM);

    // 1) x -> hi/lo
    split_act<<<(M * 512 + 255) / 256, 256>>>(x, 2048, 0, 2048, xhi, xlo);
    // 2) W_dkv
    wsplit_t<<<dim3(1024 / 32, 2048 / 32), 256>>>(W_dkv, 2048, 1024, wdkvh, wdkvl);
    // 3) W_o
    wsplit_t<<<dim3(2048 / 32, 2048 / 32), 256>>>(W_o, 2048, 2048, woh, wol);
    // 4) h = x @ W_dkv + b_dkv  (mode 1)   <-- profiled launch
    gemm_mma<<<dim3(8, 32), 128, GSMEM>>>(xhi, xlo, 2048, 0, wdkvh, wdkvl, 2048,
                                          b_dkv, h, 1024, 2048, hhi, hlo, 0, 0, 1);
    // 5) kr projection
    sgemm_bias<<<dim3(1, 64), 256>>>(h, 1024, 0, W_kr, b_kr, kr, 64, M, 64, 1024);
    // 6) W_qr
    wsplit_t<<<dim3(1024 / 32, 1024 / 32), 256>>>(W_qr, 1024, 1024, wqrh, wqrl);
    // 7) qr = h @ W_qr (mode 0)
    gemm_mma<<<dim3(8, 32), 128, GSMEM>>>(hhi, hlo, 1024, 0, wqrh, wqrl, 1024,
                                          b_qr, qr, 1024, 1024, 0, 0, 0, 0, 0);
    // 8,9) RoPE
    rope_kernel<<<(M * 32 + 255) / 256, 256>>>(kr, M, 64);
    rope_kernel<<<(M * 512 + 255) / 256, 256>>>(qr, M, 1024);
    // 10,11) W_uv, W_uq
    wsplit_t<<<dim3(4096 / 32, 512 / 32), 256>>>(W_uv, 512, 4096, wuvh, wuvl);
    wsplit_t<<<dim3(2048 / 32, 512 / 32), 256>>>(W_uq, 512, 2048, wuqh, wuql);
    // 12) kv GEMM (mode 2)
    gemm_mma<<<dim3(32, 32), 128, GSMEM>>>(hhi, hlo, 1024, 0, wuvh, wuvl, 512,
                                           b_uv, 0, 0, 512, khi, klo, vhi, vlo, 2);
    // 13) q GEMM (mode 3)
    gemm_mma<<<dim3(16, 32), 128, GSMEM>>>(hhi, hlo, 1024, 512, wuqh, wuql, 512,
                                           b_uq, 0, 0, 512, qhi, qlo, 0, 0, 3);
    // 14,15) RoPE slices
    build_kr<<<(BB * NHH * TT * 64 + 255) / 256, 256>>>(kr, khi, klo);
    build_qr<<<(BB * NHH * TT * 64 + 255) / 256, 256>>>(qr, qhi, qlo);
    // 16) attention -> athi/atlo
    attn_tc<<<dim3(TT / 128, BB * NHH), 256, ATTN_SMEM>>>(qhi, qlo, khi, klo,
                                                          vhi, vlo, athi, atlo);
    // 17) out = attn @ W_o + b_o (mode 0)
    gemm_mma<<<dim3(16, 32), 128, GSMEM>>>(athi, atlo, 2048, 0, woh, wol, 2048,
                                           b_o, out, 2048, 2048, 0, 0, 0, 0, 0);
}

// round 13
// speedup vs baseline: 2.3843x; 1.0242x over previous
#include <cuda_runtime.h>
#include <cuda_bf16.h>
#include <math.h>
#include <stdint.h>

// Problem constants
#define BB   2
#define TT   2048
#define CC   2048
#define NHH  16
#define DKK  128
#define LATT 512
#define DHRR 64
#define MROWS (BB * TT)   // 4096

typedef __nv_bfloat16 bf16;

// ---------------------------------------------------------------------------
// Scratch (static device globals -- no allocation allowed)
// ---------------------------------------------------------------------------
__device__ float g_h   [(size_t)MROWS * 1024];
__device__ float g_kr  [(size_t)MROWS * 64];
__device__ float g_qr  [(size_t)MROWS * 1024];

__device__ bf16 g_xhi [(size_t)MROWS * 2048];
__device__ bf16 g_xlo [(size_t)MROWS * 2048];
__device__ bf16 g_hhi [(size_t)MROWS * 1024];
__device__ bf16 g_hlo [(size_t)MROWS * 1024];
__device__ bf16 g_athi[(size_t)MROWS * 2048];
__device__ bf16 g_atlo[(size_t)MROWS * 2048];

__device__ bf16 g_wdkvh[(size_t)1024 * 2048];
__device__ bf16 g_wdkvl[(size_t)1024 * 2048];
__device__ bf16 g_wqrh [(size_t)1024 * 1024];
__device__ bf16 g_wqrl [(size_t)1024 * 1024];
__device__ bf16 g_wuvh [(size_t)4096 * 512];
__device__ bf16 g_wuvl [(size_t)4096 * 512];
__device__ bf16 g_wuqh [(size_t)2048 * 512];
__device__ bf16 g_wuql [(size_t)2048 * 512];
__device__ bf16 g_woh  [(size_t)2048 * 2048];
__device__ bf16 g_wol  [(size_t)2048 * 2048];

__device__ bf16 g_qhi[(size_t)BB * NHH * TT * 192];
__device__ bf16 g_qlo[(size_t)BB * NHH * TT * 192];
__device__ bf16 g_khi[(size_t)BB * NHH * TT * 192];
__device__ bf16 g_klo[(size_t)BB * NHH * TT * 192];
__device__ bf16 g_vhi[(size_t)BB * NHH * TT * 128];
__device__ bf16 g_vlo[(size_t)BB * NHH * TT * 128];

#define SCLQ 0.12754984837627695f   // 1/sqrt(128) * log2(e)

// ---------------------------------------------------------------------------
// PTX helpers
// ---------------------------------------------------------------------------
__device__ __forceinline__ uint32_t smem_u32(const void* p)
{ return (uint32_t)__cvta_generic_to_shared(p); }

__device__ __forceinline__ void cp16(uint32_t dst, const void* src)
{ asm volatile("cp.async.cg.shared.global [%0], [%1], 16;\n" :: "r"(dst), "l"(src)); }

__device__ __forceinline__ void cp_commit()
{ asm volatile("cp.async.commit_group;\n"); }

template <int N>
__device__ __forceinline__ void cp_wait()
{ asm volatile("cp.async.wait_group %0;\n" :: "n"(N)); }

__device__ __forceinline__ void ldm_x4(uint32_t* r, uint32_t addr)
{
    asm volatile("ldmatrix.sync.aligned.m8n8.x4.shared.b16 {%0,%1,%2,%3}, [%4];\n"
        : "=r"(r[0]), "=r"(r[1]), "=r"(r[2]), "=r"(r[3]) : "r"(addr));
}
__device__ __forceinline__ void ldm_x4t(uint32_t* r, uint32_t addr)
{
    asm volatile("ldmatrix.sync.aligned.m8n8.x4.trans.shared.b16 {%0,%1,%2,%3}, [%4];\n"
        : "=r"(r[0]), "=r"(r[1]), "=r"(r[2]), "=r"(r[3]) : "r"(addr));
}
__device__ __forceinline__ void mma_bf16(float* d, const uint32_t* a, const uint32_t* b)
{
    asm volatile(
        "mma.sync.aligned.m16n8k16.row.col.f32.bf16.bf16.f32 "
        "{%0,%1,%2,%3}, {%4,%5,%6,%7}, {%8,%9}, {%0,%1,%2,%3};\n"
        : "+f"(d[0]), "+f"(d[1]), "+f"(d[2]), "+f"(d[3])
        : "r"(a[0]), "r"(a[1]), "r"(a[2]), "r"(a[3]), "r"(b[0]), "r"(b[1]));
}
__device__ __forceinline__ float ex2f(float x)
{ float y; asm("ex2.approx.f32 %0, %1;" : "=f"(y) : "f"(x)); return y; }

__device__ __forceinline__ uint32_t packbf2(float lo, float hi)
{ uint32_t d; asm("cvt.rn.bf16x2.f32 %0, %1, %2;" : "=r"(d) : "f"(hi), "f"(lo)); return d; }

__device__ __forceinline__ float bfround(float v)
{ return __bfloat162float(__float2bfloat16(v)); }

// ---------------------------------------------------------------------------
// prep_all: one launch = split_act(x) + 5 weight transpose/splits.
// blocks [0,8192): x split; then W_dkv(2048), W_o(4096), W_qr(1024),
// W_uv(2048), W_uq(1024) 32x32 transpose tiles.
// ---------------------------------------------------------------------------
__global__ __launch_bounds__(256)
void prep_all(const float* __restrict__ x,
              const float* __restrict__ Wdkv, const float* __restrict__ Wo,
              const float* __restrict__ Wqr,  const float* __restrict__ Wuv,
              const float* __restrict__ Wuq,
              bf16* __restrict__ xhi, bf16* __restrict__ xlo,
              bf16* __restrict__ wdkvh, bf16* __restrict__ wdkvl,
              bf16* __restrict__ woh,  bf16* __restrict__ wol,
              bf16* __restrict__ wqrh, bf16* __restrict__ wqrl,
              bf16* __restrict__ wuvh, bf16* __restrict__ wuvl,
              bf16* __restrict__ wuqh, bf16* __restrict__ wuql)
{
    __shared__ float ts[32][33];
    const int bid = blockIdx.x, tid = threadIdx.x;

    if (bid < 8192) {
        // x -> hi/lo (float4 per thread)
        int idx = bid * 256 + tid;                 // over 4096 * 512
        int m = idx >> 9, k4 = (idx & 511) * 4;
        float4 v = *(const float4*)&x[(size_t)m * 2048 + k4];
        float h0 = bfround(v.x), h1 = bfround(v.y);
        float h2 = bfround(v.z), h3 = bfround(v.w);
        uint2 ph, pl;
        ph.x = packbf2(h0, h1); ph.y = packbf2(h2, h3);
        pl.x = packbf2(v.x - h0, v.y - h1); pl.y = packbf2(v.z - h2, v.w - h3);
        *(uint2*)&xhi[(size_t)m * 2048 + k4] = ph;
        *(uint2*)&xlo[(size_t)m * 2048 + k4] = pl;
        return;
    }

    const float* W; bf16 *hiT, *loT; int K, N, tl;
    if (bid < 10240)      { W = Wdkv; hiT = wdkvh; loT = wdkvl; K = 2048; N = 1024; tl = bid - 8192; }
    else if (bid < 14336) { W = Wo;   hiT = woh;   loT = wol;   K = 2048; N = 2048; tl = bid - 10240; }
    else if (bid < 15360) { W = Wqr;  hiT = wqrh;  loT = wqrl;  K = 1024; N = 1024; tl = bid - 14336; }
    else if (bid < 17408) { W = Wuv;  hiT = wuvh;  loT = wuvl;  K = 512;  N = 4096; tl = bid - 15360; }
    else                  { W = Wuq;  hiT = wuqh;  loT = wuql;  K = 512;  N = 2048; tl = bid - 17408; }

    int ntx = N / 32;
    int n0 = (tl % ntx) * 32, k0 = (tl / ntx) * 32;
    int tx = tid & 31, ty = tid >> 5;
#pragma unroll
    for (int r = 0; r < 4; r++)
        ts[ty + 8 * r][tx] = W[(size_t)(k0 + ty + 8 * r) * N + n0 + tx];
    __syncthreads();
#pragma unroll
    for (int r = 0; r < 4; r++) {
        float v = ts[tx][ty + 8 * r];
        bf16 h = __float2bfloat16(v);
        size_t o = (size_t)(n0 + ty + 8 * r) * K + k0 + tx;
        hiT[o] = h;
        loT[o] = __float2bfloat16(v - __bfloat162float(h));
    }
}

// ---------------------------------------------------------------------------
// Fused rope + hi/lo split + per-head scatter
// ---------------------------------------------------------------------------
__global__ void rope_split_qr(const float* __restrict__ qr,
                              bf16* __restrict__ qhi, bf16* __restrict__ qlo)
{
    int idx = blockIdx.x * blockDim.x + threadIdx.x;     // over 4096*512 pairs
    if (idx >= MROWS * 512) return;
    int row = idx >> 9, i = idx & 511;
    int t = row & 2047, b = row >> 11;
    float theta = (float)exp(-2.0 * (double)i / 1024.0 * log(10000.0));
    float angle = (float)(t + 1) * theta;
    double a = (double)angle;
    float cs = (float)cos(a), sn = (float)sin(a);
    const float* p = qr + (size_t)row * 1024 + 2 * i;
    float x0 = p[0], x1 = p[1];
    float p0 = (x0 * cs - x1 * sn) * SCLQ;
    float p1 = (x1 * cs + x0 * sn) * SCLQ;
    int h = (2 * i) >> 6, d = (2 * i) & 63;
    size_t base = ((size_t)((b * NHH + h) * TT) + t) * 192 + 128 + d;
    float f0 = bfround(p0), f1 = bfround(p1);
    *(uint32_t*)&qhi[base] = packbf2(f0, f1);
    *(uint32_t*)&qlo[base] = packbf2(p0 - f0, p1 - f1);
}

__global__ void rope_split_kr(const float* __restrict__ kr,
                              bf16* __restrict__ khi, bf16* __restrict__ klo)
{
    int idx = blockIdx.x * blockDim.x + threadIdx.x;     // over 4096*32 pairs
    if (idx >= MROWS * 32) return;
    int row = idx >> 5, i = idx & 31;
    int t = row & 2047, b = row >> 11;
    float theta = (float)exp(-2.0 * (double)i / 64.0 * log(10000.0));
    float angle = (float)(t + 1) * theta;
    double a = (double)angle;
    float cs = (float)cos(a), sn = (float)sin(a);
    const float* p = kr + (size_t)row * 64 + 2 * i;
    float x0 = p[0], x1 = p[1];
    float p0 = x0 * cs - x1 * sn;
    float p1 = x1 * cs + x0 * sn;
    float f0 = bfround(p0), f1 = bfround(p1);
    uint32_t ph = packbf2(f0, f1), pl = packbf2(p0 - f0, p1 - f1);
#pragma unroll
    for (int hh = 0; hh < NHH; hh++) {
        size_t base = ((size_t)((b * NHH + hh) * TT) + t) * 192 + 128 + 2 * i;
        *(uint32_t*)&khi[base] = ph;
        *(uint32_t*)&klo[base] = pl;
    }
}

// ---------------------------------------------------------------------------
// HMMA GEMM, compensated hi/lo, fused epilogues (unchanged from R12)
// ---------------------------------------------------------------------------
#define TST 40
#define A_ELE (128 * TST)
#define B_ELE (128 * TST)
#define STG_ELE (2 * A_ELE + 2 * B_ELE)
#define GSMEM (2 * STG_ELE * 2)

__global__ __launch_bounds__(128, 2)
void gemm_mma(const bf16* __restrict__ Ahi, const bf16* __restrict__ Alo,
              int lda, int aoff,
              const bf16* __restrict__ Bhi, const bf16* __restrict__ Blo,
              int ldb,
              const float* __restrict__ bias,
              float* __restrict__ Y, int ldy, int K,
              bf16* __restrict__ ho, bf16* __restrict__ lo_,
              bf16* __restrict__ ho2, bf16* __restrict__ lo2, int mode)
{
    extern __shared__ bf16 dsm[];
    const uint32_t sb0 = smem_u32(dsm);

    const int tid = threadIdx.x, lane = tid & 31, wid = tid >> 5;
    const int brow = blockIdx.y * 128, bcol = blockIdx.x * 128;
    const int wm = (wid >> 1) * 64, wn = (wid & 1) * 64;

    auto issue = [&](int st, int kt) {
        uint32_t s = sb0 + (uint32_t)(st * STG_ELE) * 2;
        int ke = kt * 32;
#pragma unroll
        for (int i = 0; i < 4; i++) {
            int c = tid + i * 128;
            int r = c >> 2, sg = (c & 3) * 8;
            uint32_t d = (uint32_t)(r * TST + sg) * 2;
            cp16(s + d, Ahi + (size_t)(brow + r) * lda + aoff + ke + sg);
            cp16(s + (uint32_t)A_ELE * 2 + d,
                 Alo + (size_t)(brow + r) * lda + aoff + ke + sg);
            cp16(s + (uint32_t)(2 * A_ELE) * 2 + d,
                 Bhi + (size_t)(bcol + r) * ldb + ke + sg);
            cp16(s + (uint32_t)(2 * A_ELE + B_ELE) * 2 + d,
                 Blo + (size_t)(bcol + r) * ldb + ke + sg);
        }
        cp_commit();
    };

    float acc[4][8][4];
#pragma unroll
    for (int i = 0; i < 4; i++)
#pragma unroll
        for (int j = 0; j < 8; j++)
#pragma unroll
            for (int f = 0; f < 4; f++) acc[i][j][f] = 0.f;

    const int ntiles = K / 32;
    issue(0, 0);
    issue(1, 1);

    const int l16 = lane & 15, lhi = (lane >> 4) * 8;
    const int brofs = (lane & 7) + ((lane >> 4) & 1) * 8;
    const int bcofs = ((lane >> 3) & 1) * 8;

    for (int kt = 0; kt < ntiles; kt++) {
        if (kt + 1 < ntiles) { cp_wait<1>(); } else { cp_wait<0>(); }
        __syncthreads();
        int cur = kt & 1;
        uint32_t s = sb0 + (uint32_t)(cur * STG_ELE) * 2;
        uint32_t sAh = s, sAl = s + (uint32_t)A_ELE * 2;
        uint32_t sBh = s + (uint32_t)(2 * A_ELE) * 2;
        uint32_t sBl = sBh + (uint32_t)B_ELE * 2;

#pragma unroll
        for (int kk = 0; kk < 32; kk += 16) {
            uint32_t bh[4][4], bl[4][4];
#pragma unroll
            for (int j2 = 0; j2 < 4; j2++) {
                uint32_t baddr =
                    (uint32_t)((wn + j2 * 16 + brofs) * TST + kk + bcofs) * 2;
                ldm_x4(bh[j2], sBh + baddr);
                ldm_x4(bl[j2], sBl + baddr);
            }
#pragma unroll
            for (int i = 0; i < 4; i++) {
                uint32_t ah[4], al[4];
                uint32_t aaddr = (uint32_t)((wm + i * 16 + l16) * TST + kk + lhi) * 2;
                ldm_x4(ah, sAh + aaddr);
                ldm_x4(al, sAl + aaddr);
#pragma unroll
                for (int j2 = 0; j2 < 4; j2++) {
                    mma_bf16(acc[i][2 * j2],     ah, bh[j2]);
                    mma_bf16(acc[i][2 * j2 + 1], ah, bh[j2] + 2);
                }
#pragma unroll
                for (int j2 = 0; j2 < 4; j2++) {
                    mma_bf16(acc[i][2 * j2],     ah, bl[j2]);
                    mma_bf16(acc[i][2 * j2 + 1], ah, bl[j2] + 2);
                }
#pragma unroll
                for (int j2 = 0; j2 < 4; j2++) {
                    mma_bf16(acc[i][2 * j2],     al, bh[j2]);
                    mma_bf16(acc[i][2 * j2 + 1], al, bh[j2] + 2);
                }
            }
        }
        __syncthreads();
        if (kt + 2 < ntiles) issue(cur, kt + 2);
    }

#pragma unroll
    for (int i = 0; i < 4; i++) {
#pragma unroll
        for (int j = 0; j < 8; j++) {
            int r0 = brow + wm + i * 16 + (lane >> 2);
            int c0 = bcol + wn + j * 8 + (lane & 3) * 2;
            float b0 = bias[c0], b1 = bias[c0 + 1];
            float v00 = acc[i][j][0] + b0, v01 = acc[i][j][1] + b1;
            float v10 = acc[i][j][2] + b0, v11 = acc[i][j][3] + b1;

            if (mode <= 1) {
                *(float2*)&Y[(size_t)r0 * ldy + c0]       = make_float2(v00, v01);
                *(float2*)&Y[(size_t)(r0 + 8) * ldy + c0] = make_float2(v10, v11);
            }
            if (mode == 1) {
                float f00 = bfround(v00), f01 = bfround(v01);
                float f10 = bfround(v10), f11 = bfround(v11);
                *(uint32_t*)&ho [(size_t)r0 * ldy + c0]       = packbf2(f00, f01);
                *(uint32_t*)&lo_[(size_t)r0 * ldy + c0]       = packbf2(v00 - f00, v01 - f01);
                *(uint32_t*)&ho [(size_t)(r0 + 8) * ldy + c0] = packbf2(f10, f11);
                *(uint32_t*)&lo_[(size_t)(r0 + 8) * ldy + c0] = packbf2(v10 - f10, v11 - f11);
            } else if (mode == 2) {
#pragma unroll
                for (int rr = 0; rr < 2; rr++) {
                    int r = r0 + rr * 8;
                    float va = rr ? v10 : v00, vb = rr ? v11 : v01;
                    int b = r >> 11, t = r & 2047;
                    float fa = bfround(va), fb = bfround(vb);
                    if (c0 < 2048) {
                        int hh = c0 >> 7, d = c0 & 127;
                        size_t base = ((size_t)(b * NHH + hh) * TT + t) * 192 + d;
                        *(uint32_t*)&ho [base] = packbf2(fa, fb);
                        *(uint32_t*)&lo_[base] = packbf2(va - fa, vb - fb);
                    } else {
                        int c2 = c0 - 2048;
                        int hh = c2 >> 7, d = c2 & 127;
                        size_t base = ((size_t)(b * NHH + hh) * TT + t) * 128 + d;
                        *(uint32_t*)&ho2[base] = packbf2(fa, fb);
                        *(uint32_t*)&lo2[base] = packbf2(va - fa, vb - fb);
                    }
                }
            } else if (mode == 3) {
#pragma unroll
                for (int rr = 0; rr < 2; rr++) {
                    int r = r0 + rr * 8;
                    float va = (rr ? v10 : v00) * SCLQ, vb = (rr ? v11 : v01) * SCLQ;
                    int b = r >> 11, t = r & 2047;
                    int hh = c0 >> 7, d = c0 & 127;
                    size_t base = ((size_t)(b * NHH + hh) * TT + t) * 192 + d;
                    float fa = bfround(va), fb = bfround(vb);
                    *(uint32_t*)&ho [base] = packbf2(fa, fb);
                    *(uint32_t*)&lo_[base] = packbf2(va - fa, vb - fb);
                }
            }
        }
    }
}

// ---------------------------------------------------------------------------
// Small SGEMM (N=64 W_kr projection only)
// ---------------------------------------------------------------------------
#define GBM 64
#define GBN 64
#define GBK 16

__global__ __launch_bounds__(256)
void sgemm_bias(const float* __restrict__ A, int lda, int aoff,
                const float* __restrict__ W,
                const float* __restrict__ bias,
                float* __restrict__ Y, int ldy,
                int M, int N, int K)
{
    __shared__ float As[GBK][GBM];
    __shared__ float Bs[GBK][GBN];

    const int tid = threadIdx.x;
    const int brow = blockIdx.y * GBM;
    const int bcol = blockIdx.x * GBN;
    const int tr = (tid / 16) * 4;
    const int tc = (tid % 16) * 4;

    float acc[4][4];
#pragma unroll
    for (int i = 0; i < 4; i++)
#pragma unroll
        for (int j = 0; j < 4; j++) acc[i][j] = 0.f;

    for (int k0 = 0; k0 < K; k0 += GBK) {
#pragma unroll
        for (int it = 0; it < (GBM * GBK) / 256; it++) {
            int i = tid + it * 256;
            int m = i / GBK, kk = i % GBK;
            As[kk][m] = A[(size_t)(brow + m) * lda + aoff + k0 + kk];
        }
#pragma unroll
        for (int it = 0; it < (GBK * GBN) / 256; it++) {
            int i = tid + it * 256;
            int kk = i / GBN, n = i % GBN;
            Bs[kk][n] = W[(size_t)(k0 + kk) * N + bcol + n];
        }
        __syncthreads();

#pragma unroll
        for (int kk = 0; kk < GBK; kk++) {
            float a[4], b[4];
#pragma unroll
            for (int i = 0; i < 4; i++) a[i] = As[kk][tr + i];
#pragma unroll
            for (int j = 0; j < 4; j++) b[j] = Bs[kk][tc + j];
#pragma unroll
            for (int i = 0; i < 4; i++)
#pragma unroll
                for (int j = 0; j < 4; j++) acc[i][j] = fmaf(a[i], b[j], acc[i][j]);
        }
        __syncthreads();
    }

#pragma unroll
    for (int i = 0; i < 4; i++)
#pragma unroll
        for (int j = 0; j < 4; j++)
            Y[(size_t)(brow + tr + i) * ldy + bcol + tc + j] =
                acc[i][j] + bias[bcol + tc + j];
}

// ---------------------------------------------------------------------------
// Tensor-core flash attention (unchanged from R12)
// ---------------------------------------------------------------------------
#define QSTR 200
#define KSTR 200
#define VSTR 136
#define Q_ELEMS (128 * QSTR)
#define KST_ELEMS (64 * KSTR)
#define VST_ELEMS (64 * VSTR)
#define K_BASE Q_ELEMS
#define V_BASE (Q_ELEMS + 4 * KST_ELEMS)
#define ATTN_SMEM ((Q_ELEMS + 4 * KST_ELEMS + 4 * VST_ELEMS) * 2)

__global__ __launch_bounds__(256, 1)
void attn_tc(const bf16* __restrict__ qhi, const bf16* __restrict__ qlo,
             const bf16* __restrict__ khi, const bf16* __restrict__ klo,
             const bf16* __restrict__ vhi, const bf16* __restrict__ vlo,
             bf16* __restrict__ ohi, bf16* __restrict__ olo)
{
    extern __shared__ bf16 smA[];
    const uint32_t sQh = smem_u32(smA);
    const uint32_t sK  = sQh + K_BASE * 2;
    const uint32_t sV  = sQh + V_BASE * 2;

    const int tid = threadIdx.x, lane = tid & 31, wp = tid >> 5;
    const int bh = blockIdx.y;
    const int qi = gridDim.x - 1 - blockIdx.x;
    const int b = bh >> 4, h = bh & 15;
    const size_t base = (size_t)bh * TT;

    const int l16 = lane & 15, lhi = (lane >> 4) * 8;

    for (int i = tid; i < 128 * 24; i += 256) {
        int r = i / 24, c = (i % 24) * 8;
        size_t g = (base + (size_t)qi * 128 + r) * 192 + c;
        uint32_t d = (uint32_t)(r * QSTR + c) * 2;
        cp16(sQh + d, qhi + g);
        cp16(sK + d, qlo + g);
    }
    cp_commit();
    cp_wait<0>();
    __syncthreads();

    uint32_t qlof[12][4];
#pragma unroll
    for (int kk = 0; kk < 12; kk++) {
        uint32_t aaddr = (uint32_t)((wp * 16 + l16) * QSTR + kk * 16 + lhi) * 2;
        ldm_x4(qlof[kk], sK + aaddr);
    }
    __syncthreads();

    auto issueKV = [&](int st, int kt) {
        uint32_t kb = sK + (uint32_t)(st * 2 * KST_ELEMS) * 2;
        uint32_t vb = sV + (uint32_t)(st * 2 * VST_ELEMS) * 2;
        for (int i = tid; i < 64 * 24; i += 256) {
            int r = i / 24, c = (i % 24) * 8;
            size_t g = (base + (size_t)kt * 64 + r) * 192 + c;
            uint32_t d = (uint32_t)(r * KSTR + c) * 2;
            cp16(kb + d, khi + g);
            cp16(kb + (uint32_t)KST_ELEMS * 2 + d, klo + g);
        }
        for (int i = tid; i < 64 * 16; i += 256) {
            int r = i / 16, c = (i % 16) * 8;
            size_t g = (base + (size_t)kt * 64 + r) * 128 + c;
            uint32_t d = (uint32_t)(r * VSTR + c) * 2;
            cp16(vb + d, vhi + g);
            cp16(vb + (uint32_t)VST_ELEMS * 2 + d, vlo + g);
        }
        cp_commit();
    };

    float o[16][4];
#pragma unroll
    for (int i = 0; i < 16; i++)
#pragma unroll
        for (int f = 0; f < 4; f++) o[i][f] = 0.f;

    float m1 = -1e30f, m2 = -1e30f, l1 = 0.f, l2 = 0.f;
    const int qrow1 = qi * 128 + wp * 16 + (lane >> 2);
    const int qrow2 = qrow1 + 8;
    const int brofs = (lane & 7) + ((lane >> 4) & 1) * 8;
    const int bcofs = ((lane >> 3) & 1) * 8;

    const int nkt = 2 * qi + 2;
    issueKV(0, 0);

    for (int kt = 0; kt < nkt; kt++) {
        if (kt + 1 < nkt) {
            issueKV((kt + 1) & 1, kt + 1);
            cp_wait<1>();
        } else {
            cp_wait<0>();
        }
        __syncthreads();

        const int st = kt & 1;
        const uint32_t sKh = sK + (uint32_t)(st * 2 * KST_ELEMS) * 2;
        const uint32_t sKl = sKh + (uint32_t)KST_ELEMS * 2;
        const uint32_t sVh = sV + (uint32_t)(st * 2 * VST_ELEMS) * 2;
        const uint32_t sVl = sVh + (uint32_t)VST_ELEMS * 2;

        float s[8][4];
#pragma unroll
        for (int j = 0; j < 8; j++)
#pragma unroll
            for (int f = 0; f < 4; f++) s[j][f] = 0.f;

#pragma unroll
        for (int kk = 0; kk < 12; kk++) {
            uint32_t ah[4];
            uint32_t aaddr = (uint32_t)((wp * 16 + l16) * QSTR + kk * 16 + lhi) * 2;
            ldm_x4(ah, sQh + aaddr);
            const uint32_t* al = qlof[kk];
#pragma unroll
            for (int j2 = 0; j2 < 4; j2++) {
                uint32_t baddr = (uint32_t)((j2 * 16 + brofs) * KSTR + kk * 16 + bcofs) * 2;
                uint32_t tbv[4], tl[4];
                ldm_x4(tbv, sKh + baddr);
                ldm_x4(tl, sKl + baddr);
                mma_bf16(s[2 * j2],     ah, tbv);
                mma_bf16(s[2 * j2 + 1], ah, tbv + 2);
                mma_bf16(s[2 * j2],     ah, tl);
                mma_bf16(s[2 * j2 + 1], ah, tl + 2);
                mma_bf16(s[2 * j2],     al, tbv);
                mma_bf16(s[2 * j2 + 1], al, tbv + 2);
            }
        }

#pragma unroll
        for (int j = 0; j < 8; j++) {
            int k0 = kt * 64 + j * 8 + 2 * (lane & 3);
            if (k0     > qrow1) s[j][0] = -1e30f;
            if (k0 + 1 > qrow1) s[j][1] = -1e30f;
            if (k0     > qrow2) s[j][2] = -1e30f;
            if (k0 + 1 > qrow2) s[j][3] = -1e30f;
        }
        float mr1 = -1e30f, mr2 = -1e30f;
#pragma unroll
        for (int j = 0; j < 8; j++) {
            mr1 = fmaxf(mr1, fmaxf(s[j][0], s[j][1]));
            mr2 = fmaxf(mr2, fmaxf(s[j][2], s[j][3]));
        }
        mr1 = fmaxf(mr1, __shfl_xor_sync(0xffffffffu, mr1, 1));
        mr1 = fmaxf(mr1, __shfl_xor_sync(0xffffffffu, mr1, 2));
        mr2 = fmaxf(mr2, __shfl_xor_sync(0xffffffffu, mr2, 1));
        mr2 = fmaxf(mr2, __shfl_xor_sync(0xffffffffu, mr2, 2));
        float mn1 = fmaxf(m1, mr1), mn2 = fmaxf(m2, mr2);
        float a1 = ex2f(m1 - mn1), a2 = ex2f(m2 - mn2);
        m1 = mn1; m2 = mn2;

        uint32_t phx[8][2], plx[8][2];
        float rs1 = 0.f, rs2 = 0.f;
#pragma unroll
        for (int j = 0; j < 8; j++) {
            float p0 = ex2f(s[j][0] - mn1), p1 = ex2f(s[j][1] - mn1);
            float p2 = ex2f(s[j][2] - mn2), p3 = ex2f(s[j][3] - mn2);
            rs1 += p0 + p1; rs2 += p2 + p3;
            phx[j][0] = packbf2(p0, p1);
            phx[j][1] = packbf2(p2, p3);
            float q0 = p0 - bfround(p0);
            float q1 = p1 - bfround(p1);
            float q2 = p2 - bfround(p2);
            float q3 = p3 - bfround(p3);
            plx[j][0] = packbf2(q0, q1);
            plx[j][1] = packbf2(q2, q3);
        }
        rs1 += __shfl_xor_sync(0xffffffffu, rs1, 1);
        rs1 += __shfl_xor_sync(0xffffffffu, rs1, 2);
        rs2 += __shfl_xor_sync(0xffffffffu, rs2, 1);
        rs2 += __shfl_xor_sync(0xffffffffu, rs2, 2);
        l1 = l1 * a1 + rs1;
        l2 = l2 * a2 + rs2;
#pragma unroll
        for (int t16 = 0; t16 < 16; t16++) {
            o[t16][0] *= a1; o[t16][1] *= a1;
            o[t16][2] *= a2; o[t16][3] *= a2;
        }

#pragma unroll
        for (int kt2 = 0; kt2 < 4; kt2++) {
            uint32_t pa_h[4] = {phx[2 * kt2][0], phx[2 * kt2][1],
                                phx[2 * kt2 + 1][0], phx[2 * kt2 + 1][1]};
            uint32_t pa_l[4] = {plx[2 * kt2][0], plx[2 * kt2][1],
                                plx[2 * kt2 + 1][0], plx[2 * kt2 + 1][1]};
            uint32_t vrow = (uint32_t)((kt2 * 16 + l16) * VSTR) * 2;
#pragma unroll
            for (int j2 = 0; j2 < 8; j2++) {
                uint32_t vaddr = vrow + (uint32_t)(j2 * 16 + lhi) * 2;
                uint32_t tv[4], tw[4];
                ldm_x4t(tv, sVh + vaddr);
                ldm_x4t(tw, sVl + vaddr);
                mma_bf16(o[2 * j2],     pa_h, tv);
                mma_bf16(o[2 * j2 + 1], pa_h, tv + 2);
                mma_bf16(o[2 * j2],     pa_h, tw);
                mma_bf16(o[2 * j2 + 1], pa_h, tw + 2);
                mma_bf16(o[2 * j2],     pa_l, tv);
                mma_bf16(o[2 * j2 + 1], pa_l, tv + 2);
            }
        }
        __syncthreads();
    }

    float inv1 = 1.f / l1, inv2 = 1.f / l2;
    size_t row1 = (size_t)(b * TT + qrow1) * 2048 + h * 128;
    size_t row2 = (size_t)(b * TT + qrow2) * 2048 + h * 128;
#pragma unroll
    for (int t16 = 0; t16 < 16; t16++) {
        int col = t16 * 8 + 2 * (lane & 3);
        float v0 = o[t16][0] * inv1, v1 = o[t16][1] * inv1;
        float v2 = o[t16][2] * inv2, v3 = o[t16][3] * inv2;
        float f0 = bfround(v0), f1 = bfround(v1);
        float f2 = bfround(v2), f3 = bfround(v3);
        *(uint32_t*)&ohi[row1 + col] = packbf2(f0, f1);
        *(uint32_t*)&olo[row1 + col] = packbf2(v0 - f0, v1 - f1);
        *(uint32_t*)&ohi[row2 + col] = packbf2(f2, f3);
        *(uint32_t*)&olo[row2 + col] = packbf2(v2 - f2, v3 - f3);
    }
}

// ---------------------------------------------------------------------------
// Host launcher
// ---------------------------------------------------------------------------
extern "C" void kernel_launch(void* const* d_in, const int* in_sizes, int n_in,
                              void* d_out, int out_size)
{
    (void)in_sizes; (void)n_in; (void)out_size;

    const float* x     = (const float*)d_in[0];
    const float* W_dkv = (const float*)d_in[1];
    const float* b_dkv = (const float*)d_in[2];
    const float* W_kr  = (const float*)d_in[3];
    const float* b_kr  = (const float*)d_in[4];
    const float* W_qr  = (const float*)d_in[5];
    const float* b_qr  = (const float*)d_in[6];
    const float* W_uv  = (const float*)d_in[7];
    const float* b_uv  = (const float*)d_in[8];
    const float* W_uq  = (const float*)d_in[9];
    const float* b_uq  = (const float*)d_in[10];
    const float* W_o   = (const float*)d_in[11];
    const float* b_o   = (const float*)d_in[12];
    float* out = (float*)d_out;

    float *h, *kr, *qr;
    bf16 *xhi, *xlo, *hhi, *hlo, *athi, *atlo;
    bf16 *wdkvh, *wdkvl, *wqrh, *wqrl, *wuvh, *wuvl, *wuqh, *wuql, *woh, *wol;
    bf16 *qhi, *qlo, *khi, *klo, *vhi, *vlo;
    cudaGetSymbolAddress((void**)&h,    g_h);
    cudaGetSymbolAddress((void**)&kr,   g_kr);
    cudaGetSymbolAddress((void**)&qr,   g_qr);
    cudaGetSymbolAddress((void**)&xhi,  g_xhi);
    cudaGetSymbolAddress((void**)&xlo,  g_xlo);
    cudaGetSymbolAddress((void**)&hhi,  g_hhi);
    cudaGetSymbolAddress((void**)&hlo,  g_hlo);
    cudaGetSymbolAddress((void**)&athi, g_athi);
    cudaGetSymbolAddress((void**)&atlo, g_atlo);
    cudaGetSymbolAddress((void**)&wdkvh, g_wdkvh);
    cudaGetSymbolAddress((void**)&wdkvl, g_wdkvl);
    cudaGetSymbolAddress((void**)&wqrh, g_wqrh);
    cudaGetSymbolAddress((void**)&wqrl, g_wqrl);
    cudaGetSymbolAddress((void**)&wuvh, g_wuvh);
    cudaGetSymbolAddress((void**)&wuvl, g_wuvl);
    cudaGetSymbolAddress((void**)&wuqh, g_wuqh);
    cudaGetSymbolAddress((void**)&wuql, g_wuql);
    cudaGetSymbolAddress((void**)&woh,  g_woh);
    cudaGetSymbolAddress((void**)&wol,  g_wol);
    cudaGetSymbolAddress((void**)&qhi, g_qhi);
    cudaGetSymbolAddress((void**)&qlo, g_qlo);
    cudaGetSymbolAddress((void**)&khi, g_khi);
    cudaGetSymbolAddress((void**)&klo, g_klo);
    cudaGetSymbolAddress((void**)&vhi, g_vhi);
    cudaGetSymbolAddress((void**)&vlo, g_vlo);

    const int M = MROWS;  // 4096

    cudaFuncSetAttribute(gemm_mma, cudaFuncAttributeMaxDynamicSharedMemorySize, GSMEM);
    cudaFuncSetAttribute(attn_tc, cudaFuncAttributeMaxDynamicSharedMemorySize, ATTN_SMEM);

    // 1) prep: x split + all 5 weight transpose/splits (one launch)
    prep_all<<<18432, 256>>>(x, W_dkv, W_o, W_qr, W_uv, W_uq,
                             xhi, xlo, wdkvh, wdkvl, woh, wol,
                             wqrh, wqrl, wuvh, wuvl, wuqh, wuql);
    // 2) h = x @ W_dkv + b_dkv (mode 1: fp32 h + hhi/hlo)
    gemm_mma<<<dim3(8, 32), 128, GSMEM>>>(xhi, xlo, 2048, 0, wdkvh, wdkvl, 2048,
                                          b_dkv, h, 1024, 2048, hhi, hlo, 0, 0, 1);
    // 3) kr projection (fp32)
    sgemm_bias<<<dim3(1, 64), 256>>>(h, 1024, 0, W_kr, b_kr, kr, 64, M, 64, 1024);
    // 4) qr = h @ W_qr (mode 0 -> fp32 qr)
    gemm_mma<<<dim3(8, 32), 128, GSMEM>>>(hhi, hlo, 1024, 0, wqrh, wqrl, 1024,
                                          b_qr, qr, 1024, 1024, 0, 0, 0, 0, 0);
    // 5) fused rope+split qr -> qhi/qlo slices
    rope_split_qr<<<(M * 512 + 255) / 256, 256>>>(qr, qhi, qlo);
    // 6) fused rope+split kr -> khi/klo slices (broadcast 16 heads)
    rope_split_kr<<<(M * 32 + 255) / 256, 256>>>(kr, khi, klo);
    // 7) kv GEMM (mode 2: khi/klo + vhi/vlo per-head)
    gemm_mma<<<dim3(32, 32), 128, GSMEM>>>(hhi, hlo, 1024, 0, wuvh, wuvl, 512,
                                           b_uv, 0, 0, 512, khi, klo, vhi, vlo, 2);
    // 8) q GEMM (mode 3: qhi/qlo scaled per-head)
    gemm_mma<<<dim3(16, 32), 128, GSMEM>>>(hhi, hlo, 1024, 512, wuqh, wuql, 512,
                                           b_uq, 0, 0, 512, qhi, qlo, 0, 0, 3);
    // 9) attention -> athi/atlo
    attn_tc<<<dim3(TT / 128, BB * NHH), 256, ATTN_SMEM>>>(qhi, qlo, khi, klo,
                                                          vhi, vlo, athi, atlo);
    // 10) out = attn @ W_o + b_o (mode 0)
    gemm_mma<<<dim3(16, 32), 128, GSMEM>>>(athi, atlo, 2048, 0, woh, wol, 2048,
                                           b_o, out, 2048, 2048, 0, 0, 0, 0, 0);
}

// round 14
// speedup vs baseline: 2.4780x; 1.0393x over previous
#include <cuda_runtime.h>
#include <cuda_bf16.h>
#include <math.h>
#include <stdint.h>

// Problem constants
#define BB   2
#define TT   2048
#define CC   2048
#define NHH  16
#define DKK  128
#define LATT 512
#define DHRR 64
#define MROWS (BB * TT)   // 4096

typedef __nv_bfloat16 bf16;

// ---------------------------------------------------------------------------
// Scratch (static device globals -- no allocation allowed)
// ---------------------------------------------------------------------------
__device__ float g_h   [(size_t)MROWS * 1024];
__device__ float g_kr  [(size_t)MROWS * 64];
__device__ float g_qr  [(size_t)MROWS * 1024];

__device__ bf16 g_xhi [(size_t)MROWS * 2048];
__device__ bf16 g_xlo [(size_t)MROWS * 2048];
__device__ bf16 g_hhi [(size_t)MROWS * 1024];
__device__ bf16 g_hlo [(size_t)MROWS * 1024];
__device__ bf16 g_athi[(size_t)MROWS * 2048];
__device__ bf16 g_atlo[(size_t)MROWS * 2048];

__device__ bf16 g_wdkvh[(size_t)1024 * 2048];
__device__ bf16 g_wdkvl[(size_t)1024 * 2048];
__device__ bf16 g_wqrh [(size_t)1024 * 1024];
__device__ bf16 g_wqrl [(size_t)1024 * 1024];
__device__ bf16 g_wuvh [(size_t)4096 * 512];
__device__ bf16 g_wuvl [(size_t)4096 * 512];
__device__ bf16 g_wuqh [(size_t)2048 * 512];
__device__ bf16 g_wuql [(size_t)2048 * 512];
__device__ bf16 g_woh  [(size_t)2048 * 2048];
__device__ bf16 g_wol  [(size_t)2048 * 2048];

__device__ bf16 g_qhi[(size_t)BB * NHH * TT * 192];
__device__ bf16 g_qlo[(size_t)BB * NHH * TT * 192];
__device__ bf16 g_khi[(size_t)BB * NHH * TT * 192];
__device__ bf16 g_klo[(size_t)BB * NHH * TT * 192];
__device__ bf16 g_vhi[(size_t)BB * NHH * TT * 128];
__device__ bf16 g_vlo[(size_t)BB * NHH * TT * 128];

#define SCLQ 0.12754984837627695f   // 1/sqrt(128) * log2(e)

// ---------------------------------------------------------------------------
// PTX helpers
// ---------------------------------------------------------------------------
__device__ __forceinline__ uint32_t smem_u32(const void* p)
{ return (uint32_t)__cvta_generic_to_shared(p); }

__device__ __forceinline__ void cp16(uint32_t dst, const void* src)
{ asm volatile("cp.async.cg.shared.global [%0], [%1], 16;\n" :: "r"(dst), "l"(src)); }

__device__ __forceinline__ void cp_commit()
{ asm volatile("cp.async.commit_group;\n"); }

template <int N>
__device__ __forceinline__ void cp_wait()
{ asm volatile("cp.async.wait_group %0;\n" :: "n"(N)); }

__device__ __forceinline__ void ldm_x4(uint32_t* r, uint32_t addr)
{
    asm volatile("ldmatrix.sync.aligned.m8n8.x4.shared.b16 {%0,%1,%2,%3}, [%4];\n"
        : "=r"(r[0]), "=r"(r[1]), "=r"(r[2]), "=r"(r[3]) : "r"(addr));
}
__device__ __forceinline__ void ldm_x4t(uint32_t* r, uint32_t addr)
{
    asm volatile("ldmatrix.sync.aligned.m8n8.x4.trans.shared.b16 {%0,%1,%2,%3}, [%4];\n"
        : "=r"(r[0]), "=r"(r[1]), "=r"(r[2]), "=r"(r[3]) : "r"(addr));
}
__device__ __forceinline__ void mma_bf16(float* d, const uint32_t* a, const uint32_t* b)
{
    asm volatile(
        "mma.sync.aligned.m16n8k16.row.col.f32.bf16.bf16.f32 "
        "{%0,%1,%2,%3}, {%4,%5,%6,%7}, {%8,%9}, {%0,%1,%2,%3};\n"
        : "+f"(d[0]), "+f"(d[1]), "+f"(d[2]), "+f"(d[3])
        : "r"(a[0]), "r"(a[1]), "r"(a[2]), "r"(a[3]), "r"(b[0]), "r"(b[1]));
}
__device__ __forceinline__ float ex2f(float x)
{ float y; asm("ex2.approx.f32 %0, %1;" : "=f"(y) : "f"(x)); return y; }

__device__ __forceinline__ uint32_t packbf2(float lo, float hi)
{ uint32_t d; asm("cvt.rn.bf16x2.f32 %0, %1, %2;" : "=r"(d) : "f"(hi), "f"(lo)); return d; }

__device__ __forceinline__ float bfround(float v)
{ return __bfloat162float(__float2bfloat16(v)); }

// ---------------------------------------------------------------------------
// prep_all: one launch = split_act(x) + 5 weight transpose/splits.
// ---------------------------------------------------------------------------
__global__ __launch_bounds__(256)
void prep_all(const float* __restrict__ x,
              const float* __restrict__ Wdkv, const float* __restrict__ Wo,
              const float* __restrict__ Wqr,  const float* __restrict__ Wuv,
              const float* __restrict__ Wuq,
              bf16* __restrict__ xhi, bf16* __restrict__ xlo,
              bf16* __restrict__ wdkvh, bf16* __restrict__ wdkvl,
              bf16* __restrict__ woh,  bf16* __restrict__ wol,
              bf16* __restrict__ wqrh, bf16* __restrict__ wqrl,
              bf16* __restrict__ wuvh, bf16* __restrict__ wuvl,
              bf16* __restrict__ wuqh, bf16* __restrict__ wuql)
{
    __shared__ float ts[32][33];
    const int bid = blockIdx.x, tid = threadIdx.x;

    if (bid < 8192) {
        int idx = bid * 256 + tid;
        int m = idx >> 9, k4 = (idx & 511) * 4;
        float4 v = *(const float4*)&x[(size_t)m * 2048 + k4];
        float h0 = bfround(v.x), h1 = bfround(v.y);
        float h2 = bfround(v.z), h3 = bfround(v.w);
        uint2 ph, pl;
        ph.x = packbf2(h0, h1); ph.y = packbf2(h2, h3);
        pl.x = packbf2(v.x - h0, v.y - h1); pl.y = packbf2(v.z - h2, v.w - h3);
        *(uint2*)&xhi[(size_t)m * 2048 + k4] = ph;
        *(uint2*)&xlo[(size_t)m * 2048 + k4] = pl;
        return;
    }

    const float* W; bf16 *hiT, *loT; int K, N, tl;
    if (bid < 10240)      { W = Wdkv; hiT = wdkvh; loT = wdkvl; K = 2048; N = 1024; tl = bid - 8192; }
    else if (bid < 14336) { W = Wo;   hiT = woh;   loT = wol;   K = 2048; N = 2048; tl = bid - 10240; }
    else if (bid < 15360) { W = Wqr;  hiT = wqrh;  loT = wqrl;  K = 1024; N = 1024; tl = bid - 14336; }
    else if (bid < 17408) { W = Wuv;  hiT = wuvh;  loT = wuvl;  K = 512;  N = 4096; tl = bid - 15360; }
    else                  { W = Wuq;  hiT = wuqh;  loT = wuql;  K = 512;  N = 2048; tl = bid - 17408; }

    int ntx = N / 32;
    int n0 = (tl % ntx) * 32, k0 = (tl / ntx) * 32;
    int tx = tid & 31, ty = tid >> 5;
#pragma unroll
    for (int r = 0; r < 4; r++)
        ts[ty + 8 * r][tx] = W[(size_t)(k0 + ty + 8 * r) * N + n0 + tx];
    __syncthreads();
#pragma unroll
    for (int r = 0; r < 4; r++) {
        float v = ts[tx][ty + 8 * r];
        bf16 h = __float2bfloat16(v);
        size_t o = (size_t)(n0 + ty + 8 * r) * K + k0 + tx;
        hiT[o] = h;
        loT[o] = __float2bfloat16(v - __bfloat162float(h));
    }
}

// ---------------------------------------------------------------------------
// Fused rope + hi/lo split + per-head scatter (qr blocks then kr blocks)
// ---------------------------------------------------------------------------
__global__ void rope_split_both(const float* __restrict__ qr,
                                const float* __restrict__ kr,
                                bf16* __restrict__ qhi, bf16* __restrict__ qlo,
                                bf16* __restrict__ khi, bf16* __restrict__ klo)
{
    const int bid = blockIdx.x, tid = threadIdx.x;
    if (bid < 8192) {
        int idx = bid * 256 + tid;                   // over 4096*512 pairs
        int row = idx >> 9, i = idx & 511;
        int t = row & 2047, b = row >> 11;
        float theta = (float)exp(-2.0 * (double)i / 1024.0 * log(10000.0));
        float angle = (float)(t + 1) * theta;
        double a = (double)angle;
        float cs = (float)cos(a), sn = (float)sin(a);
        const float* p = qr + (size_t)row * 1024 + 2 * i;
        float x0 = p[0], x1 = p[1];
        float p0 = (x0 * cs - x1 * sn) * SCLQ;
        float p1 = (x1 * cs + x0 * sn) * SCLQ;
        int h = (2 * i) >> 6, d = (2 * i) & 63;
        size_t base = ((size_t)((b * NHH + h) * TT) + t) * 192 + 128 + d;
        float f0 = bfround(p0), f1 = bfround(p1);
        *(uint32_t*)&qhi[base] = packbf2(f0, f1);
        *(uint32_t*)&qlo[base] = packbf2(p0 - f0, p1 - f1);
    } else {
        int idx = (bid - 8192) * 256 + tid;          // over 4096*32 pairs
        int row = idx >> 5, i = idx & 31;
        int t = row & 2047, b = row >> 11;
        float theta = (float)exp(-2.0 * (double)i / 64.0 * log(10000.0));
        float angle = (float)(t + 1) * theta;
        double a = (double)angle;
        float cs = (float)cos(a), sn = (float)sin(a);
        const float* p = kr + (size_t)row * 64 + 2 * i;
        float x0 = p[0], x1 = p[1];
        float p0 = x0 * cs - x1 * sn;
        float p1 = x1 * cs + x0 * sn;
        float f0 = bfround(p0), f1 = bfround(p1);
        uint32_t ph = packbf2(f0, f1), pl = packbf2(p0 - f0, p1 - f1);
#pragma unroll
        for (int hh = 0; hh < NHH; hh++) {
            size_t base = ((size_t)((b * NHH + hh) * TT) + t) * 192 + 128 + 2 * i;
            *(uint32_t*)&khi[base] = ph;
            *(uint32_t*)&klo[base] = pl;
        }
    }
}

// ---------------------------------------------------------------------------
// Shared HMMA GEMM body (compensated hi/lo, fused epilogues) — R12 proven.
// ---------------------------------------------------------------------------
#define TST 40
#define A_ELE (128 * TST)
#define B_ELE (128 * TST)
#define STG_ELE (2 * A_ELE + 2 * B_ELE)
#define GSMEM (2 * STG_ELE * 2)

__device__ __forceinline__
void gemm_body(int brow, int bcol,
               const bf16* __restrict__ Ahi, const bf16* __restrict__ Alo,
               int lda, int aoff,
               const bf16* __restrict__ Bhi, const bf16* __restrict__ Blo,
               int ldb,
               const float* __restrict__ bias,
               float* __restrict__ Y, int ldy, int K,
               bf16* __restrict__ ho, bf16* __restrict__ lo_,
               bf16* __restrict__ ho2, bf16* __restrict__ lo2, int mode,
               bf16* dsm)
{
    const uint32_t sb0 = smem_u32(dsm);
    const int tid = threadIdx.x, lane = tid & 31, wid = tid >> 5;
    const int wm = (wid >> 1) * 64, wn = (wid & 1) * 64;

    auto issue = [&](int st, int kt) {
        uint32_t s = sb0 + (uint32_t)(st * STG_ELE) * 2;
        int ke = kt * 32;
#pragma unroll
        for (int i = 0; i < 4; i++) {
            int c = tid + i * 128;
            int r = c >> 2, sg = (c & 3) * 8;
            uint32_t d = (uint32_t)(r * TST + sg) * 2;
            cp16(s + d, Ahi + (size_t)(brow + r) * lda + aoff + ke + sg);
            cp16(s + (uint32_t)A_ELE * 2 + d,
                 Alo + (size_t)(brow + r) * lda + aoff + ke + sg);
            cp16(s + (uint32_t)(2 * A_ELE) * 2 + d,
                 Bhi + (size_t)(bcol + r) * ldb + ke + sg);
            cp16(s + (uint32_t)(2 * A_ELE + B_ELE) * 2 + d,
                 Blo + (size_t)(bcol + r) * ldb + ke + sg);
        }
        cp_commit();
    };

    float acc[4][8][4];
#pragma unroll
    for (int i = 0; i < 4; i++)
#pragma unroll
        for (int j = 0; j < 8; j++)
#pragma unroll
            for (int f = 0; f < 4; f++) acc[i][j][f] = 0.f;

    const int ntiles = K / 32;
    issue(0, 0);
    issue(1, 1);

    const int l16 = lane & 15, lhi = (lane >> 4) * 8;
    const int brofs = (lane & 7) + ((lane >> 4) & 1) * 8;
    const int bcofs = ((lane >> 3) & 1) * 8;

    for (int kt = 0; kt < ntiles; kt++) {
        if (kt + 1 < ntiles) { cp_wait<1>(); } else { cp_wait<0>(); }
        __syncthreads();
        int cur = kt & 1;
        uint32_t s = sb0 + (uint32_t)(cur * STG_ELE) * 2;
        uint32_t sAh = s, sAl = s + (uint32_t)A_ELE * 2;
        uint32_t sBh = s + (uint32_t)(2 * A_ELE) * 2;
        uint32_t sBl = sBh + (uint32_t)B_ELE * 2;

#pragma unroll
        for (int kk = 0; kk < 32; kk += 16) {
            uint32_t bh[4][4], bl[4][4];
#pragma unroll
            for (int j2 = 0; j2 < 4; j2++) {
                uint32_t baddr =
                    (uint32_t)((wn + j2 * 16 + brofs) * TST + kk + bcofs) * 2;
                ldm_x4(bh[j2], sBh + baddr);
                ldm_x4(bl[j2], sBl + baddr);
            }
#pragma unroll
            for (int i = 0; i < 4; i++) {
                uint32_t ah[4], al[4];
                uint32_t aaddr = (uint32_t)((wm + i * 16 + l16) * TST + kk + lhi) * 2;
                ldm_x4(ah, sAh + aaddr);
                ldm_x4(al, sAl + aaddr);
#pragma unroll
                for (int j2 = 0; j2 < 4; j2++) {
                    mma_bf16(acc[i][2 * j2],     ah, bh[j2]);
                    mma_bf16(acc[i][2 * j2 + 1], ah, bh[j2] + 2);
                }
#pragma unroll
                for (int j2 = 0; j2 < 4; j2++) {
                    mma_bf16(acc[i][2 * j2],     ah, bl[j2]);
                    mma_bf16(acc[i][2 * j2 + 1], ah, bl[j2] + 2);
                }
#pragma unroll
                for (int j2 = 0; j2 < 4; j2++) {
                    mma_bf16(acc[i][2 * j2],     al, bh[j2]);
                    mma_bf16(acc[i][2 * j2 + 1], al, bh[j2] + 2);
                }
            }
        }
        __syncthreads();
        if (kt + 2 < ntiles) issue(cur, kt + 2);
    }

#pragma unroll
    for (int i = 0; i < 4; i++) {
#pragma unroll
        for (int j = 0; j < 8; j++) {
            int r0 = brow + wm + i * 16 + (lane >> 2);
            int c0 = bcol + wn + j * 8 + (lane & 3) * 2;
            float b0 = bias[c0], b1 = bias[c0 + 1];
            float v00 = acc[i][j][0] + b0, v01 = acc[i][j][1] + b1;
            float v10 = acc[i][j][2] + b0, v11 = acc[i][j][3] + b1;

            if (mode <= 1) {
                *(float2*)&Y[(size_t)r0 * ldy + c0]       = make_float2(v00, v01);
                *(float2*)&Y[(size_t)(r0 + 8) * ldy + c0] = make_float2(v10, v11);
            }
            if (mode == 1) {
                float f00 = bfround(v00), f01 = bfround(v01);
                float f10 = bfround(v10), f11 = bfround(v11);
                *(uint32_t*)&ho [(size_t)r0 * ldy + c0]       = packbf2(f00, f01);
                *(uint32_t*)&lo_[(size_t)r0 * ldy + c0]       = packbf2(v00 - f00, v01 - f01);
                *(uint32_t*)&ho [(size_t)(r0 + 8) * ldy + c0] = packbf2(f10, f11);
                *(uint32_t*)&lo_[(size_t)(r0 + 8) * ldy + c0] = packbf2(v10 - f10, v11 - f11);
            } else if (mode == 2) {
#pragma unroll
                for (int rr = 0; rr < 2; rr++) {
                    int r = r0 + rr * 8;
                    float va = rr ? v10 : v00, vb = rr ? v11 : v01;
                    int b = r >> 11, t = r & 2047;
                    float fa = bfround(va), fb = bfround(vb);
                    if (c0 < 2048) {
                        int hh = c0 >> 7, d = c0 & 127;
                        size_t base = ((size_t)(b * NHH + hh) * TT + t) * 192 + d;
                        *(uint32_t*)&ho [base] = packbf2(fa, fb);
                        *(uint32_t*)&lo_[base] = packbf2(va - fa, vb - fb);
                    } else {
                        int c2 = c0 - 2048;
                        int hh = c2 >> 7, d = c2 & 127;
                        size_t base = ((size_t)(b * NHH + hh) * TT + t) * 128 + d;
                        *(uint32_t*)&ho2[base] = packbf2(fa, fb);
                        *(uint32_t*)&lo2[base] = packbf2(va - fa, vb - fb);
                    }
                }
            } else if (mode == 3) {
#pragma unroll
                for (int rr = 0; rr < 2; rr++) {
                    int r = r0 + rr * 8;
                    float va = (rr ? v10 : v00) * SCLQ, vb = (rr ? v11 : v01) * SCLQ;
                    int b = r >> 11, t = r & 2047;
                    int hh = c0 >> 7, d = c0 & 127;
                    size_t base = ((size_t)(b * NHH + hh) * TT + t) * 192 + d;
                    float fa = bfround(va), fb = bfround(vb);
                    *(uint32_t*)&ho [base] = packbf2(fa, fb);
                    *(uint32_t*)&lo_[base] = packbf2(va - fa, vb - fb);
                }
            }
        }
    }
}

// Standalone GEMM (h and out projections)
__global__ __launch_bounds__(128, 2)
void gemm_mma(const bf16* __restrict__ Ahi, const bf16* __restrict__ Alo,
              int lda, int aoff,
              const bf16* __restrict__ Bhi, const bf16* __restrict__ Blo,
              int ldb,
              const float* __restrict__ bias,
              float* __restrict__ Y, int ldy, int K,
              bf16* __restrict__ ho, bf16* __restrict__ lo_,
              bf16* __restrict__ ho2, bf16* __restrict__ lo2, int mode)
{
    extern __shared__ bf16 dsm[];
    gemm_body(blockIdx.y * 128, blockIdx.x * 128, Ahi, Alo, lda, aoff,
              Bhi, Blo, ldb, bias, Y, ldy, K, ho, lo_, ho2, lo2, mode, dsm);
}

// Fused qr + kv + q GEMMs (all read hhi/hlo); one launch, range dispatch.
// Blocks: [0,256) qr (8x32, K=1024); [256,1280) kv (32x32, K=512);
//         [1280,1792) q (16x32, K=512).
__global__ __launch_bounds__(128, 2)
void gemm_fused3(const bf16* __restrict__ hhi, const bf16* __restrict__ hlo,
                 const bf16* __restrict__ wqrh, const bf16* __restrict__ wqrl,
                 const float* __restrict__ b_qr, float* __restrict__ qr,
                 const bf16* __restrict__ wuvh, const bf16* __restrict__ wuvl,
                 const float* __restrict__ b_uv,
                 bf16* __restrict__ khi, bf16* __restrict__ klo,
                 bf16* __restrict__ vhi, bf16* __restrict__ vlo,
                 const bf16* __restrict__ wuqh, const bf16* __restrict__ wuql,
                 const float* __restrict__ b_uq,
                 bf16* __restrict__ qhi, bf16* __restrict__ qlo)
{
    extern __shared__ bf16 dsm[];
    const int id = blockIdx.x;
    if (id < 256) {
        int bx = id & 7, by = id >> 3;
        gemm_body(by * 128, bx * 128, hhi, hlo, 1024, 0, wqrh, wqrl, 1024,
                  b_qr, qr, 1024, 1024, 0, 0, 0, 0, 0, dsm);
    } else if (id < 1280) {
        int t = id - 256;
        int bx = t & 31, by = t >> 5;
        gemm_body(by * 128, bx * 128, hhi, hlo, 1024, 0, wuvh, wuvl, 512,
                  b_uv, 0, 512, 512, khi, klo, vhi, vlo, 2, dsm);
    } else {
        int t = id - 1280;
        int bx = t & 15, by = t >> 4;
        gemm_body(by * 128, bx * 128, hhi, hlo, 1024, 512, wuqh, wuql, 512,
                  b_uq, 0, 512, 512, qhi, qlo, 0, 0, 3, dsm);
    }
}

// ---------------------------------------------------------------------------
// Small SGEMM (N=64 W_kr projection only)
// ---------------------------------------------------------------------------
#define GBM 64
#define GBN 64
#define GBK 16

__global__ __launch_bounds__(256)
void sgemm_bias(const float* __restrict__ A, int lda, int aoff,
                const float* __restrict__ W,
                const float* __restrict__ bias,
                float* __restrict__ Y, int ldy,
                int M, int N, int K)
{
    __shared__ float As[GBK][GBM];
    __shared__ float Bs[GBK][GBN];

    const int tid = threadIdx.x;
    const int brow = blockIdx.y * GBM;
    const int bcol = blockIdx.x * GBN;
    const int tr = (tid / 16) * 4;
    const int tc = (tid % 16) * 4;

    float acc[4][4];
#pragma unroll
    for (int i = 0; i < 4; i++)
#pragma unroll
        for (int j = 0; j < 4; j++) acc[i][j] = 0.f;

    for (int k0 = 0; k0 < K; k0 += GBK) {
#pragma unroll
        for (int it = 0; it < (GBM * GBK) / 256; it++) {
            int i = tid + it * 256;
            int m = i / GBK, kk = i % GBK;
            As[kk][m] = A[(size_t)(brow + m) * lda + aoff + k0 + kk];
        }
#pragma unroll
        for (int it = 0; it < (GBK * GBN) / 256; it++) {
            int i = tid + it * 256;
            int kk = i / GBN, n = i % GBN;
            Bs[kk][n] = W[(size_t)(k0 + kk) * N + bcol + n];
        }
        __syncthreads();

#pragma unroll
        for (int kk = 0; kk < GBK; kk++) {
            float a[4], b[4];
#pragma unroll
            for (int i = 0; i < 4; i++) a[i] = As[kk][tr + i];
#pragma unroll
            for (int j = 0; j < 4; j++) b[j] = Bs[kk][tc + j];
#pragma unroll
            for (int i = 0; i < 4; i++)
#pragma unroll
                for (int j = 0; j < 4; j++) acc[i][j] = fmaf(a[i], b[j], acc[i][j]);
        }
        __syncthreads();
    }

#pragma unroll
    for (int i = 0; i < 4; i++)
#pragma unroll
        for (int j = 0; j < 4; j++)
            Y[(size_t)(brow + tr + i) * ldy + bcol + tc + j] =
                acc[i][j] + bias[bcol + tc + j];
}

// ---------------------------------------------------------------------------
// Tensor-core flash attention (unchanged from R12/R13)
// ---------------------------------------------------------------------------
#define QSTR 200
#define KSTR 200
#define VSTR 136
#define Q_ELEMS (128 * QSTR)
#define KST_ELEMS (64 * KSTR)
#define VST_ELEMS (64 * VSTR)
#define K_BASE Q_ELEMS
#define V_BASE (Q_ELEMS + 4 * KST_ELEMS)
#define ATTN_SMEM ((Q_ELEMS + 4 * KST_ELEMS + 4 * VST_ELEMS) * 2)

__global__ __launch_bounds__(256, 1)
void attn_tc(const bf16* __restrict__ qhi, const bf16* __restrict__ qlo,
             const bf16* __restrict__ khi, const bf16* __restrict__ klo,
             const bf16* __restrict__ vhi, const bf16* __restrict__ vlo,
             bf16* __restrict__ ohi, bf16* __restrict__ olo)
{
    extern __shared__ bf16 smA[];
    const uint32_t sQh = smem_u32(smA);
    const uint32_t sK  = sQh + K_BASE * 2;
    const uint32_t sV  = sQh + V_BASE * 2;

    const int tid = threadIdx.x, lane = tid & 31, wp = tid >> 5;
    const int bh = blockIdx.y;
    const int qi = gridDim.x - 1 - blockIdx.x;
    const int b = bh >> 4, h = bh & 15;
    const size_t base = (size_t)bh * TT;

    const int l16 = lane & 15, lhi = (lane >> 4) * 8;

    for (int i = tid; i < 128 * 24; i += 256) {
        int r = i / 24, c = (i % 24) * 8;
        size_t g = (base + (size_t)qi * 128 + r) * 192 + c;
        uint32_t d = (uint32_t)(r * QSTR + c) * 2;
        cp16(sQh + d, qhi + g);
        cp16(sK + d, qlo + g);
    }
    cp_commit();
    cp_wait<0>();
    __syncthreads();

    uint32_t qlof[12][4];
#pragma unroll
    for (int kk = 0; kk < 12; kk++) {
        uint32_t aaddr = (uint32_t)((wp * 16 + l16) * QSTR + kk * 16 + lhi) * 2;
        ldm_x4(qlof[kk], sK + aaddr);
    }
    __syncthreads();

    auto issueKV = [&](int st, int kt) {
        uint32_t kb = sK + (uint32_t)(st * 2 * KST_ELEMS) * 2;
        uint32_t vb = sV + (uint32_t)(st * 2 * VST_ELEMS) * 2;
        for (int i = tid; i < 64 * 24; i += 256) {
            int r = i / 24, c = (i % 24) * 8;
            size_t g = (base + (size_t)kt * 64 + r) * 192 + c;
            uint32_t d = (uint32_t)(r * KSTR + c) * 2;
            cp16(kb + d, khi + g);
            cp16(kb + (uint32_t)KST_ELEMS * 2 + d, klo + g);
        }
        for (int i = tid; i < 64 * 16; i += 256) {
            int r = i / 16, c = (i % 16) * 8;
            size_t g = (base + (size_t)kt * 64 + r) * 128 + c;
            uint32_t d = (uint32_t)(r * VSTR + c) * 2;
            cp16(vb + d, vhi + g);
            cp16(vb + (uint32_t)VST_ELEMS * 2 + d, vlo + g);
        }
        cp_commit();
    };

    float o[16][4];
#pragma unroll
    for (int i = 0; i < 16; i++)
#pragma unroll
        for (int f = 0; f < 4; f++) o[i][f] = 0.f;

    float m1 = -1e30f, m2 = -1e30f, l1 = 0.f, l2 = 0.f;
    const int qrow1 = qi * 128 + wp * 16 + (lane >> 2);
    const int qrow2 = qrow1 + 8;
    const int brofs = (lane & 7) + ((lane >> 4) & 1) * 8;
    const int bcofs = ((lane >> 3) & 1) * 8;

    const int nkt = 2 * qi + 2;
    issueKV(0, 0);

    for (int kt = 0; kt < nkt; kt++) {
        if (kt + 1 < nkt) {
            issueKV((kt + 1) & 1, kt + 1);
            cp_wait<1>();
        } else {
            cp_wait<0>();
        }
        __syncthreads();

        const int st = kt & 1;
        const uint32_t sKh = sK + (uint32_t)(st * 2 * KST_ELEMS) * 2;
        const uint32_t sKl = sKh + (uint32_t)KST_ELEMS * 2;
        const uint32_t sVh = sV + (uint32_t)(st * 2 * VST_ELEMS) * 2;
        const uint32_t sVl = sVh + (uint32_t)VST_ELEMS * 2;

        float s[8][4];
#pragma unroll
        for (int j = 0; j < 8; j++)
#pragma unroll
            for (int f = 0; f < 4; f++) s[j][f] = 0.f;

#pragma unroll
        for (int kk = 0; kk < 12; kk++) {
            uint32_t ah[4];
            uint32_t aaddr = (uint32_t)((wp * 16 + l16) * QSTR + kk * 16 + lhi) * 2;
            ldm_x4(ah, sQh + aaddr);
            const uint32_t* al = qlof[kk];
#pragma unroll
            for (int j2 = 0; j2 < 4; j2++) {
                uint32_t baddr = (uint32_t)((j2 * 16 + brofs) * KSTR + kk * 16 + bcofs) * 2;
                uint32_t tbv[4], tl[4];
                ldm_x4(tbv, sKh + baddr);
                ldm_x4(tl, sKl + baddr);
                mma_bf16(s[2 * j2],     ah, tbv);
                mma_bf16(s[2 * j2 + 1], ah, tbv + 2);
                mma_bf16(s[2 * j2],     ah, tl);
                mma_bf16(s[2 * j2 + 1], ah, tl + 2);
                mma_bf16(s[2 * j2],     al, tbv);
                mma_bf16(s[2 * j2 + 1], al, tbv + 2);
            }
        }

#pragma unroll
        for (int j = 0; j < 8; j++) {
            int k0 = kt * 64 + j * 8 + 2 * (lane & 3);
            if (k0     > qrow1) s[j][0] = -1e30f;
            if (k0 + 1 > qrow1) s[j][1] = -1e30f;
            if (k0     > qrow2) s[j][2] = -1e30f;
            if (k0 + 1 > qrow2) s[j][3] = -1e30f;
        }
        float mr1 = -1e30f, mr2 = -1e30f;
#pragma unroll
        for (int j = 0; j < 8; j++) {
            mr1 = fmaxf(mr1, fmaxf(s[j][0], s[j][1]));
            mr2 = fmaxf(mr2, fmaxf(s[j][2], s[j][3]));
        }
        mr1 = fmaxf(mr1, __shfl_xor_sync(0xffffffffu, mr1, 1));
        mr1 = fmaxf(mr1, __shfl_xor_sync(0xffffffffu, mr1, 2));
        mr2 = fmaxf(mr2, __shfl_xor_sync(0xffffffffu, mr2, 1));
        mr2 = fmaxf(mr2, __shfl_xor_sync(0xffffffffu, mr2, 2));
        float mn1 = fmaxf(m1, mr1), mn2 = fmaxf(m2, mr2);
        float a1 = ex2f(m1 - mn1), a2 = ex2f(m2 - mn2);
        m1 = mn1; m2 = mn2;

        uint32_t phx[8][2], plx[8][2];
        float rs1 = 0.f, rs2 = 0.f;
#pragma unroll
        for (int j = 0; j < 8; j++) {
            float p0 = ex2f(s[j][0] - mn1), p1 = ex2f(s[j][1] - mn1);
            float p2 = ex2f(s[j][2] - mn2), p3 = ex2f(s[j][3] - mn2);
            rs1 += p0 + p1; rs2 += p2 + p3;
            phx[j][0] = packbf2(p0, p1);
            phx[j][1] = packbf2(p2, p3);
            float q0 = p0 - bfround(p0);
            float q1 = p1 - bfround(p1);
            float q2 = p2 - bfround(p2);
            float q3 = p3 - bfround(p3);
            plx[j][0] = packbf2(q0, q1);
            plx[j][1] = packbf2(q2, q3);
        }
        rs1 += __shfl_xor_sync(0xffffffffu, rs1, 1);
        rs1 += __shfl_xor_sync(0xffffffffu, rs1, 2);
        rs2 += __shfl_xor_sync(0xffffffffu, rs2, 1);
        rs2 += __shfl_xor_sync(0xffffffffu, rs2, 2);
        l1 = l1 * a1 + rs1;
        l2 = l2 * a2 + rs2;
#pragma unroll
        for (int t16 = 0; t16 < 16; t16++) {
            o[t16][0] *= a1; o[t16][1] *= a1;
            o[t16][2] *= a2; o[t16][3] *= a2;
        }

#pragma unroll
        for (int kt2 = 0; kt2 < 4; kt2++) {
            uint32_t pa_h[4] = {phx[2 * kt2][0], phx[2 * kt2][1],
                                phx[2 * kt2 + 1][0], phx[2 * kt2 + 1][1]};
            uint32_t pa_l[4] = {plx[2 * kt2][0], plx[2 * kt2][1],
                                plx[2 * kt2 + 1][0], plx[2 * kt2 + 1][1]};
            uint32_t vrow = (uint32_t)((kt2 * 16 + l16) * VSTR) * 2;
#pragma unroll
            for (int j2 = 0; j2 < 8; j2++) {
                uint32_t vaddr = vrow + (uint32_t)(j2 * 16 + lhi) * 2;
                uint32_t tv[4], tw[4];
                ldm_x4t(tv, sVh + vaddr);
                ldm_x4t(tw, sVl + vaddr);
                mma_bf16(o[2 * j2],     pa_h, tv);
                mma_bf16(o[2 * j2 + 1], pa_h, tv + 2);
                mma_bf16(o[2 * j2],     pa_h, tw);
                mma_bf16(o[2 * j2 + 1], pa_h, tw + 2);
                mma_bf16(o[2 * j2],     pa_l, tv);
                mma_bf16(o[2 * j2 + 1], pa_l, tv + 2);
            }
        }
        __syncthreads();
    }

    float inv1 = 1.f / l1, inv2 = 1.f / l2;
    size_t row1 = (size_t)(b * TT + qrow1) * 2048 + h * 128;
    size_t row2 = (size_t)(b * TT + qrow2) * 2048 + h * 128;
#pragma unroll
    for (int t16 = 0; t16 < 16; t16++) {
        int col = t16 * 8 + 2 * (lane & 3);
        float v0 = o[t16][0] * inv1, v1 = o[t16][1] * inv1;
        float v2 = o[t16][2] * inv2, v3 = o[t16][3] * inv2;
        float f0 = bfround(v0), f1 = bfround(v1);
        float f2 = bfround(v2), f3 = bfround(v3);
        *(uint32_t*)&ohi[row1 + col] = packbf2(f0, f1);
        *(uint32_t*)&olo[row1 + col] = packbf2(v0 - f0, v1 - f1);
        *(uint32_t*)&ohi[row2 + col] = packbf2(f2, f3);
        *(uint32_t*)&olo[row2 + col] = packbf2(v2 - f2, v3 - f3);
    }
}

// ---------------------------------------------------------------------------
// Host launcher
// ---------------------------------------------------------------------------
extern "C" void kernel_launch(void* const* d_in, const int* in_sizes, int n_in,
                              void* d_out, int out_size)
{
    (void)in_sizes; (void)n_in; (void)out_size;

    const float* x     = (const float*)d_in[0];
    const float* W_dkv = (const float*)d_in[1];
    const float* b_dkv = (const float*)d_in[2];
    const float* W_kr  = (const float*)d_in[3];
    const float* b_kr  = (const float*)d_in[4];
    const float* W_qr  = (const float*)d_in[5];
    const float* b_qr  = (const float*)d_in[6];
    const float* W_uv  = (const float*)d_in[7];
    const float* b_uv  = (const float*)d_in[8];
    const float* W_uq  = (const float*)d_in[9];
    const float* b_uq  = (const float*)d_in[10];
    const float* W_o   = (const float*)d_in[11];
    const float* b_o   = (const float*)d_in[12];
    float* out = (float*)d_out;

    float *h, *kr, *qr;
    bf16 *xhi, *xlo, *hhi, *hlo, *athi, *atlo;
    bf16 *wdkvh, *wdkvl, *wqrh, *wqrl, *wuvh, *wuvl, *wuqh, *wuql, *woh, *wol;
    bf16 *qhi, *qlo, *khi, *klo, *vhi, *vlo;
    cudaGetSymbolAddress((void**)&h,    g_h);
    cudaGetSymbolAddress((void**)&kr,   g_kr);
    cudaGetSymbolAddress((void**)&qr,   g_qr);
    cudaGetSymbolAddress((void**)&xhi,  g_xhi);
    cudaGetSymbolAddress((void**)&xlo,  g_xlo);
    cudaGetSymbolAddress((void**)&hhi,  g_hhi);
    cudaGetSymbolAddress((void**)&hlo,  g_hlo);
    cudaGetSymbolAddress((void**)&athi, g_athi);
    cudaGetSymbolAddress((void**)&atlo, g_atlo);
    cudaGetSymbolAddress((void**)&wdkvh, g_wdkvh);
    cudaGetSymbolAddress((void**)&wdkvl, g_wdkvl);
    cudaGetSymbolAddress((void**)&wqrh, g_wqrh);
    cudaGetSymbolAddress((void**)&wqrl, g_wqrl);
    cudaGetSymbolAddress((void**)&wuvh, g_wuvh);
    cudaGetSymbolAddress((void**)&wuvl, g_wuvl);
    cudaGetSymbolAddress((void**)&wuqh, g_wuqh);
    cudaGetSymbolAddress((void**)&wuql, g_wuql);
    cudaGetSymbolAddress((void**)&woh,  g_woh);
    cudaGetSymbolAddress((void**)&wol,  g_wol);
    cudaGetSymbolAddress((void**)&qhi, g_qhi);
    cudaGetSymbolAddress((void**)&qlo, g_qlo);
    cudaGetSymbolAddress((void**)&khi, g_khi);
    cudaGetSymbolAddress((void**)&klo, g_klo);
    cudaGetSymbolAddress((void**)&vhi, g_vhi);
    cudaGetSymbolAddress((void**)&vlo, g_vlo);

    const int M = MROWS;  // 4096

    cudaFuncSetAttribute(gemm_mma, cudaFuncAttributeMaxDynamicSharedMemorySize, GSMEM);
    cudaFuncSetAttribute(gemm_fused3, cudaFuncAttributeMaxDynamicSharedMemorySize, GSMEM);
    cudaFuncSetAttribute(attn_tc, cudaFuncAttributeMaxDynamicSharedMemorySize, ATTN_SMEM);

    // 1) prep: x split + all 5 weight transpose/splits
    prep_all<<<18432, 256>>>(x, W_dkv, W_o, W_qr, W_uv, W_uq,
                             xhi, xlo, wdkvh, wdkvl, woh, wol,
                             wqrh, wqrl, wuvh, wuvl, wuqh, wuql);
    // 2) h = x @ W_dkv + b_dkv (mode 1: fp32 h + hhi/hlo)
    gemm_mma<<<dim3(8, 32), 128, GSMEM>>>(xhi, xlo, 2048, 0, wdkvh, wdkvl, 2048,
                                          b_dkv, h, 1024, 2048, hhi, hlo, 0, 0, 1);
    // 3) kr projection (fp32)
    sgemm_bias<<<dim3(1, 64), 256>>>(h, 1024, 0, W_kr, b_kr, kr, 64, M, 64, 1024);
    // 4) fused qr + kv + q GEMMs (one launch, 1792 CTAs)
    gemm_fused3<<<1792, 128, GSMEM>>>(hhi, hlo,
                                      wqrh, wqrl, b_qr, qr,
                                      wuvh, wuvl, b_uv, khi, klo, vhi, vlo,
                                      wuqh, wuql, b_uq, qhi, qlo);
    // 5) fused rope+split (qr blocks then kr blocks)
    rope_split_both<<<8192 + 512, 256>>>(qr, kr, qhi, qlo, khi, klo);
    // 6) attention -> athi/atlo
    attn_tc<<<dim3(TT / 128, BB * NHH), 256, ATTN_SMEM>>>(qhi, qlo, khi, klo,
                                                          vhi, vlo, athi, atlo);
    // 7) out = attn @ W_o + b_o (mode 0)
    gemm_mma<<<dim3(16, 32), 128, GSMEM>>>(athi, atlo, 2048, 0, woh, wol, 2048,
                                           b_o, out, 2048, 2048, 0, 0, 0, 0, 0);
}

// round 15
// speedup vs baseline: 2.6456x; 1.0676x over previous
#include <cuda_runtime.h>
#include <cuda_bf16.h>
#include <math.h>
#include <stdint.h>

// Problem constants
#define BB   2
#define TT   2048
#define CC   2048
#define NHH  16
#define DKK  128
#define LATT 512
#define DHRR 64
#define MROWS (BB * TT)   // 4096

typedef __nv_bfloat16 bf16;

// ---------------------------------------------------------------------------
// Scratch (static device globals -- no allocation allowed)
// ---------------------------------------------------------------------------
__device__ float g_h   [(size_t)MROWS * 1024];
__device__ float g_kr  [(size_t)MROWS * 64];
__device__ float g_qr  [(size_t)MROWS * 1024];

__device__ bf16 g_xhi [(size_t)MROWS * 2048];
__device__ bf16 g_xlo [(size_t)MROWS * 2048];
__device__ bf16 g_hhi [(size_t)MROWS * 1024];
__device__ bf16 g_hlo [(size_t)MROWS * 1024];
__device__ bf16 g_athi[(size_t)MROWS * 2048];
__device__ bf16 g_atlo[(size_t)MROWS * 2048];

__device__ bf16 g_wdkvh[(size_t)1024 * 2048];
__device__ bf16 g_wdkvl[(size_t)1024 * 2048];
__device__ bf16 g_wqrh [(size_t)1024 * 1024];
__device__ bf16 g_wqrl [(size_t)1024 * 1024];
__device__ bf16 g_wuvh [(size_t)4096 * 512];
__device__ bf16 g_wuvl [(size_t)4096 * 512];
__device__ bf16 g_wuqh [(size_t)2048 * 512];
__device__ bf16 g_wuql [(size_t)2048 * 512];
__device__ bf16 g_woh  [(size_t)2048 * 2048];
__device__ bf16 g_wol  [(size_t)2048 * 2048];

__device__ bf16 g_qhi[(size_t)BB * NHH * TT * 192];
__device__ bf16 g_qlo[(size_t)BB * NHH * TT * 192];
__device__ bf16 g_khi[(size_t)BB * NHH * TT * 192];
__device__ bf16 g_klo[(size_t)BB * NHH * TT * 192];
__device__ bf16 g_vhi[(size_t)BB * NHH * TT * 128];
__device__ bf16 g_vlo[(size_t)BB * NHH * TT * 128];

#define SCLQ 0.12754984837627695f   // 1/sqrt(128) * log2(e)

// ---------------------------------------------------------------------------
// PTX helpers
// ---------------------------------------------------------------------------
__device__ __forceinline__ uint32_t smem_u32(const void* p)
{ return (uint32_t)__cvta_generic_to_shared(p); }

__device__ __forceinline__ void cp16(uint32_t dst, const void* src)
{ asm volatile("cp.async.cg.shared.global [%0], [%1], 16;\n" :: "r"(dst), "l"(src)); }

__device__ __forceinline__ void cp_commit()
{ asm volatile("cp.async.commit_group;\n"); }

template <int N>
__device__ __forceinline__ void cp_wait()
{ asm volatile("cp.async.wait_group %0;\n" :: "n"(N)); }

__device__ __forceinline__ void ldm_x4(uint32_t* r, uint32_t addr)
{
    asm volatile("ldmatrix.sync.aligned.m8n8.x4.shared.b16 {%0,%1,%2,%3}, [%4];\n"
        : "=r"(r[0]), "=r"(r[1]), "=r"(r[2]), "=r"(r[3]) : "r"(addr));
}
__device__ __forceinline__ void ldm_x4t(uint32_t* r, uint32_t addr)
{
    asm volatile("ldmatrix.sync.aligned.m8n8.x4.trans.shared.b16 {%0,%1,%2,%3}, [%4];\n"
        : "=r"(r[0]), "=r"(r[1]), "=r"(r[2]), "=r"(r[3]) : "r"(addr));
}
__device__ __forceinline__ void mma_bf16(float* d, const uint32_t* a, const uint32_t* b)
{
    asm volatile(
        "mma.sync.aligned.m16n8k16.row.col.f32.bf16.bf16.f32 "
        "{%0,%1,%2,%3}, {%4,%5,%6,%7}, {%8,%9}, {%0,%1,%2,%3};\n"
        : "+f"(d[0]), "+f"(d[1]), "+f"(d[2]), "+f"(d[3])
        : "r"(a[0]), "r"(a[1]), "r"(a[2]), "r"(a[3]), "r"(b[0]), "r"(b[1]));
}
__device__ __forceinline__ float ex2f(float x)
{ float y; asm("ex2.approx.f32 %0, %1;" : "=f"(y) : "f"(x)); return y; }

__device__ __forceinline__ uint32_t packbf2(float lo, float hi)
{ uint32_t d; asm("cvt.rn.bf16x2.f32 %0, %1, %2;" : "=r"(d) : "f"(hi), "f"(lo)); return d; }

__device__ __forceinline__ float bfround(float v)
{ return __bfloat162float(__float2bfloat16(v)); }

// ---------------------------------------------------------------------------
// prep_all: one launch = split_act(x) + 5 weight transpose/splits.
// ---------------------------------------------------------------------------
__global__ __launch_bounds__(256)
void prep_all(const float* __restrict__ x,
              const float* __restrict__ Wdkv, const float* __restrict__ Wo,
              const float* __restrict__ Wqr,  const float* __restrict__ Wuv,
              const float* __restrict__ Wuq,
              bf16* __restrict__ xhi, bf16* __restrict__ xlo,
              bf16* __restrict__ wdkvh, bf16* __restrict__ wdkvl,
              bf16* __restrict__ woh,  bf16* __restrict__ wol,
              bf16* __restrict__ wqrh, bf16* __restrict__ wqrl,
              bf16* __restrict__ wuvh, bf16* __restrict__ wuvl,
              bf16* __restrict__ wuqh, bf16* __restrict__ wuql)
{
    __shared__ float ts[32][33];
    const int bid = blockIdx.x, tid = threadIdx.x;

    if (bid < 8192) {
        int idx = bid * 256 + tid;
        int m = idx >> 9, k4 = (idx & 511) * 4;
        float4 v = *(const float4*)&x[(size_t)m * 2048 + k4];
        float h0 = bfround(v.x), h1 = bfround(v.y);
        float h2 = bfround(v.z), h3 = bfround(v.w);
        uint2 ph, pl;
        ph.x = packbf2(h0, h1); ph.y = packbf2(h2, h3);
        pl.x = packbf2(v.x - h0, v.y - h1); pl.y = packbf2(v.z - h2, v.w - h3);
        *(uint2*)&xhi[(size_t)m * 2048 + k4] = ph;
        *(uint2*)&xlo[(size_t)m * 2048 + k4] = pl;
        return;
    }

    const float* W; bf16 *hiT, *loT; int K, N, tl;
    if (bid < 10240)      { W = Wdkv; hiT = wdkvh; loT = wdkvl; K = 2048; N = 1024; tl = bid - 8192; }
    else if (bid < 14336) { W = Wo;   hiT = woh;   loT = wol;   K = 2048; N = 2048; tl = bid - 10240; }
    else if (bid < 15360) { W = Wqr;  hiT = wqrh;  loT = wqrl;  K = 1024; N = 1024; tl = bid - 14336; }
    else if (bid < 17408) { W = Wuv;  hiT = wuvh;  loT = wuvl;  K = 512;  N = 4096; tl = bid - 15360; }
    else                  { W = Wuq;  hiT = wuqh;  loT = wuql;  K = 512;  N = 2048; tl = bid - 17408; }

    int ntx = N / 32;
    int n0 = (tl % ntx) * 32, k0 = (tl / ntx) * 32;
    int tx = tid & 31, ty = tid >> 5;
#pragma unroll
    for (int r = 0; r < 4; r++)
        ts[ty + 8 * r][tx] = W[(size_t)(k0 + ty + 8 * r) * N + n0 + tx];
    __syncthreads();
#pragma unroll
    for (int r = 0; r < 4; r++) {
        float v = ts[tx][ty + 8 * r];
        bf16 h = __float2bfloat16(v);
        size_t o = (size_t)(n0 + ty + 8 * r) * K + k0 + tx;
        hiT[o] = h;
        loT[o] = __float2bfloat16(v - __bfloat162float(h));
    }
}

// ---------------------------------------------------------------------------
// Fused rope + hi/lo split + per-head scatter (qr blocks then kr blocks)
// ---------------------------------------------------------------------------
__global__ void rope_split_both(const float* __restrict__ qr,
                                const float* __restrict__ kr,
                                bf16* __restrict__ qhi, bf16* __restrict__ qlo,
                                bf16* __restrict__ khi, bf16* __restrict__ klo)
{
    const int bid = blockIdx.x, tid = threadIdx.x;
    if (bid < 8192) {
        int idx = bid * 256 + tid;
        int row = idx >> 9, i = idx & 511;
        int t = row & 2047, b = row >> 11;
        float theta = (float)exp(-2.0 * (double)i / 1024.0 * log(10000.0));
        float angle = (float)(t + 1) * theta;
        double a = (double)angle;
        float cs = (float)cos(a), sn = (float)sin(a);
        const float* p = qr + (size_t)row * 1024 + 2 * i;
        float x0 = p[0], x1 = p[1];
        float p0 = (x0 * cs - x1 * sn) * SCLQ;
        float p1 = (x1 * cs + x0 * sn) * SCLQ;
        int h = (2 * i) >> 6, d = (2 * i) & 63;
        size_t base = ((size_t)((b * NHH + h) * TT) + t) * 192 + 128 + d;
        float f0 = bfround(p0), f1 = bfround(p1);
        *(uint32_t*)&qhi[base] = packbf2(f0, f1);
        *(uint32_t*)&qlo[base] = packbf2(p0 - f0, p1 - f1);
    } else {
        int idx = (bid - 8192) * 256 + tid;
        int row = idx >> 5, i = idx & 31;
        int t = row & 2047, b = row >> 11;
        float theta = (float)exp(-2.0 * (double)i / 64.0 * log(10000.0));
        float angle = (float)(t + 1) * theta;
        double a = (double)angle;
        float cs = (float)cos(a), sn = (float)sin(a);
        const float* p = kr + (size_t)row * 64 + 2 * i;
        float x0 = p[0], x1 = p[1];
        float p0 = x0 * cs - x1 * sn;
        float p1 = x1 * cs + x0 * sn;
        float f0 = bfround(p0), f1 = bfround(p1);
        uint32_t ph = packbf2(f0, f1), pl = packbf2(p0 - f0, p1 - f1);
#pragma unroll
        for (int hh = 0; hh < NHH; hh++) {
            size_t base = ((size_t)((b * NHH + hh) * TT) + t) * 192 + 128 + 2 * i;
            *(uint32_t*)&khi[base] = ph;
            *(uint32_t*)&klo[base] = pl;
        }
    }
}

// ---------------------------------------------------------------------------
// Shared HMMA GEMM body (compensated hi/lo, fused epilogues) — R12 proven.
// ---------------------------------------------------------------------------
#define TST 40
#define A_ELE (128 * TST)
#define B_ELE (128 * TST)
#define STG_ELE (2 * A_ELE + 2 * B_ELE)
#define GSMEM (2 * STG_ELE * 2)

__device__ __forceinline__
void gemm_body(int brow, int bcol,
               const bf16* __restrict__ Ahi, const bf16* __restrict__ Alo,
               int lda, int aoff,
               const bf16* __restrict__ Bhi, const bf16* __restrict__ Blo,
               int ldb,
               const float* __restrict__ bias,
               float* __restrict__ Y, int ldy, int K,
               bf16* __restrict__ ho, bf16* __restrict__ lo_,
               bf16* __restrict__ ho2, bf16* __restrict__ lo2, int mode,
               bf16* dsm)
{
    const uint32_t sb0 = smem_u32(dsm);
    const int tid = threadIdx.x, lane = tid & 31, wid = tid >> 5;
    const int wm = (wid >> 1) * 64, wn = (wid & 1) * 64;

    auto issue = [&](int st, int kt) {
        uint32_t s = sb0 + (uint32_t)(st * STG_ELE) * 2;
        int ke = kt * 32;
#pragma unroll
        for (int i = 0; i < 4; i++) {
            int c = tid + i * 128;
            int r = c >> 2, sg = (c & 3) * 8;
            uint32_t d = (uint32_t)(r * TST + sg) * 2;
            cp16(s + d, Ahi + (size_t)(brow + r) * lda + aoff + ke + sg);
            cp16(s + (uint32_t)A_ELE * 2 + d,
                 Alo + (size_t)(brow + r) * lda + aoff + ke + sg);
            cp16(s + (uint32_t)(2 * A_ELE) * 2 + d,
                 Bhi + (size_t)(bcol + r) * ldb + ke + sg);
            cp16(s + (uint32_t)(2 * A_ELE + B_ELE) * 2 + d,
                 Blo + (size_t)(bcol + r) * ldb + ke + sg);
        }
        cp_commit();
    };

    float acc[4][8][4];
#pragma unroll
    for (int i = 0; i < 4; i++)
#pragma unroll
        for (int j = 0; j < 8; j++)
#pragma unroll
            for (int f = 0; f < 4; f++) acc[i][j][f] = 0.f;

    const int ntiles = K / 32;
    issue(0, 0);
    issue(1, 1);

    const int l16 = lane & 15, lhi = (lane >> 4) * 8;
    const int brofs = (lane & 7) + ((lane >> 4) & 1) * 8;
    const int bcofs = ((lane >> 3) & 1) * 8;

    for (int kt = 0; kt < ntiles; kt++) {
        if (kt + 1 < ntiles) { cp_wait<1>(); } else { cp_wait<0>(); }
        __syncthreads();
        int cur = kt & 1;
        uint32_t s = sb0 + (uint32_t)(cur * STG_ELE) * 2;
        uint32_t sAh = s, sAl = s + (uint32_t)A_ELE * 2;
        uint32_t sBh = s + (uint32_t)(2 * A_ELE) * 2;
        uint32_t sBl = sBh + (uint32_t)B_ELE * 2;

#pragma unroll
        for (int kk = 0; kk < 32; kk += 16) {
            uint32_t bh[4][4], bl[4][4];
#pragma unroll
            for (int j2 = 0; j2 < 4; j2++) {
                uint32_t baddr =
                    (uint32_t)((wn + j2 * 16 + brofs) * TST + kk + bcofs) * 2;
                ldm_x4(bh[j2], sBh + baddr);
                ldm_x4(bl[j2], sBl + baddr);
            }
#pragma unroll
            for (int i = 0; i < 4; i++) {
                uint32_t ah[4], al[4];
                uint32_t aaddr = (uint32_t)((wm + i * 16 + l16) * TST + kk + lhi) * 2;
                ldm_x4(ah, sAh + aaddr);
                ldm_x4(al, sAl + aaddr);
#pragma unroll
                for (int j2 = 0; j2 < 4; j2++) {
                    mma_bf16(acc[i][2 * j2],     ah, bh[j2]);
                    mma_bf16(acc[i][2 * j2 + 1], ah, bh[j2] + 2);
                }
#pragma unroll
                for (int j2 = 0; j2 < 4; j2++) {
                    mma_bf16(acc[i][2 * j2],     ah, bl[j2]);
                    mma_bf16(acc[i][2 * j2 + 1], ah, bl[j2] + 2);
                }
#pragma unroll
                for (int j2 = 0; j2 < 4; j2++) {
                    mma_bf16(acc[i][2 * j2],     al, bh[j2]);
                    mma_bf16(acc[i][2 * j2 + 1], al, bh[j2] + 2);
                }
            }
        }
        __syncthreads();
        if (kt + 2 < ntiles) issue(cur, kt + 2);
    }

#pragma unroll
    for (int i = 0; i < 4; i++) {
#pragma unroll
        for (int j = 0; j < 8; j++) {
            int r0 = brow + wm + i * 16 + (lane >> 2);
            int c0 = bcol + wn + j * 8 + (lane & 3) * 2;
            float b0 = bias[c0], b1 = bias[c0 + 1];
            float v00 = acc[i][j][0] + b0, v01 = acc[i][j][1] + b1;
            float v10 = acc[i][j][2] + b0, v11 = acc[i][j][3] + b1;

            if (mode <= 1) {
                *(float2*)&Y[(size_t)r0 * ldy + c0]       = make_float2(v00, v01);
                *(float2*)&Y[(size_t)(r0 + 8) * ldy + c0] = make_float2(v10, v11);
            }
            if (mode == 1) {
                float f00 = bfround(v00), f01 = bfround(v01);
                float f10 = bfround(v10), f11 = bfround(v11);
                *(uint32_t*)&ho [(size_t)r0 * ldy + c0]       = packbf2(f00, f01);
                *(uint32_t*)&lo_[(size_t)r0 * ldy + c0]       = packbf2(v00 - f00, v01 - f01);
                *(uint32_t*)&ho [(size_t)(r0 + 8) * ldy + c0] = packbf2(f10, f11);
                *(uint32_t*)&lo_[(size_t)(r0 + 8) * ldy + c0] = packbf2(v10 - f10, v11 - f11);
            } else if (mode == 2) {
#pragma unroll
                for (int rr = 0; rr < 2; rr++) {
                    int r = r0 + rr * 8;
                    float va = rr ? v10 : v00, vb = rr ? v11 : v01;
                    int b = r >> 11, t = r & 2047;
                    float fa = bfround(va), fb = bfround(vb);
                    if (c0 < 2048) {
                        int hh = c0 >> 7, d = c0 & 127;
                        size_t base = ((size_t)(b * NHH + hh) * TT + t) * 192 + d;
                        *(uint32_t*)&ho [base] = packbf2(fa, fb);
                        *(uint32_t*)&lo_[base] = packbf2(va - fa, vb - fb);
                    } else {
                        int c2 = c0 - 2048;
                        int hh = c2 >> 7, d = c2 & 127;
                        size_t base = ((size_t)(b * NHH + hh) * TT + t) * 128 + d;
                        *(uint32_t*)&ho2[base] = packbf2(fa, fb);
                        *(uint32_t*)&lo2[base] = packbf2(va - fa, vb - fb);
                    }
                }
            } else if (mode == 3) {
#pragma unroll
                for (int rr = 0; rr < 2; rr++) {
                    int r = r0 + rr * 8;
                    float va = (rr ? v10 : v00) * SCLQ, vb = (rr ? v11 : v01) * SCLQ;
                    int b = r >> 11, t = r & 2047;
                    int hh = c0 >> 7, d = c0 & 127;
                    size_t base = ((size_t)(b * NHH + hh) * TT + t) * 192 + d;
                    float fa = bfround(va), fb = bfround(vb);
                    *(uint32_t*)&ho [base] = packbf2(fa, fb);
                    *(uint32_t*)&lo_[base] = packbf2(va - fa, vb - fb);
                }
            }
        }
    }
}

// Standalone GEMM (h and out projections)
__global__ __launch_bounds__(128, 2)
void gemm_mma(const bf16* __restrict__ Ahi, const bf16* __restrict__ Alo,
              int lda, int aoff,
              const bf16* __restrict__ Bhi, const bf16* __restrict__ Blo,
              int ldb,
              const float* __restrict__ bias,
              float* __restrict__ Y, int ldy, int K,
              bf16* __restrict__ ho, bf16* __restrict__ lo_,
              bf16* __restrict__ ho2, bf16* __restrict__ lo2, int mode)
{
    extern __shared__ bf16 dsm[];
    gemm_body(blockIdx.y * 128, blockIdx.x * 128, Ahi, Alo, lda, aoff,
              Bhi, Blo, ldb, bias, Y, ldy, K, ho, lo_, ho2, lo2, mode, dsm);
}

// Fused qr + kv + q GEMMs + kr mini-GEMM; one launch, range dispatch.
// Blocks: [0,256) qr; [256,1280) kv; [1280,1792) q; [1792,1856) kr.
__global__ __launch_bounds__(128, 2)
void gemm_fused3(const bf16* __restrict__ hhi, const bf16* __restrict__ hlo,
                 const bf16* __restrict__ wqrh, const bf16* __restrict__ wqrl,
                 const float* __restrict__ b_qr, float* __restrict__ qr,
                 const bf16* __restrict__ wuvh, const bf16* __restrict__ wuvl,
                 const float* __restrict__ b_uv,
                 bf16* __restrict__ khi, bf16* __restrict__ klo,
                 bf16* __restrict__ vhi, bf16* __restrict__ vlo,
                 const bf16* __restrict__ wuqh, const bf16* __restrict__ wuql,
                 const float* __restrict__ b_uq,
                 bf16* __restrict__ qhi, bf16* __restrict__ qlo,
                 const float* __restrict__ h, const float* __restrict__ W_kr,
                 const float* __restrict__ b_kr, float* __restrict__ kr)
{
    extern __shared__ bf16 dsm[];
    const int id = blockIdx.x;
    if (id < 256) {
        int bx = id & 7, by = id >> 3;
        gemm_body(by * 128, bx * 128, hhi, hlo, 1024, 0, wqrh, wqrl, 1024,
                  b_qr, qr, 1024, 1024, 0, 0, 0, 0, 0, dsm);
    } else if (id < 1280) {
        int t = id - 256;
        int bx = t & 31, by = t >> 5;
        gemm_body(by * 128, bx * 128, hhi, hlo, 1024, 0, wuvh, wuvl, 512,
                  b_uv, 0, 512, 512, khi, klo, vhi, vlo, 2, dsm);
    } else if (id < 1792) {
        int t = id - 1280;
        int bx = t & 15, by = t >> 4;
        gemm_body(by * 128, bx * 128, hhi, hlo, 1024, 512, wuqh, wuql, 512,
                  b_uq, 0, 512, 512, qhi, qlo, 0, 0, 3, dsm);
    } else {
        // kr mini-GEMM: 64x64 tile, K=1024, fp32 (same k-order as before)
        float* As = (float*)dsm;             // [16][64]
        float* Bs = As + 16 * 64;            // [16][64]
        const int tid = threadIdx.x;
        const int brow = (id - 1792) * 64;
        const int tr = (tid >> 4) * 8, tc = (tid & 15) * 4;
        float acc[8][4];
#pragma unroll
        for (int i = 0; i < 8; i++)
#pragma unroll
            for (int j = 0; j < 4; j++) acc[i][j] = 0.f;
        for (int k0 = 0; k0 < 1024; k0 += 16) {
            __syncthreads();
#pragma unroll
            for (int it = 0; it < 8; it++) {
                int i = tid + it * 128;
                int m = i >> 4, kk = i & 15;
                As[kk * 64 + m] = h[(size_t)(brow + m) * 1024 + k0 + kk];
            }
#pragma unroll
            for (int it = 0; it < 8; it++) {
                int i = tid + it * 128;
                int kk = i >> 6, n = i & 63;
                Bs[kk * 64 + n] = W_kr[(size_t)(k0 + kk) * 64 + n];
            }
            __syncthreads();
#pragma unroll
            for (int kk = 0; kk < 16; kk++) {
                float a[8], b[4];
#pragma unroll
                for (int i = 0; i < 8; i++) a[i] = As[kk * 64 + tr + i];
#pragma unroll
                for (int j = 0; j < 4; j++) b[j] = Bs[kk * 64 + tc + j];
#pragma unroll
                for (int i = 0; i < 8; i++)
#pragma unroll
                    for (int j = 0; j < 4; j++) acc[i][j] = fmaf(a[i], b[j], acc[i][j]);
            }
        }
#pragma unroll
        for (int i = 0; i < 8; i++)
#pragma unroll
            for (int j = 0; j < 4; j++)
                kr[(size_t)(brow + tr + i) * 64 + tc + j] = acc[i][j] + b_kr[tc + j];
    }
}

// ---------------------------------------------------------------------------
// Tensor-core flash attention — PERSISTENT with static snake schedule.
// Grid = 148 CTAs; CTA c handles tile ranks p*148+c / (p+1)*148-1-c.
// rank r -> qi = 15 - r/32 (largest first), bh = r%32.
// Per-tile body identical to R12/R13/R14.
// ---------------------------------------------------------------------------
#define QSTR 200
#define KSTR 200
#define VSTR 136
#define Q_ELEMS (128 * QSTR)
#define KST_ELEMS (64 * KSTR)
#define VST_ELEMS (64 * VSTR)
#define K_BASE Q_ELEMS
#define V_BASE (Q_ELEMS + 4 * KST_ELEMS)
#define ATTN_SMEM ((Q_ELEMS + 4 * KST_ELEMS + 4 * VST_ELEMS) * 2)
#define NSM 148

__global__ __launch_bounds__(256, 1)
void attn_tc(const bf16* __restrict__ qhi, const bf16* __restrict__ qlo,
             const bf16* __restrict__ khi, const bf16* __restrict__ klo,
             const bf16* __restrict__ vhi, const bf16* __restrict__ vlo,
             bf16* __restrict__ ohi, bf16* __restrict__ olo)
{
    extern __shared__ bf16 smA[];
    const uint32_t sQh = smem_u32(smA);
    const uint32_t sK  = sQh + K_BASE * 2;
    const uint32_t sV  = sQh + V_BASE * 2;

    const int tid = threadIdx.x, lane = tid & 31, wp = tid >> 5;
    const int c = blockIdx.x;
    const int l16 = lane & 15, lhi = (lane >> 4) * 8;

    for (int p = 0; ; p++) {
        int r = (p & 1) ? ((p + 1) * NSM - 1 - c) : (p * NSM + c);
        if (r >= 512) break;
        const int qi = 15 - (r >> 5);
        const int bh = r & 31;
        const int b = bh >> 4, h = bh & 15;
        const size_t base = (size_t)bh * TT;

        // Q load: Qh -> smem; Qlo -> K-stage staging
        for (int i = tid; i < 128 * 24; i += 256) {
            int rr = i / 24, cc = (i % 24) * 8;
            size_t g = (base + (size_t)qi * 128 + rr) * 192 + cc;
            uint32_t d = (uint32_t)(rr * QSTR + cc) * 2;
            cp16(sQh + d, qhi + g);
            cp16(sK + d, qlo + g);
        }
        cp_commit();
        cp_wait<0>();
        __syncthreads();

        uint32_t qlof[12][4];
#pragma unroll
        for (int kk = 0; kk < 12; kk++) {
            uint32_t aaddr = (uint32_t)((wp * 16 + l16) * QSTR + kk * 16 + lhi) * 2;
            ldm_x4(qlof[kk], sK + aaddr);
        }
        __syncthreads();

        auto issueKV = [&](int st, int kt) {
            uint32_t kb = sK + (uint32_t)(st * 2 * KST_ELEMS) * 2;
            uint32_t vb = sV + (uint32_t)(st * 2 * VST_ELEMS) * 2;
            for (int i = tid; i < 64 * 24; i += 256) {
                int rr = i / 24, cc = (i % 24) * 8;
                size_t g = (base + (size_t)kt * 64 + rr) * 192 + cc;
                uint32_t d = (uint32_t)(rr * KSTR + cc) * 2;
                cp16(kb + d, khi + g);
                cp16(kb + (uint32_t)KST_ELEMS * 2 + d, klo + g);
            }
            for (int i = tid; i < 64 * 16; i += 256) {
                int rr = i / 16, cc = (i % 16) * 8;
                size_t g = (base + (size_t)kt * 64 + rr) * 128 + cc;
                uint32_t d = (uint32_t)(rr * VSTR + cc) * 2;
                cp16(vb + d, vhi + g);
                cp16(vb + (uint32_t)VST_ELEMS * 2 + d, vlo + g);
            }
            cp_commit();
        };

        float o[16][4];
#pragma unroll
        for (int i = 0; i < 16; i++)
#pragma unroll
            for (int f = 0; f < 4; f++) o[i][f] = 0.f;

        float m1 = -1e30f, m2 = -1e30f, l1 = 0.f, l2 = 0.f;
        const int qrow1 = qi * 128 + wp * 16 + (lane >> 2);
        const int qrow2 = qrow1 + 8;
        const int brofs = (lane & 7) + ((lane >> 4) & 1) * 8;
        const int bcofs = ((lane >> 3) & 1) * 8;

        const int nkt = 2 * qi + 2;
        issueKV(0, 0);

        for (int kt = 0; kt < nkt; kt++) {
            if (kt + 1 < nkt) {
                issueKV((kt + 1) & 1, kt + 1);
                cp_wait<1>();
            } else {
                cp_wait<0>();
            }
            __syncthreads();

            const int st = kt & 1;
            const uint32_t sKh = sK + (uint32_t)(st * 2 * KST_ELEMS) * 2;
            const uint32_t sKl = sKh + (uint32_t)KST_ELEMS * 2;
            const uint32_t sVh = sV + (uint32_t)(st * 2 * VST_ELEMS) * 2;
            const uint32_t sVl = sVh + (uint32_t)VST_ELEMS * 2;

            float s[8][4];
#pragma unroll
            for (int j = 0; j < 8; j++)
#pragma unroll
                for (int f = 0; f < 4; f++) s[j][f] = 0.f;

#pragma unroll
            for (int kk = 0; kk < 12; kk++) {
                uint32_t ah[4];
                uint32_t aaddr = (uint32_t)((wp * 16 + l16) * QSTR + kk * 16 + lhi) * 2;
                ldm_x4(ah, sQh + aaddr);
                const uint32_t* al = qlof[kk];
#pragma unroll
                for (int j2 = 0; j2 < 4; j2++) {
                    uint32_t baddr = (uint32_t)((j2 * 16 + brofs) * KSTR + kk * 16 + bcofs) * 2;
                    uint32_t tbv[4], tl[4];
                    ldm_x4(tbv, sKh + baddr);
                    ldm_x4(tl, sKl + baddr);
                    mma_bf16(s[2 * j2],     ah, tbv);
                    mma_bf16(s[2 * j2 + 1], ah, tbv + 2);
                    mma_bf16(s[2 * j2],     ah, tl);
                    mma_bf16(s[2 * j2 + 1], ah, tl + 2);
                    mma_bf16(s[2 * j2],     al, tbv);
                    mma_bf16(s[2 * j2 + 1], al, tbv + 2);
                }
            }

#pragma unroll
            for (int j = 0; j < 8; j++) {
                int k0 = kt * 64 + j * 8 + 2 * (lane & 3);
                if (k0     > qrow1) s[j][0] = -1e30f;
                if (k0 + 1 > qrow1) s[j][1] = -1e30f;
                if (k0     > qrow2) s[j][2] = -1e30f;
                if (k0 + 1 > qrow2) s[j][3] = -1e30f;
            }
            float mr1 = -1e30f, mr2 = -1e30f;
#pragma unroll
            for (int j = 0; j < 8; j++) {
                mr1 = fmaxf(mr1, fmaxf(s[j][0], s[j][1]));
                mr2 = fmaxf(mr2, fmaxf(s[j][2], s[j][3]));
            }
            mr1 = fmaxf(mr1, __shfl_xor_sync(0xffffffffu, mr1, 1));
            mr1 = fmaxf(mr1, __shfl_xor_sync(0xffffffffu, mr1, 2));
            mr2 = fmaxf(mr2, __shfl_xor_sync(0xffffffffu, mr2, 1));
            mr2 = fmaxf(mr2, __shfl_xor_sync(0xffffffffu, mr2, 2));
            float mn1 = fmaxf(m1, mr1), mn2 = fmaxf(m2, mr2);
            float a1 = ex2f(m1 - mn1), a2 = ex2f(m2 - mn2);
            m1 = mn1; m2 = mn2;

            uint32_t phx[8][2], plx[8][2];
            float rs1 = 0.f, rs2 = 0.f;
#pragma unroll
            for (int j = 0; j < 8; j++) {
                float p0 = ex2f(s[j][0] - mn1), p1 = ex2f(s[j][1] - mn1);
                float p2 = ex2f(s[j][2] - mn2), p3 = ex2f(s[j][3] - mn2);
                rs1 += p0 + p1; rs2 += p2 + p3;
                phx[j][0] = packbf2(p0, p1);
                phx[j][1] = packbf2(p2, p3);
                float q0 = p0 - bfround(p0);
                float q1 = p1 - bfround(p1);
                float q2 = p2 - bfround(p2);
                float q3 = p3 - bfround(p3);
                plx[j][0] = packbf2(q0, q1);
                plx[j][1] = packbf2(q2, q3);
            }
            rs1 += __shfl_xor_sync(0xffffffffu, rs1, 1);
            rs1 += __shfl_xor_sync(0xffffffffu, rs1, 2);
            rs2 += __shfl_xor_sync(0xffffffffu, rs2, 1);
            rs2 += __shfl_xor_sync(0xffffffffu, rs2, 2);
            l1 = l1 * a1 + rs1;
            l2 = l2 * a2 + rs2;
#pragma unroll
            for (int t16 = 0; t16 < 16; t16++) {
                o[t16][0] *= a1; o[t16][1] *= a1;
                o[t16][2] *= a2; o[t16][3] *= a2;
            }

#pragma unroll
            for (int kt2 = 0; kt2 < 4; kt2++) {
                uint32_t pa_h[4] = {phx[2 * kt2][0], phx[2 * kt2][1],
                                    phx[2 * kt2 + 1][0], phx[2 * kt2 + 1][1]};
                uint32_t pa_l[4] = {plx[2 * kt2][0], plx[2 * kt2][1],
                                    plx[2 * kt2 + 1][0], plx[2 * kt2 + 1][1]};
                uint32_t vrow = (uint32_t)((kt2 * 16 + l16) * VSTR) * 2;
#pragma unroll
                for (int j2 = 0; j2 < 8; j2++) {
                    uint32_t vaddr = vrow + (uint32_t)(j2 * 16 + lhi) * 2;
                    uint32_t tv[4], tw[4];
                    ldm_x4t(tv, sVh + vaddr);
                    ldm_x4t(tw, sVl + vaddr);
                    mma_bf16(o[2 * j2],     pa_h, tv);
                    mma_bf16(o[2 * j2 + 1], pa_h, tv + 2);
                    mma_bf16(o[2 * j2],     pa_h, tw);
                    mma_bf16(o[2 * j2 + 1], pa_h, tw + 2);
                    mma_bf16(o[2 * j2],     pa_l, tv);
                    mma_bf16(o[2 * j2 + 1], pa_l, tv + 2);
                }
            }
            __syncthreads();
        }

        // epilogue
        float inv1 = 1.f / l1, inv2 = 1.f / l2;
        size_t row1 = (size_t)(b * TT + qrow1) * 2048 + h * 128;
        size_t row2 = (size_t)(b * TT + qrow2) * 2048 + h * 128;
#pragma unroll
        for (int t16 = 0; t16 < 16; t16++) {
            int col = t16 * 8 + 2 * (lane & 3);
            float v0 = o[t16][0] * inv1, v1 = o[t16][1] * inv1;
            float v2 = o[t16][2] * inv2, v3 = o[t16][3] * inv2;
            float f0 = bfround(v0), f1 = bfround(v1);
            float f2 = bfround(v2), f3 = bfround(v3);
            *(uint32_t*)&ohi[row1 + col] = packbf2(f0, f1);
            *(uint32_t*)&olo[row1 + col] = packbf2(v0 - f0, v1 - f1);
            *(uint32_t*)&ohi[row2 + col] = packbf2(f2, f3);
            *(uint32_t*)&olo[row2 + col] = packbf2(v2 - f2, v3 - f3);
        }
        __syncthreads();   // staging (sK) safe for next tile's Q-lo
    }
}

// ---------------------------------------------------------------------------
// Host launcher
// ---------------------------------------------------------------------------
extern "C" void kernel_launch(void* const* d_in, const int* in_sizes, int n_in,
                              void* d_out, int out_size)
{
    (void)in_sizes; (void)n_in; (void)out_size;

    const float* x     = (const float*)d_in[0];
    const float* W_dkv = (const float*)d_in[1];
    const float* b_dkv = (const float*)d_in[2];
    const float* W_kr  = (const float*)d_in[3];
    const float* b_kr  = (const float*)d_in[4];
    const float* W_qr  = (const float*)d_in[5];
    const float* b_qr  = (const float*)d_in[6];
    const float* W_uv  = (const float*)d_in[7];
    const float* b_uv  = (const float*)d_in[8];
    const float* W_uq  = (const float*)d_in[9];
    const float* b_uq  = (const float*)d_in[10];
    const float* W_o   = (const float*)d_in[11];
    const float* b_o   = (const float*)d_in[12];
    float* out = (float*)d_out;

    float *h, *kr, *qr;
    bf16 *xhi, *xlo, *hhi, *hlo, *athi, *atlo;
    bf16 *wdkvh, *wdkvl, *wqrh, *wqrl, *wuvh, *wuvl, *wuqh, *wuql, *woh, *wol;
    bf16 *qhi, *qlo, *khi, *klo, *vhi, *vlo;
    cudaGetSymbolAddress((void**)&h,    g_h);
    cudaGetSymbolAddress((void**)&kr,   g_kr);
    cudaGetSymbolAddress((void**)&qr,   g_qr);
    cudaGetSymbolAddress((void**)&xhi,  g_xhi);
    cudaGetSymbolAddress((void**)&xlo,  g_xlo);
    cudaGetSymbolAddress((void**)&hhi,  g_hhi);
    cudaGetSymbolAddress((void**)&hlo,  g_hlo);
    cudaGetSymbolAddress((void**)&athi, g_athi);
    cudaGetSymbolAddress((void**)&atlo, g_atlo);
    cudaGetSymbolAddress((void**)&wdkvh, g_wdkvh);
    cudaGetSymbolAddress((void**)&wdkvl, g_wdkvl);
    cudaGetSymbolAddress((void**)&wqrh, g_wqrh);
    cudaGetSymbolAddress((void**)&wqrl, g_wqrl);
    cudaGetSymbolAddress((void**)&wuvh, g_wuvh);
    cudaGetSymbolAddress((void**)&wuvl, g_wuvl);
    cudaGetSymbolAddress((void**)&wuqh, g_wuqh);
    cudaGetSymbolAddress((void**)&wuql, g_wuql);
    cudaGetSymbolAddress((void**)&woh,  g_woh);
    cudaGetSymbolAddress((void**)&wol,  g_wol);
    cudaGetSymbolAddress((void**)&qhi, g_qhi);
    cudaGetSymbolAddress((void**)&qlo, g_qlo);
    cudaGetSymbolAddress((void**)&khi, g_khi);
    cudaGetSymbolAddress((void**)&klo, g_klo);
    cudaGetSymbolAddress((void**)&vhi, g_vhi);
    cudaGetSymbolAddress((void**)&vlo, g_vlo);

    cudaFuncSetAttribute(gemm_mma, cudaFuncAttributeMaxDynamicSharedMemorySize, GSMEM);
    cudaFuncSetAttribute(gemm_fused3, cudaFuncAttributeMaxDynamicSharedMemorySize, GSMEM);
    cudaFuncSetAttribute(attn_tc, cudaFuncAttributeMaxDynamicSharedMemorySize, ATTN_SMEM);

    // 1) prep: x split + all 5 weight transpose/splits
    prep_all<<<18432, 256>>>(x, W_dkv, W_o, W_qr, W_uv, W_uq,
                             xhi, xlo, wdkvh, wdkvl, woh, wol,
                             wqrh, wqrl, wuvh, wuvl, wuqh, wuql);
    // 2) h = x @ W_dkv + b_dkv (mode 1: fp32 h + hhi/hlo)
    gemm_mma<<<dim3(8, 32), 128, GSMEM>>>(xhi, xlo, 2048, 0, wdkvh, wdkvl, 2048,
                                          b_dkv, h, 1024, 2048, hhi, hlo, 0, 0, 1);
    // 3) fused qr + kv + q GEMMs + kr (one launch, 1856 CTAs)
    gemm_fused3<<<1856, 128, GSMEM>>>(hhi, hlo,
                                      wqrh, wqrl, b_qr, qr,
                                      wuvh, wuvl, b_uv, khi, klo, vhi, vlo,
                                      wuqh, wuql, b_uq, qhi, qlo,
                                      h, W_kr, b_kr, kr);
    // 4) fused rope+split (qr blocks then kr blocks)
    rope_split_both<<<8192 + 512, 256>>>(qr, kr, qhi, qlo, khi, klo);
    // 5) attention (persistent, 148 CTAs, snake schedule)
    attn_tc<<<NSM, 256, ATTN_SMEM>>>(qhi, qlo, khi, klo, vhi, vlo, athi, atlo);
    // 6) out = attn @ W_o + b_o (mode 0)
    gemm_mma<<<dim3(16, 32), 128, GSMEM>>>(athi, atlo, 2048, 0, woh, wol, 2048,
                                           b_o, out, 2048, 2048, 0, 0, 0, 0, 0);
}